// round 2
// baseline (speedup 1.0000x reference)
#include <cuda_runtime.h>

typedef unsigned long long u64;

#define Bn   8
#define Vn   4096
#define CIN  256
#define Fn   128
#define En   256
#define NCH  16

// ---------------- scratch (device globals; no allocation in kernel_launch) ----
__device__ float g_phi [Bn*Vn*Fn];        // 16.8 MB
__device__ float g_a   [Bn*Fn];
__device__ float g_M   [Bn*Vn*En];        // conv output M; later reused as y
__device__ float g_t   [Bn*Fn*En];        // a-scaled phi^T M
__device__ float g_H   [Bn*Vn*En];        // H, then D_H in place
__device__ float g_Binv[Bn*En];
__device__ float g_tmp [Bn*En*CIN];       // Binv-scaled D_H^T x
__device__ float g_p1  [Bn*NCH*Fn*En];    // split-K partials for phi^T M
__device__ float g_p2  [Bn*NCH*En*CIN];   // split-K partials for D_H^T x
__device__ float g_xp  [Bn*NCH*CIN];      // mean partials
__device__ float g_cp  [Bn*NCH*En];       // colsum partials

// ---------------- packed f32x2 helpers (Blackwell FFMA2) ---------------------
__device__ __forceinline__ u64 pack2(float x){
    u64 r; asm("mov.b64 %0, {%1, %1};" : "=l"(r) : "f"(x)); return r;
}
__device__ __forceinline__ void ffma2(u64 &c, u64 a, u64 b){
    asm("fma.rn.f32x2 %0, %1, %2, %0;" : "+l"(c) : "l"(a), "l"(b));
}
__device__ __forceinline__ float2 unpk(u64 v){
    float2 r; asm("mov.b64 {%0, %1}, %2;" : "=f"(r.x), "=f"(r.y) : "l"(v)); return r;
}

// ---------------- shared 128x128 microkernel, BK=16, 256 thr, 8x8/thr -------
__device__ __forceinline__ void mma_tile(const float* As, const float* Bs,
                                         u64 acc[8][4], int ty8, int tx8){
#pragma unroll
    for (int k=0;k<16;k++){
        const float* ar = As + k*128 + ty8;
        float4 av0 = *(const float4*)ar;
        float4 av1 = *(const float4*)(ar+4);
        const ulonglong2* br = (const ulonglong2*)(Bs + k*128 + tx8);
        ulonglong2 q0 = br[0];
        ulonglong2 q1 = br[1];
        float a[8] = {av0.x,av0.y,av0.z,av0.w,av1.x,av1.y,av1.z,av1.w};
#pragma unroll
        for (int i=0;i<8;i++){
            u64 a2 = pack2(a[i]);
            ffma2(acc[i][0], a2, q0.x);
            ffma2(acc[i][1], a2, q0.y);
            ffma2(acc[i][2], a2, q1.x);
            ffma2(acc[i][3], a2, q1.y);
        }
    }
}

// ---------------- generic NN GEMM: C = A(MxK) * B(KxN), batched -------------
// epi: 0 -> C = acc + aux[n] (bias)   1 -> C = |acc|   2 -> C = aux[m,n] - acc
__global__ void __launch_bounds__(256)
sgemm_nn(const float* __restrict__ A, const float* __restrict__ Bm,
         float* __restrict__ C, const float* __restrict__ aux,
         int M, int N, int K,
         long sA, long sB, long sC, long sAux, int epi)
{
    __shared__ float As[16*128];
    __shared__ float Bs[16*128];
    int b = blockIdx.z;
    A += (long)b*sA; Bm += (long)b*sB; C += (long)b*sC;
    const float* auxp = aux ? aux + (long)b*sAux : (const float*)0;
    int m0 = blockIdx.y*128, n0 = blockIdx.x*128;
    int tid = threadIdx.x;
    int tx8 = (tid & 15)*8, ty8 = (tid >> 4)*8;
    int am = tid >> 1, ak = (tid & 1)*8;
    int brw = tid >> 5, bc = (tid & 31)*4;
    u64 acc[8][4];
#pragma unroll
    for (int i=0;i<8;i++)
#pragma unroll
        for (int j=0;j<4;j++) acc[i][j]=0ull;

    const float* Arow = A + (long)(m0+am)*K + ak;
    for (int k0=0;k0<K;k0+=16){
        float4 a0 = *(const float4*)(Arow + k0);
        float4 a1 = *(const float4*)(Arow + k0 + 4);
        As[(ak+0)*128+am]=a0.x; As[(ak+1)*128+am]=a0.y;
        As[(ak+2)*128+am]=a0.z; As[(ak+3)*128+am]=a0.w;
        As[(ak+4)*128+am]=a1.x; As[(ak+5)*128+am]=a1.y;
        As[(ak+6)*128+am]=a1.z; As[(ak+7)*128+am]=a1.w;
        *(float4*)&Bs[brw*128+bc]     = *(const float4*)(Bm + (long)(k0+brw)*N + n0 + bc);
        *(float4*)&Bs[(brw+8)*128+bc] = *(const float4*)(Bm + (long)(k0+brw+8)*N + n0 + bc);
        __syncthreads();
        mma_tile(As, Bs, acc, ty8, tx8);
        __syncthreads();
    }
#pragma unroll
    for (int i=0;i<8;i++){
        int m = m0 + ty8 + i;
        float o[8];
#pragma unroll
        for (int j=0;j<4;j++){ float2 u = unpk(acc[i][j]); o[2*j]=u.x; o[2*j+1]=u.y; }
        if (epi==0){
#pragma unroll
            for (int j=0;j<8;j++) o[j] += auxp[n0+tx8+j];
        } else if (epi==1){
#pragma unroll
            for (int j=0;j<8;j++) o[j] = fabsf(o[j]);
        } else {
#pragma unroll
            for (int j=0;j<8;j++) o[j] = auxp[(long)m*N + n0+tx8+j] - o[j];
        }
        float* crow = C + (long)m*N + n0 + tx8;
        *(float4*)crow     = make_float4(o[0],o[1],o[2],o[3]);
        *(float4*)(crow+4) = make_float4(o[4],o[5],o[6],o[7]);
    }
}

// ---------------- TN GEMM partials: P[b,s] = A_chunk^T * B_chunk ------------
// A: [K x Mo] rows (lda), B: [K x No] rows (ldb); split-K over NCH chunks
__global__ void __launch_bounds__(256)
sgemm_tn(const float* __restrict__ A, const float* __restrict__ Bm,
         float* __restrict__ P, int Mo, int No, int lda, int ldb, int Kc,
         long sA, long sB)
{
    __shared__ float As[16*128];
    __shared__ float Bs[16*128];
    int b = blockIdx.z / NCH, s = blockIdx.z % NCH;
    A  += (long)b*sA + (long)s*Kc*lda;
    Bm += (long)b*sB + (long)s*Kc*ldb;
    P  += (long)(b*NCH+s)*Mo*No;
    int m0 = blockIdx.y*128, n0 = blockIdx.x*128;
    int tid = threadIdx.x;
    int tx8=(tid&15)*8, ty8=(tid>>4)*8;
    int rw = tid>>5, cl=(tid&31)*4;
    u64 acc[8][4];
#pragma unroll
    for (int i=0;i<8;i++)
#pragma unroll
        for (int j=0;j<4;j++) acc[i][j]=0ull;

    for (int k0=0;k0<Kc;k0+=16){
        *(float4*)&As[rw*128+cl]     = *(const float4*)(A + (long)(k0+rw)*lda + m0 + cl);
        *(float4*)&As[(rw+8)*128+cl] = *(const float4*)(A + (long)(k0+rw+8)*lda + m0 + cl);
        *(float4*)&Bs[rw*128+cl]     = *(const float4*)(Bm + (long)(k0+rw)*ldb + n0 + cl);
        *(float4*)&Bs[(rw+8)*128+cl] = *(const float4*)(Bm + (long)(k0+rw+8)*ldb + n0 + cl);
        __syncthreads();
        mma_tile(As,Bs,acc,ty8,tx8);
        __syncthreads();
    }
#pragma unroll
    for (int i=0;i<8;i++){
        float o[8];
#pragma unroll
        for (int j=0;j<4;j++){ float2 u=unpk(acc[i][j]); o[2*j]=u.x; o[2*j+1]=u.y; }
        float* crow = P + (long)(m0+ty8+i)*No + n0 + tx8;
        *(float4*)crow     = make_float4(o[0],o[1],o[2],o[3]);
        *(float4*)(crow+4) = make_float4(o[4],o[5],o[6],o[7]);
    }
}

// ---------------- 7x7 SAME conv as implicit GEMM ----------------------------
__global__ void __launch_bounds__(256)
conv7(const float* __restrict__ x, const float* __restrict__ wm,
      const float* __restrict__ bm, float* __restrict__ out)
{
    __shared__ float As[16*128];
    __shared__ float Bs[16*128];
    int tid=threadIdx.x;
    int tx8=(tid&15)*8, ty8=(tid>>4)*8;
    int n0=blockIdx.x*128, p0=blockIdx.y*128, b=blockIdx.z;
    int am=tid>>1, ac=(tid&1)*8;
    int pa=p0+am, ha=pa>>6, wa=pa&63;
    int brw=tid>>5, bc=(tid&31)*4;
    const float* xb = x + (long)b*Vn*CIN;
    u64 acc[8][4];
#pragma unroll
    for (int i=0;i<8;i++)
#pragma unroll
        for (int j=0;j<4;j++) acc[i][j]=0ull;

    for (int tap=0;tap<49;tap++){
        int ky=tap/7, kx=tap-ky*7;
        int hs=ha+ky-3, ws=wa+kx-3;
        bool valid = ((unsigned)hs<64u) && ((unsigned)ws<64u);
        const float* asrc = xb + (long)((hs<<6)+ws)*CIN + ac;
        const float* wsrc = wm + (long)tap*CIN*En + n0;
        for (int cc=0;cc<CIN;cc+=16){
            float4 a0,a1;
            if (valid){
                a0 = *(const float4*)(asrc+cc);
                a1 = *(const float4*)(asrc+cc+4);
            } else {
                a0 = make_float4(0.f,0.f,0.f,0.f); a1 = a0;
            }
            As[(ac+0)*128+am]=a0.x; As[(ac+1)*128+am]=a0.y;
            As[(ac+2)*128+am]=a0.z; As[(ac+3)*128+am]=a0.w;
            As[(ac+4)*128+am]=a1.x; As[(ac+5)*128+am]=a1.y;
            As[(ac+6)*128+am]=a1.z; As[(ac+7)*128+am]=a1.w;
            *(float4*)&Bs[brw*128+bc]     = *(const float4*)(wsrc + (long)(cc+brw)*En + bc);
            *(float4*)&Bs[(brw+8)*128+bc] = *(const float4*)(wsrc + (long)(cc+brw+8)*En + bc);
            __syncthreads();
            mma_tile(As,Bs,acc,ty8,tx8);
            __syncthreads();
        }
    }
    float bias[8];
#pragma unroll
    for (int j=0;j<8;j++) bias[j]=bm[n0+tx8+j];
#pragma unroll
    for (int i=0;i<8;i++){
        float o[8];
#pragma unroll
        for (int j=0;j<4;j++){ float2 u=unpk(acc[i][j]); o[2*j]=u.x; o[2*j+1]=u.y; }
#pragma unroll
        for (int j=0;j<8;j++) o[j]+=bias[j];
        float* crow = out + ((long)b*Vn + p0+ty8+i)*En + n0 + tx8;
        *(float4*)crow     = make_float4(o[0],o[1],o[2],o[3]);
        *(float4*)(crow+4) = make_float4(o[4],o[5],o[6],o[7]);
    }
}

// ---------------- small kernels ---------------------------------------------
__global__ void xmean_part(const float* __restrict__ x, float* __restrict__ xp){
    int b=blockIdx.x, s=blockIdx.y, tid=threadIdx.x;
    const float* p = x + ((long)b*Vn + s*(Vn/NCH))*CIN + tid;
    float acc=0.f;
    for (int i=0;i<Vn/NCH;i++) acc += p[(long)i*CIN];
    xp[(b*NCH+s)*CIN+tid]=acc;
}

__global__ void a_kernel(const float* __restrict__ xp, const float* __restrict__ w_a,
                         const float* __restrict__ b_a, float* __restrict__ a){
    __shared__ float xm[CIN];
    int b=blockIdx.x, tid=threadIdx.x;
    float acc=0.f;
    for (int ch=0;ch<NCH;ch++) acc += xp[(b*NCH+ch)*CIN+tid];
    xm[tid] = acc * (1.0f/(float)Vn);
    __syncthreads();
    if (tid < Fn){
        float s = b_a[tid];
        for (int c=0;c<CIN;c++) s += xm[c]*w_a[c*Fn+tid];
        a[b*Fn+tid] = s;
    }
}

__global__ void colsum_part(const float* __restrict__ Hm, float* __restrict__ cp){
    int b=blockIdx.x, s=blockIdx.y, tid=threadIdx.x;
    const float* p = Hm + ((long)b*Vn + s*(Vn/NCH))*En + tid;
    float acc=0.f;
    for (int i=0;i<Vn/NCH;i++) acc += p[(long)i*En];
    cp[(b*NCH+s)*En+tid]=acc;
}

__global__ void binv_kernel(const float* __restrict__ cp, float* __restrict__ binv){
    int b=blockIdx.x, tid=threadIdx.x;
    float s=0.f;
    for (int ch=0;ch<NCH;ch++) s += cp[(b*NCH+ch)*En+tid];
    binv[b*En+tid] = 1.0f/s;
}

__global__ void rowscale_kernel(float* __restrict__ H){
    __shared__ float red[256];
    long row = blockIdx.x;
    int tid=threadIdx.x;
    float* hr = H + row*En;
    float v = hr[tid];
    red[tid]=v; __syncthreads();
    for (int s=128;s>0;s>>=1){ if(tid<s) red[tid]+=red[tid+s]; __syncthreads(); }
    hr[tid] = v * rsqrtf(red[0]);
}

// out[b,r,c] = scale[b,r] * sum_s part[b,s,r,c]
__global__ void reduce_scale(float* __restrict__ out, const float* __restrict__ part,
                             const float* __restrict__ scale, int R, int C){
    long idx = (long)blockIdx.x*256 + threadIdx.x;
    int c = (int)(idx % C); long rc = idx / C; int r = (int)(rc % R); int b = (int)(rc / R);
    float s=0.f;
#pragma unroll
    for (int ch=0;ch<NCH;ch++) s += part[((long)(b*NCH+ch)*R + r)*C + c];
    out[idx] = s * scale[b*R + r];
}

// ---------------- host launch ------------------------------------------------
extern "C" void kernel_launch(void* const* d_in, const int* in_sizes, int n_in,
                              void* d_out, int out_size){
    (void)in_sizes; (void)n_in; (void)out_size;
    const float* x    =(const float*)d_in[0];
    const float* wphi =(const float*)d_in[1];
    const float* bphi =(const float*)d_in[2];
    const float* wa   =(const float*)d_in[3];
    const float* ba   =(const float*)d_in[4];
    const float* wm   =(const float*)d_in[5];
    const float* bm   =(const float*)d_in[6];
    const float* w2   =(const float*)d_in[7];
    const float* b2   =(const float*)d_in[8];
    float* out=(float*)d_out;

    float *phi,*aV,*Mb,*tb,*Hb,*binv,*tmp,*p1,*p2,*xp,*cp;
    cudaGetSymbolAddress((void**)&phi , g_phi);
    cudaGetSymbolAddress((void**)&aV  , g_a);
    cudaGetSymbolAddress((void**)&Mb  , g_M);
    cudaGetSymbolAddress((void**)&tb  , g_t);
    cudaGetSymbolAddress((void**)&Hb  , g_H);
    cudaGetSymbolAddress((void**)&binv, g_Binv);
    cudaGetSymbolAddress((void**)&tmp , g_tmp);
    cudaGetSymbolAddress((void**)&p1  , g_p1);
    cudaGetSymbolAddress((void**)&p2  , g_p2);
    cudaGetSymbolAddress((void**)&xp  , g_xp);
    cudaGetSymbolAddress((void**)&cp  , g_cp);

    // mean(x) -> a
    xmean_part<<<dim3(Bn,NCH),256>>>(x, xp);
    a_kernel<<<Bn,256>>>(xp, wa, ba, aV);

    // phi = x @ w_phi + b_phi   [32768 x 128]
    sgemm_nn<<<dim3(1,256,1),256>>>(x, wphi, phi, bphi, Bn*Vn, Fn, CIN, 0,0,0,0, 0);

    // M = conv7x7(x, w_m) + b_m   [B,V,E]
    conv7<<<dim3(2,32,Bn),256>>>(x, wm, bm, Mb);

    // t = a * (phi^T @ M)  (split-K partials + scaled reduce)
    sgemm_tn<<<dim3(2,1,Bn*NCH),256>>>(phi, Mb, p1, Fn, En, Fn, En, Vn/NCH,
                                       (long)Vn*Fn, (long)Vn*En);
    reduce_scale<<<(Bn*Fn*En)/256,256>>>(tb, p1, aV, Fn, En);

    // H = |phi @ t|   [B,V,E]
    sgemm_nn<<<dim3(2,32,Bn),256>>>(phi, tb, Hb, (const float*)0, Vn, En, Fn,
                                    (long)Vn*Fn, (long)Fn*En, (long)Vn*En, 0, 1);

    // Binv from column sums of H (before in-place scaling)
    colsum_part<<<dim3(Bn,NCH),256>>>(Hb, cp);
    binv_kernel<<<Bn,256>>>(cp, binv);

    // H <- D^{-1/2} H  (in place)
    rowscale_kernel<<<Bn*Vn,256>>>(Hb);

    // tmp = Binv * (D_H^T @ x)
    sgemm_tn<<<dim3(2,2,Bn*NCH),256>>>(Hb, x, p2, En, CIN, En, CIN, Vn/NCH,
                                       (long)Vn*En, (long)Vn*CIN);
    reduce_scale<<<(Bn*En*CIN)/256,256>>>(tmp, p2, binv, En, CIN);

    // y = x - D_H @ tmp   (reuse g_M as y)
    sgemm_nn<<<dim3(2,32,Bn),256>>>(Hb, tmp, Mb, x, Vn, En, En,
                                    (long)Vn*En, (long)En*CIN, (long)Vn*En, (long)Vn*CIN, 2);

    // out = y @ weight_2 + bias_2
    sgemm_nn<<<dim3(2,256,1),256>>>(Mb, w2, out, b2, Bn*Vn, 256, 256, 0,0,0,0, 0);
}

// round 5
// speedup vs baseline: 1.8725x; 1.8725x over previous
#include <cuda_runtime.h>
#include <cuda_bf16.h>
#include <cstdint>

typedef unsigned long long u64;

#define Bn   8
#define Vn   4096
#define CIN  256
#define Fn   128
#define En   256
#define NCH  16

// ---------------- scratch (device globals) -----------------------------------
__device__ float g_phi [Bn*Vn*Fn];
__device__ float g_a   [Bn*Fn];
__device__ float g_M   [Bn*Vn*En];        // conv output M; later reused as y
__device__ float g_t   [Bn*Fn*En];
__device__ float g_H   [Bn*Vn*En];
__device__ float g_Binv[Bn*En];
__device__ float g_tmp [Bn*En*CIN];
__device__ float g_p1  [Bn*NCH*Fn*En];
__device__ float g_p2  [Bn*NCH*En*CIN];
__device__ float g_xp  [Bn*NCH*CIN];
__device__ float g_cp  [Bn*NCH*En];
// bf16 split operands for the tensor-core conv
__device__ __nv_bfloat16 g_xh [Bn*Vn*CIN];
__device__ __nv_bfloat16 g_xl [Bn*Vn*CIN];
__device__ __nv_bfloat16 g_wh [49*CIN*En];   // natural layout [tap][c][e]
__device__ __nv_bfloat16 g_wl [49*CIN*En];

// =================== bf16 split prep =========================================
__global__ void cvt_split(const float* __restrict__ src, __nv_bfloat16* __restrict__ hi,
                          __nv_bfloat16* __restrict__ lo, long n){
    long i = (long)blockIdx.x*256 + threadIdx.x;
    if (i >= n) return;
    float v = src[i];
    __nv_bfloat16 h = __float2bfloat16_rn(v);
    hi[i] = h;
    lo[i] = __float2bfloat16_rn(v - __bfloat162float(h));
}

// =================== HMMA conv (mma.sync bf16, 2-term split) =================
__device__ __forceinline__ uint32_t smem_u32(const void* p) {
    uint32_t a;
    asm("{ .reg .u64 t; cvta.to.shared.u64 t, %1; cvt.u32.u64 %0, t; }" : "=r"(a) : "l"(p));
    return a;
}
__device__ __forceinline__ void cp16(uint32_t d, const void* s, int sz){
    asm volatile("cp.async.cg.shared.global [%0], [%1], 16, %2;"
                 :: "r"(d), "l"(s), "r"(sz) : "memory");
}
__device__ __forceinline__ void ldsm4(uint32_t* r, uint32_t a){
    asm volatile("ldmatrix.sync.aligned.m8n8.x4.shared.b16 {%0,%1,%2,%3}, [%4];"
                 : "=r"(r[0]),"=r"(r[1]),"=r"(r[2]),"=r"(r[3]) : "r"(a));
}
__device__ __forceinline__ void ldsm4t(uint32_t* r, uint32_t a){
    asm volatile("ldmatrix.sync.aligned.m8n8.x4.trans.shared.b16 {%0,%1,%2,%3}, [%4];"
                 : "=r"(r[0]),"=r"(r[1]),"=r"(r[2]),"=r"(r[3]) : "r"(a));
}
__device__ __forceinline__ void mma16816(float* c, const uint32_t* a, uint32_t b0, uint32_t b1){
    asm volatile("mma.sync.aligned.m16n8k16.row.col.f32.bf16.bf16.f32 "
                 "{%0,%1,%2,%3}, {%4,%5,%6,%7}, {%8,%9}, {%0,%1,%2,%3};"
                 : "+f"(c[0]),"+f"(c[1]),"+f"(c[2]),"+f"(c[3])
                 : "r"(a[0]),"r"(a[1]),"r"(a[2]),"r"(a[3]), "r"(b0),"r"(b1));
}

// smem element offsets (bf16 elems)
#define A_LD   40
#define B_LD   136
#define OFF_AH 0
#define OFF_AL 5120          // 128*40
#define OFF_BH 10240
#define OFF_BL 14592         // +32*136
#define STAGE_E 18944        // elems per stage
#define CONV_SMEM (2*STAGE_E*2)   // 75776 bytes
#define NCHUNK 392           // 49 taps * 8 chunks of 32 ch

__device__ __forceinline__ void load_chunk(
    uint32_t smb, int stage,
    const __nv_bfloat16* __restrict__ xh, const __nv_bfloat16* __restrict__ xl,
    const __nv_bfloat16* __restrict__ wh, const __nv_bfloat16* __restrict__ wl,
    long bV, int p0, int n0, int ic, int tid)
{
    int tap = ic >> 3, c0 = (ic & 7) * 32;
    int ky = tap / 7, kx = tap - ky*7;
    uint32_t base = smb + stage*STAGE_E*2;

    // ---- A: 128 rows x 32 ch, hi & lo ----
    int row  = tid >> 1;
    int koff = (tid & 1) * 16;
    int pos = p0 + row;
    int hs = (pos >> 6) + ky - 3, ws = (pos & 63) + kx - 3;
    int sz = (((unsigned)hs < 64u) && ((unsigned)ws < 64u)) ? 16 : 0;
    long sidx = sz ? (bV + ((hs << 6) + ws)) * CIN + c0 + koff : 0;
    uint32_t da = base + (uint32_t)(OFF_AH + row*A_LD + koff)*2;
    cp16(da,      xh + sidx,     sz);
    cp16(da + 16, xh + sidx + 8, sz);
    uint32_t dal = base + (uint32_t)(OFF_AL + row*A_LD + koff)*2;
    cp16(dal,      xl + sidx,     sz);
    cp16(dal + 16, xl + sidx + 8, sz);

    // ---- B: 32 ch rows x 128 E cols, hi & lo ----
    #pragma unroll
    for (int q = 0; q < 2; q++){
        int qq = tid*2 + q;
        int brow = qq >> 4;
        int bcol = (qq & 15) * 8;
        long widx = ((long)(tap*CIN + c0 + brow))*En + n0 + bcol;
        uint32_t db = base + (uint32_t)(OFF_BH + brow*B_LD + bcol)*2;
        cp16(db, wh + widx, 16);
        uint32_t dbl = base + (uint32_t)(OFF_BL + brow*B_LD + bcol)*2;
        cp16(dbl, wl + widx, 16);
    }
    asm volatile("cp.async.commit_group;" ::: "memory");
}

__global__ void __launch_bounds__(256)
conv_mma(const __nv_bfloat16* __restrict__ xh, const __nv_bfloat16* __restrict__ xl,
         const __nv_bfloat16* __restrict__ wh, const __nv_bfloat16* __restrict__ wl,
         const float* __restrict__ bm, float* __restrict__ out)
{
    extern __shared__ char smem[];
    uint32_t smb = smem_u32(smem);
    int tid = threadIdx.x;
    int wid = tid >> 5, lane = tid & 31;
    int n0 = blockIdx.x * 128;
    int p0 = blockIdx.y * 128;
    int b  = blockIdx.z;
    long bV = (long)b * Vn;

    int mbase = (wid & 3) * 32;
    int nbase = (wid >> 2) * 64;

    float acc[2][8][4];
    #pragma unroll
    for (int i=0;i<2;i++)
    #pragma unroll
        for (int j=0;j<8;j++)
        #pragma unroll
            for (int k=0;k<4;k++) acc[i][j][k]=0.f;

    load_chunk(smb, 0, xh, xl, wh, wl, bV, p0, n0, 0, tid);
    load_chunk(smb, 1, xh, xl, wh, wl, bV, p0, n0, 1, tid);

    for (int ic = 0; ic < NCHUNK; ic++){
        if (ic < NCHUNK-2) asm volatile("cp.async.wait_group 1;" ::: "memory");
        else               asm volatile("cp.async.wait_group 0;" ::: "memory");
        __syncthreads();

        uint32_t sa = smb + (uint32_t)(ic & 1)*STAGE_E*2;
        #pragma unroll
        for (int kk = 0; kk < 2; kk++){
            uint32_t ah[2][4], al[2][4];
            #pragma unroll
            for (int mt = 0; mt < 2; mt++){
                uint32_t ad = sa + (uint32_t)((mbase + mt*16 + (lane & 15))*A_LD
                                              + kk*16 + (lane >> 4)*8)*2;
                ldsm4(ah[mt], ad);
                ldsm4(al[mt], ad + OFF_AL*2);
            }
            #pragma unroll
            for (int nf = 0; nf < 4; nf++){
                uint32_t bh[4], bl[4];
                uint32_t bd = sa + (uint32_t)(OFF_BH + (kk*16 + (lane & 15))*B_LD
                                              + nbase + nf*16 + (lane >> 4)*8)*2;
                ldsm4t(bh, bd);
                ldsm4t(bl, bd + (OFF_BL - OFF_BH)*2);
                #pragma unroll
                for (int mt = 0; mt < 2; mt++){
                    float* c0 = acc[mt][nf*2];
                    float* c1 = acc[mt][nf*2+1];
                    mma16816(c0, ah[mt], bh[0], bh[1]);   // hi*hi
                    mma16816(c1, ah[mt], bh[2], bh[3]);
                    mma16816(c0, ah[mt], bl[0], bl[1]);   // hi*lo
                    mma16816(c1, ah[mt], bl[2], bl[3]);
                    mma16816(c0, al[mt], bh[0], bh[1]);   // lo*hi
                    mma16816(c1, al[mt], bh[2], bh[3]);
                }
            }
        }
        __syncthreads();
        if (ic + 2 < NCHUNK)
            load_chunk(smb, ic & 1, xh, xl, wh, wl, bV, p0, n0, ic + 2, tid);
    }

    // epilogue
    #pragma unroll
    for (int mt = 0; mt < 2; mt++){
        long r0 = bV + p0 + mbase + mt*16 + (lane >> 2);
        #pragma unroll
        for (int n8 = 0; n8 < 8; n8++){
            int col = n0 + nbase + n8*8 + (lane & 3)*2;
            float b0 = bm[col], b1 = bm[col+1];
            float* c = acc[mt][n8];
            *(float2*)(out + r0*En + col)     = make_float2(c[0]+b0, c[1]+b1);
            *(float2*)(out + (r0+8)*En + col) = make_float2(c[2]+b0, c[3]+b1);
        }
    }
}

// =================== FFMA2 fp32 GEMMs (unchanged from R2) ====================
__device__ __forceinline__ u64 pack2(float x){
    u64 r; asm("mov.b64 %0, {%1, %1};" : "=l"(r) : "f"(x)); return r;
}
__device__ __forceinline__ void ffma2(u64 &c, u64 a, u64 b){
    asm("fma.rn.f32x2 %0, %1, %2, %0;" : "+l"(c) : "l"(a), "l"(b));
}
__device__ __forceinline__ float2 unpk(u64 v){
    float2 r; asm("mov.b64 {%0, %1}, %2;" : "=f"(r.x), "=f"(r.y) : "l"(v)); return r;
}

__device__ __forceinline__ void mma_tile(const float* As, const float* Bs,
                                         u64 acc[8][4], int ty8, int tx8){
#pragma unroll
    for (int k=0;k<16;k++){
        const float* ar = As + k*128 + ty8;
        float4 av0 = *(const float4*)ar;
        float4 av1 = *(const float4*)(ar+4);
        const ulonglong2* br = (const ulonglong2*)(Bs + k*128 + tx8);
        ulonglong2 q0 = br[0];
        ulonglong2 q1 = br[1];
        float a[8] = {av0.x,av0.y,av0.z,av0.w,av1.x,av1.y,av1.z,av1.w};
#pragma unroll
        for (int i=0;i<8;i++){
            u64 a2 = pack2(a[i]);
            ffma2(acc[i][0], a2, q0.x);
            ffma2(acc[i][1], a2, q0.y);
            ffma2(acc[i][2], a2, q1.x);
            ffma2(acc[i][3], a2, q1.y);
        }
    }
}

__global__ void __launch_bounds__(256)
sgemm_nn(const float* __restrict__ A, const float* __restrict__ Bm,
         float* __restrict__ C, const float* __restrict__ aux,
         int M, int N, int K,
         long sA, long sB, long sC, long sAux, int epi)
{
    __shared__ float As[16*128];
    __shared__ float Bs[16*128];
    int b = blockIdx.z;
    A += (long)b*sA; Bm += (long)b*sB; C += (long)b*sC;
    const float* auxp = aux ? aux + (long)b*sAux : (const float*)0;
    int m0 = blockIdx.y*128, n0 = blockIdx.x*128;
    int tid = threadIdx.x;
    int tx8 = (tid & 15)*8, ty8 = (tid >> 4)*8;
    int am = tid >> 1, ak = (tid & 1)*8;
    int brw = tid >> 5, bc = (tid & 31)*4;
    u64 acc[8][4];
#pragma unroll
    for (int i=0;i<8;i++)
#pragma unroll
        for (int j=0;j<4;j++) acc[i][j]=0ull;

    const float* Arow = A + (long)(m0+am)*K + ak;
    for (int k0=0;k0<K;k0+=16){
        float4 a0 = *(const float4*)(Arow + k0);
        float4 a1 = *(const float4*)(Arow + k0 + 4);
        As[(ak+0)*128+am]=a0.x; As[(ak+1)*128+am]=a0.y;
        As[(ak+2)*128+am]=a0.z; As[(ak+3)*128+am]=a0.w;
        As[(ak+4)*128+am]=a1.x; As[(ak+5)*128+am]=a1.y;
        As[(ak+6)*128+am]=a1.z; As[(ak+7)*128+am]=a1.w;
        *(float4*)&Bs[brw*128+bc]     = *(const float4*)(Bm + (long)(k0+brw)*N + n0 + bc);
        *(float4*)&Bs[(brw+8)*128+bc] = *(const float4*)(Bm + (long)(k0+brw+8)*N + n0 + bc);
        __syncthreads();
        mma_tile(As, Bs, acc, ty8, tx8);
        __syncthreads();
    }
#pragma unroll
    for (int i=0;i<8;i++){
        int m = m0 + ty8 + i;
        float o[8];
#pragma unroll
        for (int j=0;j<4;j++){ float2 u = unpk(acc[i][j]); o[2*j]=u.x; o[2*j+1]=u.y; }
        if (epi==0){
#pragma unroll
            for (int j=0;j<8;j++) o[j] += auxp[n0+tx8+j];
        } else if (epi==1){
#pragma unroll
            for (int j=0;j<8;j++) o[j] = fabsf(o[j]);
        } else {
#pragma unroll
            for (int j=0;j<8;j++) o[j] = auxp[(long)m*N + n0+tx8+j] - o[j];
        }
        float* crow = C + (long)m*N + n0 + tx8;
        *(float4*)crow     = make_float4(o[0],o[1],o[2],o[3]);
        *(float4*)(crow+4) = make_float4(o[4],o[5],o[6],o[7]);
    }
}

__global__ void __launch_bounds__(256)
sgemm_tn(const float* __restrict__ A, const float* __restrict__ Bm,
         float* __restrict__ P, int Mo, int No, int lda, int ldb, int Kc,
         long sA, long sB)
{
    __shared__ float As[16*128];
    __shared__ float Bs[16*128];
    int b = blockIdx.z / NCH, s = blockIdx.z % NCH;
    A  += (long)b*sA + (long)s*Kc*lda;
    Bm += (long)b*sB + (long)s*Kc*ldb;
    P  += (long)(b*NCH+s)*Mo*No;
    int m0 = blockIdx.y*128, n0 = blockIdx.x*128;
    int tid = threadIdx.x;
    int tx8=(tid&15)*8, ty8=(tid>>4)*8;
    int rw = tid>>5, cl=(tid&31)*4;
    u64 acc[8][4];
#pragma unroll
    for (int i=0;i<8;i++)
#pragma unroll
        for (int j=0;j<4;j++) acc[i][j]=0ull;

    for (int k0=0;k0<Kc;k0+=16){
        *(float4*)&As[rw*128+cl]     = *(const float4*)(A + (long)(k0+rw)*lda + m0 + cl);
        *(float4*)&As[(rw+8)*128+cl] = *(const float4*)(A + (long)(k0+rw+8)*lda + m0 + cl);
        *(float4*)&Bs[rw*128+cl]     = *(const float4*)(Bm + (long)(k0+rw)*ldb + n0 + cl);
        *(float4*)&Bs[(rw+8)*128+cl] = *(const float4*)(Bm + (long)(k0+rw+8)*ldb + n0 + cl);
        __syncthreads();
        mma_tile(As,Bs,acc,ty8,tx8);
        __syncthreads();
    }
#pragma unroll
    for (int i=0;i<8;i++){
        float o[8];
#pragma unroll
        for (int j=0;j<4;j++){ float2 u=unpk(acc[i][j]); o[2*j]=u.x; o[2*j+1]=u.y; }
        float* crow = P + (long)(m0+ty8+i)*No + n0 + tx8;
        *(float4*)crow     = make_float4(o[0],o[1],o[2],o[3]);
        *(float4*)(crow+4) = make_float4(o[4],o[5],o[6],o[7]);
    }
}

// ---------------- small kernels ---------------------------------------------
__global__ void xmean_part(const float* __restrict__ x, float* __restrict__ xp){
    int b=blockIdx.x, s=blockIdx.y, tid=threadIdx.x;
    const float* p = x + ((long)b*Vn + s*(Vn/NCH))*CIN + tid;
    float acc=0.f;
    for (int i=0;i<Vn/NCH;i++) acc += p[(long)i*CIN];
    xp[(b*NCH+s)*CIN+tid]=acc;
}

__global__ void a_kernel(const float* __restrict__ xp, const float* __restrict__ w_a,
                         const float* __restrict__ b_a, float* __restrict__ a){
    __shared__ float xm[CIN];
    int b=blockIdx.x, tid=threadIdx.x;
    float acc=0.f;
    for (int ch=0;ch<NCH;ch++) acc += xp[(b*NCH+ch)*CIN+tid];
    xm[tid] = acc * (1.0f/(float)Vn);
    __syncthreads();
    if (tid < Fn){
        float s = b_a[tid];
        for (int c=0;c<CIN;c++) s += xm[c]*w_a[c*Fn+tid];
        a[b*Fn+tid] = s;
    }
}

__global__ void colsum_part(const float* __restrict__ Hm, float* __restrict__ cp){
    int b=blockIdx.x, s=blockIdx.y, tid=threadIdx.x;
    const float* p = Hm + ((long)b*Vn + s*(Vn/NCH))*En + tid;
    float acc=0.f;
    for (int i=0;i<Vn/NCH;i++) acc += p[(long)i*En];
    cp[(b*NCH+s)*En+tid]=acc;
}

__global__ void binv_kernel(const float* __restrict__ cp, float* __restrict__ binv){
    int b=blockIdx.x, tid=threadIdx.x;
    float s=0.f;
    for (int ch=0;ch<NCH;ch++) s += cp[(b*NCH+ch)*En+tid];
    binv[b*En+tid] = 1.0f/s;
}

__global__ void rowscale_kernel(float* __restrict__ H){
    __shared__ float red[256];
    long row = blockIdx.x;
    int tid=threadIdx.x;
    float* hr = H + row*En;
    float v = hr[tid];
    red[tid]=v; __syncthreads();
    for (int s=128;s>0;s>>=1){ if(tid<s) red[tid]+=red[tid+s]; __syncthreads(); }
    hr[tid] = v * rsqrtf(red[0]);
}

__global__ void reduce_scale(float* __restrict__ out, const float* __restrict__ part,
                             const float* __restrict__ scale, int R, int C){
    long idx = (long)blockIdx.x*256 + threadIdx.x;
    int c = (int)(idx % C); long rc = idx / C; int r = (int)(rc % R); int b = (int)(rc / R);
    float s=0.f;
#pragma unroll
    for (int ch=0;ch<NCH;ch++) s += part[((long)(b*NCH+ch)*R + r)*C + c];
    out[idx] = s * scale[b*R + r];
}

// ---------------- host launch ------------------------------------------------
extern "C" void kernel_launch(void* const* d_in, const int* in_sizes, int n_in,
                              void* d_out, int out_size){
    (void)in_sizes; (void)n_in; (void)out_size;
    const float* x    =(const float*)d_in[0];
    const float* wphi =(const float*)d_in[1];
    const float* bphi =(const float*)d_in[2];
    const float* wa   =(const float*)d_in[3];
    const float* ba   =(const float*)d_in[4];
    const float* wm   =(const float*)d_in[5];
    const float* bm   =(const float*)d_in[6];
    const float* w2   =(const float*)d_in[7];
    const float* b2   =(const float*)d_in[8];
    float* out=(float*)d_out;

    float *phi,*aV,*Mb,*tb,*Hb,*binv,*tmp,*p1,*p2,*xp,*cp;
    __nv_bfloat16 *xh,*xl,*wh,*wl;
    cudaGetSymbolAddress((void**)&phi , g_phi);
    cudaGetSymbolAddress((void**)&aV  , g_a);
    cudaGetSymbolAddress((void**)&Mb  , g_M);
    cudaGetSymbolAddress((void**)&tb  , g_t);
    cudaGetSymbolAddress((void**)&Hb  , g_H);
    cudaGetSymbolAddress((void**)&binv, g_Binv);
    cudaGetSymbolAddress((void**)&tmp , g_tmp);
    cudaGetSymbolAddress((void**)&p1  , g_p1);
    cudaGetSymbolAddress((void**)&p2  , g_p2);
    cudaGetSymbolAddress((void**)&xp  , g_xp);
    cudaGetSymbolAddress((void**)&cp  , g_cp);
    cudaGetSymbolAddress((void**)&xh  , g_xh);
    cudaGetSymbolAddress((void**)&xl  , g_xl);
    cudaGetSymbolAddress((void**)&wh  , g_wh);
    cudaGetSymbolAddress((void**)&wl  , g_wl);

    cudaFuncSetAttribute(conv_mma, cudaFuncAttributeMaxDynamicSharedMemorySize, CONV_SMEM);

    // bf16 split prep
    cvt_split<<<(Bn*Vn*CIN + 255)/256, 256>>>(x, xh, xl, (long)Bn*Vn*CIN);
    cvt_split<<<(49*CIN*En + 255)/256, 256>>>(wm, wh, wl, (long)49*CIN*En);

    // mean(x) -> a
    xmean_part<<<dim3(Bn,NCH),256>>>(x, xp);
    a_kernel<<<Bn,256>>>(xp, wa, ba, aV);

    // phi = x @ w_phi + b_phi   [32768 x 128]
    sgemm_nn<<<dim3(1,256,1),256>>>(x, wphi, phi, bphi, Bn*Vn, Fn, CIN, 0,0,0,0, 0);

    // M = conv7x7(x, w_m) + b_m   via HMMA bf16-split implicit GEMM
    conv_mma<<<dim3(2,32,Bn), 256, CONV_SMEM>>>(xh, xl, wh, wl, bm, Mb);

    // t = a * (phi^T @ M)
    sgemm_tn<<<dim3(2,1,Bn*NCH),256>>>(phi, Mb, p1, Fn, En, Fn, En, Vn/NCH,
                                       (long)Vn*Fn, (long)Vn*En);
    reduce_scale<<<(Bn*Fn*En)/256,256>>>(tb, p1, aV, Fn, En);

    // H = |phi @ t|
    sgemm_nn<<<dim3(2,32,Bn),256>>>(phi, tb, Hb, (const float*)0, Vn, En, Fn,
                                    (long)Vn*Fn, (long)Fn*En, (long)Vn*En, 0, 1);

    // Binv from column sums of H
    colsum_part<<<dim3(Bn,NCH),256>>>(Hb, cp);
    binv_kernel<<<Bn,256>>>(cp, binv);

    // H <- D^{-1/2} H
    rowscale_kernel<<<Bn*Vn,256>>>(Hb);

    // tmp = Binv * (D_H^T @ x)
    sgemm_tn<<<dim3(2,2,Bn*NCH),256>>>(Hb, x, p2, En, CIN, En, CIN, Vn/NCH,
                                       (long)Vn*En, (long)Vn*CIN);
    reduce_scale<<<(Bn*En*CIN)/256,256>>>(tmp, p2, binv, En, CIN);

    // y = x - D_H @ tmp
    sgemm_nn<<<dim3(2,32,Bn),256>>>(Hb, tmp, Mb, x, Vn, En, En,
                                    (long)Vn*En, (long)En*CIN, (long)Vn*En, (long)Vn*CIN, 2);

    // out = y @ weight_2 + bias_2
    sgemm_nn<<<dim3(2,256,1),256>>>(Mb, w2, out, b2, Bn*Vn, 256, 256, 0,0,0,0, 0);
}

// round 6
// speedup vs baseline: 2.1441x; 1.1450x over previous
#include <cuda_runtime.h>
#include <cuda_bf16.h>
#include <cstdint>

typedef unsigned long long u64;
typedef __nv_bfloat16 bf16;

#define Bn   8
#define Vn   4096
#define CIN  256
#define Fn   128
#define En   256
#define NCH  16

// ---------------- scratch (device globals) -----------------------------------
__device__ float g_a   [Bn*Fn];
__device__ float g_t   [Bn*Fn*En];
__device__ float g_H   [Bn*Vn*En];
__device__ float g_Binv[Bn*En];
__device__ float g_tmp [Bn*En*CIN];
__device__ float g_p1  [Bn*NCH*Fn*En];
__device__ float g_p2  [Bn*NCH*En*CIN];
__device__ float g_xp  [Bn*NCH*CIN];
__device__ float g_cp  [Bn*NCH*En];
// bf16 split operand pairs
__device__ bf16 g_xh [Bn*Vn*CIN];
__device__ bf16 g_xl [Bn*Vn*CIN];
__device__ bf16 g_wh [49*CIN*En];
__device__ bf16 g_wl [49*CIN*En];
__device__ bf16 g_phih[Bn*Vn*Fn];
__device__ bf16 g_phil[Bn*Vn*Fn];
__device__ bf16 g_Mh [Bn*Vn*En];
__device__ bf16 g_Ml [Bn*Vn*En];
__device__ bf16 g_Hh [Bn*Vn*En];
__device__ bf16 g_Hl [Bn*Vn*En];
__device__ bf16 g_yh [Bn*Vn*CIN];
__device__ bf16 g_yl [Bn*Vn*CIN];
__device__ bf16 g_th [Bn*Fn*En];
__device__ bf16 g_tl [Bn*Fn*En];
__device__ bf16 g_tmph[Bn*En*CIN];
__device__ bf16 g_tmpl[Bn*En*CIN];
__device__ bf16 g_wphih[CIN*Fn];
__device__ bf16 g_wphil[CIN*Fn];
__device__ bf16 g_w2h[CIN*En];
__device__ bf16 g_w2l[CIN*En];

// =================== helpers =================================================
__global__ void cvt_split(const float* __restrict__ src, bf16* __restrict__ hi,
                          bf16* __restrict__ lo, long n){
    long i = (long)blockIdx.x*256 + threadIdx.x;
    if (i >= n) return;
    float v = src[i];
    bf16 h = __float2bfloat16_rn(v);
    hi[i] = h;
    lo[i] = __float2bfloat16_rn(v - __bfloat162float(h));
}

__device__ __forceinline__ uint32_t smem_u32(const void* p) {
    uint32_t a;
    asm("{ .reg .u64 t; cvta.to.shared.u64 t, %1; cvt.u32.u64 %0, t; }" : "=r"(a) : "l"(p));
    return a;
}
__device__ __forceinline__ void cp16(uint32_t d, const void* s, int sz){
    asm volatile("cp.async.cg.shared.global [%0], [%1], 16, %2;"
                 :: "r"(d), "l"(s), "r"(sz) : "memory");
}
__device__ __forceinline__ void ldsm4(uint32_t* r, uint32_t a){
    asm volatile("ldmatrix.sync.aligned.m8n8.x4.shared.b16 {%0,%1,%2,%3}, [%4];"
                 : "=r"(r[0]),"=r"(r[1]),"=r"(r[2]),"=r"(r[3]) : "r"(a));
}
__device__ __forceinline__ void ldsm4t(uint32_t* r, uint32_t a){
    asm volatile("ldmatrix.sync.aligned.m8n8.x4.trans.shared.b16 {%0,%1,%2,%3}, [%4];"
                 : "=r"(r[0]),"=r"(r[1]),"=r"(r[2]),"=r"(r[3]) : "r"(a));
}
__device__ __forceinline__ void mma16816(float* c, const uint32_t* a, uint32_t b0, uint32_t b1){
    asm volatile("mma.sync.aligned.m16n8k16.row.col.f32.bf16.bf16.f32 "
                 "{%0,%1,%2,%3}, {%4,%5,%6,%7}, {%8,%9}, {%0,%1,%2,%3};"
                 : "+f"(c[0]),"+f"(c[1]),"+f"(c[2]),"+f"(c[3])
                 : "r"(a[0]),"r"(a[1]),"r"(a[2]),"r"(a[3]), "r"(b0),"r"(b1));
}
__device__ __forceinline__ void st_split2(bf16* H, bf16* L, float v0, float v1){
    bf16 h0 = __float2bfloat16_rn(v0);
    bf16 h1 = __float2bfloat16_rn(v1);
    bf16 l0 = __float2bfloat16_rn(v0 - __bfloat162float(h0));
    bf16 l1 = __float2bfloat16_rn(v1 - __bfloat162float(h1));
    __nv_bfloat162 hp; hp.x = h0; hp.y = h1;
    __nv_bfloat162 lp; lp.x = l0; lp.y = l1;
    *(__nv_bfloat162*)H = hp;
    *(__nv_bfloat162*)L = lp;
}

// shared tile constants
#define A_LD   40
#define B_LD   136
#define OFF_AH 0
#define OFF_AL 5120
#define OFF_BH 10240
#define OFF_BL 14592
#define STAGE_E 18944
#define CONV_SMEM (2*STAGE_E*2)
#define NCHUNK 392

// inner 3-pass MMA block (shared by conv + NN + TN)
#define COMPUTE_TILE(sa_ah, sa_al, sa_bh, sa_bl, LOAD_A)                        \
    _Pragma("unroll")                                                           \
    for (int kk = 0; kk < 2; kk++){                                             \
        uint32_t ah[2][4], al[2][4];                                            \
        LOAD_A;                                                                 \
        _Pragma("unroll")                                                       \
        for (int nf = 0; nf < 4; nf++){                                         \
            uint32_t bh[4], bl[4];                                              \
            uint32_t bd = (sa_bh) + (uint32_t)((kk*16 + (lane & 15))*B_LD       \
                                          + nbase + nf*16 + (lane >> 4)*8)*2;   \
            ldsm4t(bh, bd);                                                     \
            ldsm4t(bl, bd + ((sa_bl)-(sa_bh)));                                 \
            _Pragma("unroll")                                                   \
            for (int mt = 0; mt < 2; mt++){                                     \
                float* c0 = acc[mt][nf*2];                                      \
                float* c1 = acc[mt][nf*2+1];                                    \
                mma16816(c0, ah[mt], bh[0], bh[1]);                             \
                mma16816(c1, ah[mt], bh[2], bh[3]);                             \
                mma16816(c0, ah[mt], bl[0], bl[1]);                             \
                mma16816(c1, ah[mt], bl[2], bl[3]);                             \
                mma16816(c0, al[mt], bh[0], bh[1]);                             \
                mma16816(c1, al[mt], bh[2], bh[3]);                             \
            }                                                                   \
        }                                                                       \
    }

// =================== conv (unchanged core, split-output epilogue) ============
__device__ __forceinline__ void conv_load_chunk(
    uint32_t smb, int stage,
    const bf16* __restrict__ xh, const bf16* __restrict__ xl,
    const bf16* __restrict__ wh, const bf16* __restrict__ wl,
    long bV, int p0, int n0, int ic, int tid)
{
    int tap = ic >> 3, c0 = (ic & 7) * 32;
    int ky = tap / 7, kx = tap - ky*7;
    uint32_t base = smb + stage*STAGE_E*2;

    int row  = tid >> 1;
    int koff = (tid & 1) * 16;
    int pos = p0 + row;
    int hs = (pos >> 6) + ky - 3, ws = (pos & 63) + kx - 3;
    int sz = (((unsigned)hs < 64u) && ((unsigned)ws < 64u)) ? 16 : 0;
    long sidx = sz ? (bV + ((hs << 6) + ws)) * CIN + c0 + koff : 0;
    uint32_t da = base + (uint32_t)(OFF_AH + row*A_LD + koff)*2;
    cp16(da,      xh + sidx,     sz);
    cp16(da + 16, xh + sidx + 8, sz);
    uint32_t dal = base + (uint32_t)(OFF_AL + row*A_LD + koff)*2;
    cp16(dal,      xl + sidx,     sz);
    cp16(dal + 16, xl + sidx + 8, sz);

    #pragma unroll
    for (int q = 0; q < 2; q++){
        int qq = tid*2 + q;
        int brow = qq >> 4;
        int bcol = (qq & 15) * 8;
        long widx = ((long)(tap*CIN + c0 + brow))*En + n0 + bcol;
        uint32_t db = base + (uint32_t)(OFF_BH + brow*B_LD + bcol)*2;
        cp16(db, wh + widx, 16);
        uint32_t dbl = base + (uint32_t)(OFF_BL + brow*B_LD + bcol)*2;
        cp16(dbl, wl + widx, 16);
    }
    asm volatile("cp.async.commit_group;" ::: "memory");
}

__global__ void __launch_bounds__(256)
conv_mma(const bf16* __restrict__ xh, const bf16* __restrict__ xl,
         const bf16* __restrict__ wh, const bf16* __restrict__ wl,
         const float* __restrict__ bm, bf16* __restrict__ Mh, bf16* __restrict__ Ml)
{
    extern __shared__ char smem[];
    uint32_t smb = smem_u32(smem);
    int tid = threadIdx.x;
    int wid = tid >> 5, lane = tid & 31;
    int n0 = blockIdx.x * 128;
    int p0 = blockIdx.y * 128;
    int b  = blockIdx.z;
    long bV = (long)b * Vn;

    int mbase = (wid & 3) * 32;
    int nbase = (wid >> 2) * 64;

    float acc[2][8][4];
    #pragma unroll
    for (int i=0;i<2;i++)
    #pragma unroll
        for (int j=0;j<8;j++)
        #pragma unroll
            for (int k=0;k<4;k++) acc[i][j][k]=0.f;

    conv_load_chunk(smb, 0, xh, xl, wh, wl, bV, p0, n0, 0, tid);
    conv_load_chunk(smb, 1, xh, xl, wh, wl, bV, p0, n0, 1, tid);

    for (int ic = 0; ic < NCHUNK; ic++){
        if (ic < NCHUNK-2) asm volatile("cp.async.wait_group 1;" ::: "memory");
        else               asm volatile("cp.async.wait_group 0;" ::: "memory");
        __syncthreads();

        uint32_t sa = smb + (uint32_t)(ic & 1)*STAGE_E*2;
        COMPUTE_TILE(sa + OFF_AH*2, sa + OFF_AL*2, sa + OFF_BH*2, sa + OFF_BL*2,
            {
                _Pragma("unroll")
                for (int mt = 0; mt < 2; mt++){
                    uint32_t ad = sa + (uint32_t)((mbase + mt*16 + (lane & 15))*A_LD
                                                  + kk*16 + (lane >> 4)*8)*2;
                    ldsm4(ah[mt], ad);
                    ldsm4(al[mt], ad + OFF_AL*2);
                }
            });
        __syncthreads();
        if (ic + 2 < NCHUNK)
            conv_load_chunk(smb, ic & 1, xh, xl, wh, wl, bV, p0, n0, ic + 2, tid);
    }

    #pragma unroll
    for (int mt = 0; mt < 2; mt++){
        long r0 = bV + p0 + mbase + mt*16 + (lane >> 2);
        #pragma unroll
        for (int n8 = 0; n8 < 8; n8++){
            int col = n0 + nbase + n8*8 + (lane & 3)*2;
            float b0 = bm[col], b1 = bm[col+1];
            float* c = acc[mt][n8];
            st_split2(Mh + r0*En + col,     Ml + r0*En + col,     c[0]+b0, c[1]+b1);
            st_split2(Mh + (r0+8)*En + col, Ml + (r0+8)*En + col, c[2]+b0, c[3]+b1);
        }
    }
}

// =================== generic NN HMMA GEMM ====================================
// C = epi(A @ B);  A [M,K] row-major split, B [K,N] row-major split
// epi 0: +bias[n]; 1: abs; 2: aux[m,n]-acc.  Outputs: Cf (fp32) and/or Ch/Cl.
__device__ __forceinline__ void nn_load_chunk(
    uint32_t smb, int stage,
    const bf16* __restrict__ Ah, const bf16* __restrict__ Al,
    const bf16* __restrict__ Bh, const bf16* __restrict__ Bl,
    int m0, int n0, int k0, int K, int N, int tid)
{
    uint32_t base = smb + stage*STAGE_E*2;
    int row  = tid >> 1;
    int koff = (tid & 1) * 16;
    long sidx = (long)(m0+row)*K + k0 + koff;
    uint32_t da = base + (uint32_t)(OFF_AH + row*A_LD + koff)*2;
    cp16(da,      Ah + sidx,     16);
    cp16(da + 16, Ah + sidx + 8, 16);
    uint32_t dal = base + (uint32_t)(OFF_AL + row*A_LD + koff)*2;
    cp16(dal,      Al + sidx,     16);
    cp16(dal + 16, Al + sidx + 8, 16);
    #pragma unroll
    for (int q = 0; q < 2; q++){
        int qq = tid*2 + q;
        int brow = qq >> 4;
        int bcol = (qq & 15) * 8;
        long widx = (long)(k0+brow)*N + n0 + bcol;
        uint32_t db = base + (uint32_t)(OFF_BH + brow*B_LD + bcol)*2;
        cp16(db, Bh + widx, 16);
        uint32_t dbl = base + (uint32_t)(OFF_BL + brow*B_LD + bcol)*2;
        cp16(dbl, Bl + widx, 16);
    }
    asm volatile("cp.async.commit_group;" ::: "memory");
}

__global__ void __launch_bounds__(256)
hgemm_nn(const bf16* __restrict__ Ah, const bf16* __restrict__ Al,
         const bf16* __restrict__ Bh, const bf16* __restrict__ Bl,
         float* __restrict__ Cf, bf16* __restrict__ Ch, bf16* __restrict__ Cl,
         const float* __restrict__ aux,
         int N, int K, long sA, long sB, long sC, long sAux, int epi)
{
    extern __shared__ char smem[];
    uint32_t smb = smem_u32(smem);
    int tid = threadIdx.x;
    int wid = tid >> 5, lane = tid & 31;
    int n0 = blockIdx.x * 128;
    int m0 = blockIdx.y * 128;
    int b  = blockIdx.z;
    Ah += (long)b*sA; Al += (long)b*sA;
    Bh += (long)b*sB; Bl += (long)b*sB;
    const float* auxp = aux ? aux + (long)b*sAux : (const float*)0;

    int mbase = (wid & 3) * 32;
    int nbase = (wid >> 2) * 64;

    float acc[2][8][4];
    #pragma unroll
    for (int i=0;i<2;i++)
    #pragma unroll
        for (int j=0;j<8;j++)
        #pragma unroll
            for (int k=0;k<4;k++) acc[i][j][k]=0.f;

    int nchunk = K >> 5;
    nn_load_chunk(smb, 0, Ah, Al, Bh, Bl, m0, n0, 0,  K, N, tid);
    nn_load_chunk(smb, 1, Ah, Al, Bh, Bl, m0, n0, 32, K, N, tid);

    for (int ic = 0; ic < nchunk; ic++){
        if (ic < nchunk-2) asm volatile("cp.async.wait_group 1;" ::: "memory");
        else               asm volatile("cp.async.wait_group 0;" ::: "memory");
        __syncthreads();
        uint32_t sa = smb + (uint32_t)(ic & 1)*STAGE_E*2;
        COMPUTE_TILE(sa + OFF_AH*2, sa + OFF_AL*2, sa + OFF_BH*2, sa + OFF_BL*2,
            {
                _Pragma("unroll")
                for (int mt = 0; mt < 2; mt++){
                    uint32_t ad = sa + (uint32_t)((mbase + mt*16 + (lane & 15))*A_LD
                                                  + kk*16 + (lane >> 4)*8)*2;
                    ldsm4(ah[mt], ad);
                    ldsm4(al[mt], ad + OFF_AL*2);
                }
            });
        __syncthreads();
        if (ic + 2 < nchunk)
            nn_load_chunk(smb, ic & 1, Ah, Al, Bh, Bl, m0, n0, (ic+2)*32, K, N, tid);
    }

    #pragma unroll
    for (int mt = 0; mt < 2; mt++){
        long r0 = m0 + mbase + mt*16 + (lane >> 2);
        #pragma unroll
        for (int n8 = 0; n8 < 8; n8++){
            int col = n0 + nbase + n8*8 + (lane & 3)*2;
            float* c = acc[mt][n8];
            float v00=c[0], v01=c[1], v10=c[2], v11=c[3];
            if (epi == 0){
                float b0 = auxp[col], b1 = auxp[col+1];
                v00+=b0; v01+=b1; v10+=b0; v11+=b1;
            } else if (epi == 1){
                v00=fabsf(v00); v01=fabsf(v01); v10=fabsf(v10); v11=fabsf(v11);
            } else {
                v00 = auxp[r0*N + col]     - v00;
                v01 = auxp[r0*N + col + 1] - v01;
                v10 = auxp[(r0+8)*N + col]     - v10;
                v11 = auxp[(r0+8)*N + col + 1] - v11;
            }
            if (Cf){
                float* base = Cf + (long)b*sC;
                *(float2*)(base + r0*N + col)     = make_float2(v00, v01);
                *(float2*)(base + (r0+8)*N + col) = make_float2(v10, v11);
            }
            if (Ch){
                bf16* bh = Ch + (long)b*sC;
                bf16* bl = Cl + (long)b*sC;
                st_split2(bh + r0*N + col,     bl + r0*N + col,     v00, v01);
                st_split2(bh + (r0+8)*N + col, bl + (r0+8)*N + col, v10, v11);
            }
        }
    }
}

// =================== TN HMMA split-K partials ================================
// P[b,s] = A_chunk^T @ B_chunk;  A [K,Mo] rows (lda), B [K,No] rows (ldb)
#define TN_AH 0
#define TN_AL 4352
#define TN_BH 8704
#define TN_BL 13056
#define TN_STAGE 17408
#define TN_SMEM (2*TN_STAGE*2)

__device__ __forceinline__ void tn_load_chunk(
    uint32_t smb, int stage,
    const bf16* __restrict__ Ah, const bf16* __restrict__ Al,
    const bf16* __restrict__ Bh, const bf16* __restrict__ Bl,
    long offA, long offB, int m0, int n0, int k0, int lda, int ldb, int tid)
{
    uint32_t base = smb + stage*TN_STAGE*2;
    #pragma unroll
    for (int q = 0; q < 2; q++){
        int qq = tid*2 + q;
        int brow = qq >> 4;
        int bcol = (qq & 15) * 8;
        long aidx = offA + (long)(k0+brow)*lda + m0 + bcol;
        uint32_t da = base + (uint32_t)(TN_AH + brow*B_LD + bcol)*2;
        cp16(da, Ah + aidx, 16);
        cp16(base + (uint32_t)(TN_AL + brow*B_LD + bcol)*2, Al + aidx, 16);
        long bidx = offB + (long)(k0+brow)*ldb + n0 + bcol;
        cp16(base + (uint32_t)(TN_BH + brow*B_LD + bcol)*2, Bh + bidx, 16);
        cp16(base + (uint32_t)(TN_BL + brow*B_LD + bcol)*2, Bl + bidx, 16);
    }
    asm volatile("cp.async.commit_group;" ::: "memory");
}

__global__ void __launch_bounds__(256)
hgemm_tn(const bf16* __restrict__ Ah, const bf16* __restrict__ Al,
         const bf16* __restrict__ Bh, const bf16* __restrict__ Bl,
         float* __restrict__ P, int Mo, int No, int lda, int ldb, int Kc,
         long sA, long sB)
{
    extern __shared__ char smem[];
    uint32_t smb = smem_u32(smem);
    int tid = threadIdx.x;
    int wid = tid >> 5, lane = tid & 31;
    int b = blockIdx.z / NCH, s = blockIdx.z % NCH;
    long offA = (long)b*sA + (long)s*Kc*lda;
    long offB = (long)b*sB + (long)s*Kc*ldb;
    P += (long)(b*NCH + s)*Mo*No;
    int n0 = blockIdx.x * 128;
    int m0 = blockIdx.y * 128;

    int mbase = (wid & 3) * 32;
    int nbase = (wid >> 2) * 64;

    float acc[2][8][4];
    #pragma unroll
    for (int i=0;i<2;i++)
    #pragma unroll
        for (int j=0;j<8;j++)
        #pragma unroll
            for (int k=0;k<4;k++) acc[i][j][k]=0.f;

    int nchunk = Kc >> 5;
    tn_load_chunk(smb, 0, Ah, Al, Bh, Bl, offA, offB, m0, n0, 0,  lda, ldb, tid);
    tn_load_chunk(smb, 1, Ah, Al, Bh, Bl, offA, offB, m0, n0, 32, lda, ldb, tid);

    // A^T fragment lane map (ldmatrix.trans on [k][m] tile):
    int krow = (lane & 7) + (lane >> 4)*8;
    int msub = ((lane >> 3) & 1)*8;

    for (int ic = 0; ic < nchunk; ic++){
        if (ic < nchunk-2) asm volatile("cp.async.wait_group 1;" ::: "memory");
        else               asm volatile("cp.async.wait_group 0;" ::: "memory");
        __syncthreads();
        uint32_t sa = smb + (uint32_t)(ic & 1)*TN_STAGE*2;
        COMPUTE_TILE(sa + TN_AH*2, sa + TN_AL*2, sa + TN_BH*2, sa + TN_BL*2,
            {
                _Pragma("unroll")
                for (int mt = 0; mt < 2; mt++){
                    uint32_t ad = sa + (uint32_t)(TN_AH + (kk*16 + krow)*B_LD
                                                  + mbase + mt*16 + msub)*2;
                    ldsm4t(ah[mt], ad);
                    ldsm4t(al[mt], ad + (TN_AL - TN_AH)*2);
                }
            });
        __syncthreads();
        if (ic + 2 < nchunk)
            tn_load_chunk(smb, ic & 1, Ah, Al, Bh, Bl, offA, offB, m0, n0, (ic+2)*32, lda, ldb, tid);
    }

    #pragma unroll
    for (int mt = 0; mt < 2; mt++){
        long r0 = m0 + mbase + mt*16 + (lane >> 2);
        #pragma unroll
        for (int n8 = 0; n8 < 8; n8++){
            int col = n0 + nbase + n8*8 + (lane & 3)*2;
            float* c = acc[mt][n8];
            *(float2*)(P + r0*No + col)     = make_float2(c[0], c[1]);
            *(float2*)(P + (r0+8)*No + col) = make_float2(c[2], c[3]);
        }
    }
}

// ---------------- small kernels ---------------------------------------------
__global__ void xmean_part(const float* __restrict__ x, float* __restrict__ xp){
    int b=blockIdx.x, s=blockIdx.y, tid=threadIdx.x;
    const float* p = x + ((long)b*Vn + s*(Vn/NCH))*CIN + tid;
    float acc=0.f;
    for (int i=0;i<Vn/NCH;i++) acc += p[(long)i*CIN];
    xp[(b*NCH+s)*CIN+tid]=acc;
}

__global__ void a_kernel(const float* __restrict__ xp, const float* __restrict__ w_a,
                         const float* __restrict__ b_a, float* __restrict__ a){
    __shared__ float xm[CIN];
    int b=blockIdx.x, tid=threadIdx.x;
    float acc=0.f;
    for (int ch=0;ch<NCH;ch++) acc += xp[(b*NCH+ch)*CIN+tid];
    xm[tid] = acc * (1.0f/(float)Vn);
    __syncthreads();
    if (tid < Fn){
        float s = b_a[tid];
        for (int c=0;c<CIN;c++) s += xm[c]*w_a[c*Fn+tid];
        a[b*Fn+tid] = s;
    }
}

__global__ void colsum_part(const float* __restrict__ Hm, float* __restrict__ cp){
    int b=blockIdx.x, s=blockIdx.y, tid=threadIdx.x;
    const float* p = Hm + ((long)b*Vn + s*(Vn/NCH))*En + tid;
    float acc=0.f;
    for (int i=0;i<Vn/NCH;i++) acc += p[(long)i*En];
    cp[(b*NCH+s)*En+tid]=acc;
}

__global__ void binv_kernel(const float* __restrict__ cp, float* __restrict__ binv){
    int b=blockIdx.x, tid=threadIdx.x;
    float s=0.f;
    for (int ch=0;ch<NCH;ch++) s += cp[(b*NCH+ch)*En+tid];
    binv[b*En+tid] = 1.0f/s;
}

// row-normalize H (fp32 in) -> split bf16 out
__global__ void rowscale_split(const float* __restrict__ H,
                               bf16* __restrict__ Hh, bf16* __restrict__ Hl){
    __shared__ float red[256];
    long row = blockIdx.x;
    int tid = threadIdx.x;
    const float* hr = H + row*En;
    float v = hr[tid];
    red[tid]=v; __syncthreads();
    for (int s=128;s>0;s>>=1){ if(tid<s) red[tid]+=red[tid+s]; __syncthreads(); }
    float o = v * rsqrtf(red[0]);
    bf16 h = __float2bfloat16_rn(o);
    Hh[row*En + tid] = h;
    Hl[row*En + tid] = __float2bfloat16_rn(o - __bfloat162float(h));
}

__global__ void reduce_scale(float* __restrict__ out, const float* __restrict__ part,
                             const float* __restrict__ scale, int R, int C){
    long idx = (long)blockIdx.x*256 + threadIdx.x;
    int c = (int)(idx % C); long rc = idx / C; int r = (int)(rc % R); int b = (int)(rc / R);
    float s=0.f;
#pragma unroll
    for (int ch=0;ch<NCH;ch++) s += part[((long)(b*NCH+ch)*R + r)*C + c];
    out[idx] = s * scale[b*R + r];
}

// ---------------- host launch ------------------------------------------------
extern "C" void kernel_launch(void* const* d_in, const int* in_sizes, int n_in,
                              void* d_out, int out_size){
    (void)in_sizes; (void)n_in; (void)out_size;
    const float* x    =(const float*)d_in[0];
    const float* wphi =(const float*)d_in[1];
    const float* bphi =(const float*)d_in[2];
    const float* wa   =(const float*)d_in[3];
    const float* ba   =(const float*)d_in[4];
    const float* wm   =(const float*)d_in[5];
    const float* bm   =(const float*)d_in[6];
    const float* w2   =(const float*)d_in[7];
    const float* b2   =(const float*)d_in[8];
    float* out=(float*)d_out;

    float *aV,*tb,*Hb,*binv,*tmp,*p1,*p2,*xp,*cp;
    bf16 *xh,*xl,*wh,*wl,*phih,*phil,*Mh,*Ml,*Hh,*Hl,*yh,*yl,*th,*tl,*tmph,*tmpl;
    bf16 *wphih,*wphil,*w2h,*w2l;
    cudaGetSymbolAddress((void**)&aV  , g_a);
    cudaGetSymbolAddress((void**)&tb  , g_t);
    cudaGetSymbolAddress((void**)&Hb  , g_H);
    cudaGetSymbolAddress((void**)&binv, g_Binv);
    cudaGetSymbolAddress((void**)&tmp , g_tmp);
    cudaGetSymbolAddress((void**)&p1  , g_p1);
    cudaGetSymbolAddress((void**)&p2  , g_p2);
    cudaGetSymbolAddress((void**)&xp  , g_xp);
    cudaGetSymbolAddress((void**)&cp  , g_cp);
    cudaGetSymbolAddress((void**)&xh  , g_xh);
    cudaGetSymbolAddress((void**)&xl  , g_xl);
    cudaGetSymbolAddress((void**)&wh  , g_wh);
    cudaGetSymbolAddress((void**)&wl  , g_wl);
    cudaGetSymbolAddress((void**)&phih, g_phih);
    cudaGetSymbolAddress((void**)&phil, g_phil);
    cudaGetSymbolAddress((void**)&Mh  , g_Mh);
    cudaGetSymbolAddress((void**)&Ml  , g_Ml);
    cudaGetSymbolAddress((void**)&Hh  , g_Hh);
    cudaGetSymbolAddress((void**)&Hl  , g_Hl);
    cudaGetSymbolAddress((void**)&yh  , g_yh);
    cudaGetSymbolAddress((void**)&yl  , g_yl);
    cudaGetSymbolAddress((void**)&th  , g_th);
    cudaGetSymbolAddress((void**)&tl  , g_tl);
    cudaGetSymbolAddress((void**)&tmph, g_tmph);
    cudaGetSymbolAddress((void**)&tmpl, g_tmpl);
    cudaGetSymbolAddress((void**)&wphih, g_wphih);
    cudaGetSymbolAddress((void**)&wphil, g_wphil);
    cudaGetSymbolAddress((void**)&w2h , g_w2h);
    cudaGetSymbolAddress((void**)&w2l , g_w2l);

    cudaFuncSetAttribute(conv_mma, cudaFuncAttributeMaxDynamicSharedMemorySize, CONV_SMEM);
    cudaFuncSetAttribute(hgemm_nn, cudaFuncAttributeMaxDynamicSharedMemorySize, CONV_SMEM);
    cudaFuncSetAttribute(hgemm_tn, cudaFuncAttributeMaxDynamicSharedMemorySize, TN_SMEM);

    // splits of inputs
    cvt_split<<<(Bn*Vn*CIN + 255)/256, 256>>>(x, xh, xl, (long)Bn*Vn*CIN);
    cvt_split<<<(49*CIN*En + 255)/256, 256>>>(wm, wh, wl, (long)49*CIN*En);
    cvt_split<<<(CIN*Fn + 255)/256, 256>>>(wphi, wphih, wphil, (long)CIN*Fn);
    cvt_split<<<(CIN*En + 255)/256, 256>>>(w2, w2h, w2l, (long)CIN*En);

    // mean(x) -> a
    xmean_part<<<dim3(Bn,NCH),256>>>(x, xp);
    a_kernel<<<Bn,256>>>(xp, wa, ba, aV);

    // phi = x @ w_phi + b_phi -> split (M=32768, N=128, K=256)
    hgemm_nn<<<dim3(1,256,1),256,CONV_SMEM>>>(xh, xl, wphih, wphil,
        (float*)0, phih, phil, bphi, Fn, CIN, 0,0,(long)0,0, 0);

    // M = conv7x7(x) + b_m -> split
    conv_mma<<<dim3(2,32,Bn), 256, CONV_SMEM>>>(xh, xl, wh, wl, bm, Mh, Ml);

    // t = a * (phi^T @ M)
    hgemm_tn<<<dim3(2,1,Bn*NCH),256,TN_SMEM>>>(phih, phil, Mh, Ml, p1,
        Fn, En, Fn, En, Vn/NCH, (long)Vn*Fn, (long)Vn*En);
    reduce_scale<<<(Bn*Fn*En)/256,256>>>(tb, p1, aV, Fn, En);
    cvt_split<<<(Bn*Fn*En + 255)/256, 256>>>(tb, th, tl, (long)Bn*Fn*En);

    // H = |phi @ t|  (fp32 out)
    hgemm_nn<<<dim3(2,32,Bn),256,CONV_SMEM>>>(phih, phil, th, tl,
        Hb, (bf16*)0, (bf16*)0, (const float*)0, En, Fn,
        (long)Vn*Fn, (long)Fn*En, (long)Vn*En, 0, 1);

    // Binv from column sums of H
    colsum_part<<<dim3(Bn,NCH),256>>>(Hb, cp);
    binv_kernel<<<Bn,256>>>(cp, binv);

    // D_H = D^{-1/2} H -> split
    rowscale_split<<<Bn*Vn,256>>>(Hb, Hh, Hl);

    // tmp = Binv * (D_H^T @ x)
    hgemm_tn<<<dim3(2,2,Bn*NCH),256,TN_SMEM>>>(Hh, Hl, xh, xl, p2,
        En, CIN, En, CIN, Vn/NCH, (long)Vn*En, (long)Vn*CIN);
    reduce_scale<<<(Bn*En*CIN)/256,256>>>(tmp, p2, binv, En, CIN);
    cvt_split<<<(Bn*En*CIN + 255)/256, 256>>>(tmp, tmph, tmpl, (long)Bn*En*CIN);

    // y = x - D_H @ tmp -> split
    hgemm_nn<<<dim3(2,32,Bn),256,CONV_SMEM>>>(Hh, Hl, tmph, tmpl,
        (float*)0, yh, yl, x, CIN, En,
        (long)Vn*En, (long)En*CIN, (long)Vn*CIN, (long)Vn*CIN, 2);

    // out = y @ w2 + b2  (M=32768, N=256, K=256)
    hgemm_nn<<<dim3(2,256,1),256,CONV_SMEM>>>(yh, yl, w2h, w2l,
        out, (bf16*)0, (bf16*)0, b2, En, CIN, 0,0,(long)0,0, 0);
}

// round 7
// speedup vs baseline: 2.4117x; 1.1248x over previous
#include <cuda_runtime.h>
#include <cuda_bf16.h>
#include <cstdint>

typedef unsigned long long u64;
typedef __nv_bfloat16 bf16;

#define Bn   8
#define Vn   4096
#define CIN  256
#define Fn   128
#define En   256
#define NCH  16

// ---------------- scratch (device globals) -----------------------------------
__device__ float g_a   [Bn*Fn];
__device__ float g_H   [Bn*Vn*En];
__device__ float g_Binv[Bn*En];
__device__ float g_p1  [Bn*NCH*Fn*En];
__device__ float g_p2  [Bn*NCH*En*CIN];
__device__ float g_xp  [Bn*NCH*CIN];
__device__ float g_cp  [Bn*NCH*En];
// bf16 split operand pairs
__device__ bf16 g_xh [Bn*Vn*CIN];
__device__ bf16 g_xl [Bn*Vn*CIN];
__device__ bf16 g_wh [49*CIN*En];
__device__ bf16 g_wl [49*CIN*En];
__device__ bf16 g_phih[Bn*Vn*Fn];
__device__ bf16 g_phil[Bn*Vn*Fn];
__device__ bf16 g_Mh [Bn*Vn*En];
__device__ bf16 g_Ml [Bn*Vn*En];
__device__ bf16 g_Hh [Bn*Vn*En];
__device__ bf16 g_Hl [Bn*Vn*En];
__device__ bf16 g_yh [Bn*Vn*CIN];
__device__ bf16 g_yl [Bn*Vn*CIN];
__device__ bf16 g_th [Bn*Fn*En];
__device__ bf16 g_tl [Bn*Fn*En];
__device__ bf16 g_tmph[Bn*En*CIN];
__device__ bf16 g_tmpl[Bn*En*CIN];
__device__ bf16 g_wphih[CIN*Fn];
__device__ bf16 g_wphil[CIN*Fn];
__device__ bf16 g_w2h[CIN*En];
__device__ bf16 g_w2l[CIN*En];

// =================== helpers =================================================
__global__ void cvt_split(const float* __restrict__ src, bf16* __restrict__ hi,
                          bf16* __restrict__ lo, long n){
    long i = (long)blockIdx.x*256 + threadIdx.x;
    if (i >= n) return;
    float v = src[i];
    bf16 h = __float2bfloat16_rn(v);
    hi[i] = h;
    lo[i] = __float2bfloat16_rn(v - __bfloat162float(h));
}

__device__ __forceinline__ uint32_t smem_u32(const void* p) {
    uint32_t a;
    asm("{ .reg .u64 t; cvta.to.shared.u64 t, %1; cvt.u32.u64 %0, t; }" : "=r"(a) : "l"(p));
    return a;
}
__device__ __forceinline__ void cp16(uint32_t d, const void* s, int sz){
    asm volatile("cp.async.cg.shared.global [%0], [%1], 16, %2;"
                 :: "r"(d), "l"(s), "r"(sz) : "memory");
}
__device__ __forceinline__ void ldsm4(uint32_t* r, uint32_t a){
    asm volatile("ldmatrix.sync.aligned.m8n8.x4.shared.b16 {%0,%1,%2,%3}, [%4];"
                 : "=r"(r[0]),"=r"(r[1]),"=r"(r[2]),"=r"(r[3]) : "r"(a));
}
__device__ __forceinline__ void ldsm4t(uint32_t* r, uint32_t a){
    asm volatile("ldmatrix.sync.aligned.m8n8.x4.trans.shared.b16 {%0,%1,%2,%3}, [%4];"
                 : "=r"(r[0]),"=r"(r[1]),"=r"(r[2]),"=r"(r[3]) : "r"(a));
}
__device__ __forceinline__ void mma16816(float* c, const uint32_t* a, uint32_t b0, uint32_t b1){
    asm volatile("mma.sync.aligned.m16n8k16.row.col.f32.bf16.bf16.f32 "
                 "{%0,%1,%2,%3}, {%4,%5,%6,%7}, {%8,%9}, {%0,%1,%2,%3};"
                 : "+f"(c[0]),"+f"(c[1]),"+f"(c[2]),"+f"(c[3])
                 : "r"(a[0]),"r"(a[1]),"r"(a[2]),"r"(a[3]), "r"(b0),"r"(b1));
}
__device__ __forceinline__ void st_split2(bf16* H, bf16* L, float v0, float v1){
    bf16 h0 = __float2bfloat16_rn(v0);
    bf16 h1 = __float2bfloat16_rn(v1);
    bf16 l0 = __float2bfloat16_rn(v0 - __bfloat162float(h0));
    bf16 l1 = __float2bfloat16_rn(v1 - __bfloat162float(h1));
    __nv_bfloat162 hp; hp.x = h0; hp.y = h1;
    __nv_bfloat162 lp; lp.x = l0; lp.y = l1;
    *(__nv_bfloat162*)H = hp;
    *(__nv_bfloat162*)L = lp;
}

// shared tile constants
#define A_LD   40
#define B_LD   136
#define OFF_AH 0
#define OFF_AL 5120
#define OFF_BH 10240
#define OFF_BL 14592
#define STAGE_E 18944
#define CONV_SMEM (2*STAGE_E*2)
#define NCHUNK 392

// inner 3-pass MMA block (shared by conv + NN + TN)
#define COMPUTE_TILE(sa_ah, sa_al, sa_bh, sa_bl, LOAD_A)                        \
    _Pragma("unroll")                                                           \
    for (int kk = 0; kk < 2; kk++){                                             \
        uint32_t ah[2][4], al[2][4];                                            \
        LOAD_A;                                                                 \
        _Pragma("unroll")                                                       \
        for (int nf = 0; nf < 4; nf++){                                         \
            uint32_t bh[4], bl[4];                                              \
            uint32_t bd = (sa_bh) + (uint32_t)((kk*16 + (lane & 15))*B_LD       \
                                          + nbase + nf*16 + (lane >> 4)*8)*2;   \
            ldsm4t(bh, bd);                                                     \
            ldsm4t(bl, bd + ((sa_bl)-(sa_bh)));                                 \
            _Pragma("unroll")                                                   \
            for (int mt = 0; mt < 2; mt++){                                     \
                float* c0 = acc[mt][nf*2];                                      \
                float* c1 = acc[mt][nf*2+1];                                    \
                mma16816(c0, ah[mt], bh[0], bh[1]);                             \
                mma16816(c1, ah[mt], bh[2], bh[3]);                             \
                mma16816(c0, ah[mt], bl[0], bl[1]);                             \
                mma16816(c1, ah[mt], bl[2], bl[3]);                             \
                mma16816(c0, al[mt], bh[0], bh[1]);                             \
                mma16816(c1, al[mt], bh[2], bh[3]);                             \
            }                                                                   \
        }                                                                       \
    }

// =================== conv ====================================================
__device__ __forceinline__ void conv_load_chunk(
    uint32_t smb, int stage,
    const bf16* __restrict__ xh, const bf16* __restrict__ xl,
    const bf16* __restrict__ wh, const bf16* __restrict__ wl,
    long bV, int p0, int n0, int ic, int tid)
{
    int tap = ic >> 3, c0 = (ic & 7) * 32;
    int ky = tap / 7, kx = tap - ky*7;
    uint32_t base = smb + stage*STAGE_E*2;

    int row  = tid >> 1;
    int koff = (tid & 1) * 16;
    int pos = p0 + row;
    int hs = (pos >> 6) + ky - 3, ws = (pos & 63) + kx - 3;
    int sz = (((unsigned)hs < 64u) && ((unsigned)ws < 64u)) ? 16 : 0;
    long sidx = sz ? (bV + ((hs << 6) + ws)) * CIN + c0 + koff : 0;
    uint32_t da = base + (uint32_t)(OFF_AH + row*A_LD + koff)*2;
    cp16(da,      xh + sidx,     sz);
    cp16(da + 16, xh + sidx + 8, sz);
    uint32_t dal = base + (uint32_t)(OFF_AL + row*A_LD + koff)*2;
    cp16(dal,      xl + sidx,     sz);
    cp16(dal + 16, xl + sidx + 8, sz);

    #pragma unroll
    for (int q = 0; q < 2; q++){
        int qq = tid*2 + q;
        int brow = qq >> 4;
        int bcol = (qq & 15) * 8;
        long widx = ((long)(tap*CIN + c0 + brow))*En + n0 + bcol;
        uint32_t db = base + (uint32_t)(OFF_BH + brow*B_LD + bcol)*2;
        cp16(db, wh + widx, 16);
        uint32_t dbl = base + (uint32_t)(OFF_BL + brow*B_LD + bcol)*2;
        cp16(dbl, wl + widx, 16);
    }
    asm volatile("cp.async.commit_group;" ::: "memory");
}

__global__ void __launch_bounds__(256, 2)
conv_mma(const bf16* __restrict__ xh, const bf16* __restrict__ xl,
         const bf16* __restrict__ wh, const bf16* __restrict__ wl,
         const float* __restrict__ bm, bf16* __restrict__ Mh, bf16* __restrict__ Ml)
{
    extern __shared__ char smem[];
    uint32_t smb = smem_u32(smem);
    int tid = threadIdx.x;
    int wid = tid >> 5, lane = tid & 31;
    int n0 = blockIdx.x * 128;
    int p0 = blockIdx.y * 128;
    int b  = blockIdx.z;
    long bV = (long)b * Vn;

    int mbase = (wid & 3) * 32;
    int nbase = (wid >> 2) * 64;

    float acc[2][8][4];
    #pragma unroll
    for (int i=0;i<2;i++)
    #pragma unroll
        for (int j=0;j<8;j++)
        #pragma unroll
            for (int k=0;k<4;k++) acc[i][j][k]=0.f;

    conv_load_chunk(smb, 0, xh, xl, wh, wl, bV, p0, n0, 0, tid);
    conv_load_chunk(smb, 1, xh, xl, wh, wl, bV, p0, n0, 1, tid);

    for (int ic = 0; ic < NCHUNK; ic++){
        if (ic < NCHUNK-2) asm volatile("cp.async.wait_group 1;" ::: "memory");
        else               asm volatile("cp.async.wait_group 0;" ::: "memory");
        __syncthreads();

        uint32_t sa = smb + (uint32_t)(ic & 1)*STAGE_E*2;
        COMPUTE_TILE(sa + OFF_AH*2, sa + OFF_AL*2, sa + OFF_BH*2, sa + OFF_BL*2,
            {
                _Pragma("unroll")
                for (int mt = 0; mt < 2; mt++){
                    uint32_t ad = sa + (uint32_t)((mbase + mt*16 + (lane & 15))*A_LD
                                                  + kk*16 + (lane >> 4)*8)*2;
                    ldsm4(ah[mt], ad);
                    ldsm4(al[mt], ad + OFF_AL*2);
                }
            });
        __syncthreads();
        if (ic + 2 < NCHUNK)
            conv_load_chunk(smb, ic & 1, xh, xl, wh, wl, bV, p0, n0, ic + 2, tid);
    }

    #pragma unroll
    for (int mt = 0; mt < 2; mt++){
        long r0 = bV + p0 + mbase + mt*16 + (lane >> 2);
        #pragma unroll
        for (int n8 = 0; n8 < 8; n8++){
            int col = n0 + nbase + n8*8 + (lane & 3)*2;
            float b0 = bm[col], b1 = bm[col+1];
            float* c = acc[mt][n8];
            st_split2(Mh + r0*En + col,     Ml + r0*En + col,     c[0]+b0, c[1]+b1);
            st_split2(Mh + (r0+8)*En + col, Ml + (r0+8)*En + col, c[2]+b0, c[3]+b1);
        }
    }
}

// =================== generic NN HMMA GEMM ====================================
__device__ __forceinline__ void nn_load_chunk(
    uint32_t smb, int stage,
    const bf16* __restrict__ Ah, const bf16* __restrict__ Al,
    const bf16* __restrict__ Bh, const bf16* __restrict__ Bl,
    int m0, int n0, int k0, int K, int N, int tid)
{
    uint32_t base = smb + stage*STAGE_E*2;
    int row  = tid >> 1;
    int koff = (tid & 1) * 16;
    long sidx = (long)(m0+row)*K + k0 + koff;
    uint32_t da = base + (uint32_t)(OFF_AH + row*A_LD + koff)*2;
    cp16(da,      Ah + sidx,     16);
    cp16(da + 16, Ah + sidx + 8, 16);
    uint32_t dal = base + (uint32_t)(OFF_AL + row*A_LD + koff)*2;
    cp16(dal,      Al + sidx,     16);
    cp16(dal + 16, Al + sidx + 8, 16);
    #pragma unroll
    for (int q = 0; q < 2; q++){
        int qq = tid*2 + q;
        int brow = qq >> 4;
        int bcol = (qq & 15) * 8;
        long widx = (long)(k0+brow)*N + n0 + bcol;
        uint32_t db = base + (uint32_t)(OFF_BH + brow*B_LD + bcol)*2;
        cp16(db, Bh + widx, 16);
        uint32_t dbl = base + (uint32_t)(OFF_BL + brow*B_LD + bcol)*2;
        cp16(dbl, Bl + widx, 16);
    }
    asm volatile("cp.async.commit_group;" ::: "memory");
}

__global__ void __launch_bounds__(256, 2)
hgemm_nn(const bf16* __restrict__ Ah, const bf16* __restrict__ Al,
         const bf16* __restrict__ Bh, const bf16* __restrict__ Bl,
         float* __restrict__ Cf, bf16* __restrict__ Ch, bf16* __restrict__ Cl,
         const float* __restrict__ aux,
         int N, int K, long sA, long sB, long sC, long sAux, int epi)
{
    extern __shared__ char smem[];
    uint32_t smb = smem_u32(smem);
    int tid = threadIdx.x;
    int wid = tid >> 5, lane = tid & 31;
    int n0 = blockIdx.x * 128;
    int m0 = blockIdx.y * 128;
    int b  = blockIdx.z;
    Ah += (long)b*sA; Al += (long)b*sA;
    Bh += (long)b*sB; Bl += (long)b*sB;
    const float* auxp = aux ? aux + (long)b*sAux : (const float*)0;

    int mbase = (wid & 3) * 32;
    int nbase = (wid >> 2) * 64;

    float acc[2][8][4];
    #pragma unroll
    for (int i=0;i<2;i++)
    #pragma unroll
        for (int j=0;j<8;j++)
        #pragma unroll
            for (int k=0;k<4;k++) acc[i][j][k]=0.f;

    int nchunk = K >> 5;
    nn_load_chunk(smb, 0, Ah, Al, Bh, Bl, m0, n0, 0,  K, N, tid);
    nn_load_chunk(smb, 1, Ah, Al, Bh, Bl, m0, n0, 32, K, N, tid);

    for (int ic = 0; ic < nchunk; ic++){
        if (ic < nchunk-2) asm volatile("cp.async.wait_group 1;" ::: "memory");
        else               asm volatile("cp.async.wait_group 0;" ::: "memory");
        __syncthreads();
        uint32_t sa = smb + (uint32_t)(ic & 1)*STAGE_E*2;
        COMPUTE_TILE(sa + OFF_AH*2, sa + OFF_AL*2, sa + OFF_BH*2, sa + OFF_BL*2,
            {
                _Pragma("unroll")
                for (int mt = 0; mt < 2; mt++){
                    uint32_t ad = sa + (uint32_t)((mbase + mt*16 + (lane & 15))*A_LD
                                                  + kk*16 + (lane >> 4)*8)*2;
                    ldsm4(ah[mt], ad);
                    ldsm4(al[mt], ad + OFF_AL*2);
                }
            });
        __syncthreads();
        if (ic + 2 < nchunk)
            nn_load_chunk(smb, ic & 1, Ah, Al, Bh, Bl, m0, n0, (ic+2)*32, K, N, tid);
    }

    #pragma unroll
    for (int mt = 0; mt < 2; mt++){
        long r0 = m0 + mbase + mt*16 + (lane >> 2);
        #pragma unroll
        for (int n8 = 0; n8 < 8; n8++){
            int col = n0 + nbase + n8*8 + (lane & 3)*2;
            float* c = acc[mt][n8];
            float v00=c[0], v01=c[1], v10=c[2], v11=c[3];
            if (epi == 0){
                float b0 = auxp[col], b1 = auxp[col+1];
                v00+=b0; v01+=b1; v10+=b0; v11+=b1;
            } else if (epi == 1){
                v00=fabsf(v00); v01=fabsf(v01); v10=fabsf(v10); v11=fabsf(v11);
            } else {
                v00 = auxp[r0*N + col]     - v00;
                v01 = auxp[r0*N + col + 1] - v01;
                v10 = auxp[(r0+8)*N + col]     - v10;
                v11 = auxp[(r0+8)*N + col + 1] - v11;
            }
            if (Cf){
                float* base = Cf + (long)b*sC;
                *(float2*)(base + r0*N + col)     = make_float2(v00, v01);
                *(float2*)(base + (r0+8)*N + col) = make_float2(v10, v11);
            }
            if (Ch){
                bf16* bh = Ch + (long)b*sC;
                bf16* bl = Cl + (long)b*sC;
                st_split2(bh + r0*N + col,     bl + r0*N + col,     v00, v01);
                st_split2(bh + (r0+8)*N + col, bl + (r0+8)*N + col, v10, v11);
            }
        }
    }
}

// =================== TN HMMA split-K partials ================================
#define TN_AH 0
#define TN_AL 4352
#define TN_BH 8704
#define TN_BL 13056
#define TN_STAGE 17408
#define TN_SMEM (2*TN_STAGE*2)

__device__ __forceinline__ void tn_load_chunk(
    uint32_t smb, int stage,
    const bf16* __restrict__ Ah, const bf16* __restrict__ Al,
    const bf16* __restrict__ Bh, const bf16* __restrict__ Bl,
    long offA, long offB, int m0, int n0, int k0, int lda, int ldb, int tid)
{
    uint32_t base = smb + stage*TN_STAGE*2;
    #pragma unroll
    for (int q = 0; q < 2; q++){
        int qq = tid*2 + q;
        int brow = qq >> 4;
        int bcol = (qq & 15) * 8;
        long aidx = offA + (long)(k0+brow)*lda + m0 + bcol;
        uint32_t da = base + (uint32_t)(TN_AH + brow*B_LD + bcol)*2;
        cp16(da, Ah + aidx, 16);
        cp16(base + (uint32_t)(TN_AL + brow*B_LD + bcol)*2, Al + aidx, 16);
        long bidx = offB + (long)(k0+brow)*ldb + n0 + bcol;
        cp16(base + (uint32_t)(TN_BH + brow*B_LD + bcol)*2, Bh + bidx, 16);
        cp16(base + (uint32_t)(TN_BL + brow*B_LD + bcol)*2, Bl + bidx, 16);
    }
    asm volatile("cp.async.commit_group;" ::: "memory");
}

__global__ void __launch_bounds__(256, 2)
hgemm_tn(const bf16* __restrict__ Ah, const bf16* __restrict__ Al,
         const bf16* __restrict__ Bh, const bf16* __restrict__ Bl,
         float* __restrict__ P, int Mo, int No, int lda, int ldb, int Kc,
         long sA, long sB)
{
    extern __shared__ char smem[];
    uint32_t smb = smem_u32(smem);
    int tid = threadIdx.x;
    int wid = tid >> 5, lane = tid & 31;
    int b = blockIdx.z / NCH, s = blockIdx.z % NCH;
    long offA = (long)b*sA + (long)s*Kc*lda;
    long offB = (long)b*sB + (long)s*Kc*ldb;
    P += (long)(b*NCH + s)*Mo*No;
    int n0 = blockIdx.x * 128;
    int m0 = blockIdx.y * 128;

    int mbase = (wid & 3) * 32;
    int nbase = (wid >> 2) * 64;

    float acc[2][8][4];
    #pragma unroll
    for (int i=0;i<2;i++)
    #pragma unroll
        for (int j=0;j<8;j++)
        #pragma unroll
            for (int k=0;k<4;k++) acc[i][j][k]=0.f;

    int nchunk = Kc >> 5;
    tn_load_chunk(smb, 0, Ah, Al, Bh, Bl, offA, offB, m0, n0, 0,  lda, ldb, tid);
    tn_load_chunk(smb, 1, Ah, Al, Bh, Bl, offA, offB, m0, n0, 32, lda, ldb, tid);

    // A^T fragment lane map (ldmatrix.trans on [k][m] tile):
    int krow = (lane & 7) + (lane >> 4)*8;
    int msub = ((lane >> 3) & 1)*8;

    for (int ic = 0; ic < nchunk; ic++){
        if (ic < nchunk-2) asm volatile("cp.async.wait_group 1;" ::: "memory");
        else               asm volatile("cp.async.wait_group 0;" ::: "memory");
        __syncthreads();
        uint32_t sa = smb + (uint32_t)(ic & 1)*TN_STAGE*2;
        COMPUTE_TILE(sa + TN_AH*2, sa + TN_AL*2, sa + TN_BH*2, sa + TN_BL*2,
            {
                _Pragma("unroll")
                for (int mt = 0; mt < 2; mt++){
                    uint32_t ad = sa + (uint32_t)(TN_AH + (kk*16 + krow)*B_LD
                                                  + mbase + mt*16 + msub)*2;
                    ldsm4t(ah[mt], ad);
                    ldsm4t(al[mt], ad + (TN_AL - TN_AH)*2);
                }
            });
        __syncthreads();
        if (ic + 2 < nchunk)
            tn_load_chunk(smb, ic & 1, Ah, Al, Bh, Bl, offA, offB, m0, n0, (ic+2)*32, lda, ldb, tid);
    }

    #pragma unroll
    for (int mt = 0; mt < 2; mt++){
        long r0 = m0 + mbase + mt*16 + (lane >> 2);
        #pragma unroll
        for (int n8 = 0; n8 < 8; n8++){
            int col = n0 + nbase + n8*8 + (lane & 3)*2;
            float* c = acc[mt][n8];
            *(float2*)(P + r0*No + col)     = make_float2(c[0], c[1]);
            *(float2*)(P + (r0+8)*No + col) = make_float2(c[2], c[3]);
        }
    }
}

// ---------------- small kernels ---------------------------------------------
__global__ void xmean_part(const float* __restrict__ x, float* __restrict__ xp){
    int b=blockIdx.x, s=blockIdx.y, tid=threadIdx.x;
    const float* p = x + ((long)b*Vn + s*(Vn/NCH))*CIN + tid;
    float acc=0.f;
    for (int i=0;i<Vn/NCH;i++) acc += p[(long)i*CIN];
    xp[(b*NCH+s)*CIN+tid]=acc;
}

__global__ void a_kernel(const float* __restrict__ xp, const float* __restrict__ w_a,
                         const float* __restrict__ b_a, float* __restrict__ a){
    __shared__ float xm[CIN];
    __shared__ float part[256];
    int b=blockIdx.x, tid=threadIdx.x;
    float acc=0.f;
    #pragma unroll
    for (int ch=0;ch<NCH;ch++) acc += xp[(b*NCH+ch)*CIN+tid];
    xm[tid] = acc * (1.0f/(float)Vn);
    __syncthreads();
    int f = tid & 127, half = tid >> 7;
    float s = 0.f;
    #pragma unroll 4
    for (int c = half*128; c < half*128 + 128; c++) s += xm[c]*w_a[c*Fn+f];
    part[tid] = s;
    __syncthreads();
    if (tid < Fn) a[b*Fn+tid] = part[tid] + part[tid+128] + b_a[tid];
}

__global__ void colsum_part(const float* __restrict__ Hm, float* __restrict__ cp){
    int b=blockIdx.x, s=blockIdx.y, tid=threadIdx.x;
    const float* p = Hm + ((long)b*Vn + s*(Vn/NCH))*En + tid;
    float acc=0.f;
    for (int i=0;i<Vn/NCH;i++) acc += p[(long)i*En];
    cp[(b*NCH+s)*En+tid]=acc;
}

__global__ void binv_kernel(const float* __restrict__ cp, float* __restrict__ binv){
    int b=blockIdx.x, tid=threadIdx.x;
    float s=0.f;
    #pragma unroll
    for (int ch=0;ch<NCH;ch++) s += cp[(b*NCH+ch)*En+tid];
    binv[b*En+tid] = 1.0f/s;
}

// row-normalize H (fp32 in) -> split bf16 out
__global__ void rowscale_split(const float* __restrict__ H,
                               bf16* __restrict__ Hh, bf16* __restrict__ Hl){
    __shared__ float red[256];
    long row = blockIdx.x;
    int tid = threadIdx.x;
    const float* hr = H + row*En;
    float v = hr[tid];
    red[tid]=v; __syncthreads();
    for (int s=128;s>0;s>>=1){ if(tid<s) red[tid]+=red[tid+s]; __syncthreads(); }
    float o = v * rsqrtf(red[0]);
    bf16 h = __float2bfloat16_rn(o);
    Hh[row*En + tid] = h;
    Hl[row*En + tid] = __float2bfloat16_rn(o - __bfloat162float(h));
}

// fused: out(split) = scale[b,r] * sum_s part[b,s,r,c]
__global__ void reduce_scale_split(bf16* __restrict__ outh, bf16* __restrict__ outl,
                                   const float* __restrict__ part,
                                   const float* __restrict__ scale, int R, int C){
    long idx = (long)blockIdx.x*256 + threadIdx.x;
    int c = (int)(idx % C); long rc = idx / C; int r = (int)(rc % R); int b = (int)(rc / R);
    float s=0.f;
#pragma unroll
    for (int ch=0;ch<NCH;ch++) s += part[((long)(b*NCH+ch)*R + r)*C + c];
    float v = s * scale[b*R + r];
    bf16 h = __float2bfloat16_rn(v);
    outh[idx] = h;
    outl[idx] = __float2bfloat16_rn(v - __bfloat162float(h));
}

// ---------------- host launch ------------------------------------------------
extern "C" void kernel_launch(void* const* d_in, const int* in_sizes, int n_in,
                              void* d_out, int out_size){
    (void)in_sizes; (void)n_in; (void)out_size;
    const float* x    =(const float*)d_in[0];
    const float* wphi =(const float*)d_in[1];
    const float* bphi =(const float*)d_in[2];
    const float* wa   =(const float*)d_in[3];
    const float* ba   =(const float*)d_in[4];
    const float* wm   =(const float*)d_in[5];
    const float* bm   =(const float*)d_in[6];
    const float* w2   =(const float*)d_in[7];
    const float* b2   =(const float*)d_in[8];
    float* out=(float*)d_out;

    float *aV,*Hb,*binv,*p1,*p2,*xp,*cp;
    bf16 *xh,*xl,*wh,*wl,*phih,*phil,*Mh,*Ml,*Hh,*Hl,*yh,*yl,*th,*tl,*tmph,*tmpl;
    bf16 *wphih,*wphil,*w2h,*w2l;
    cudaGetSymbolAddress((void**)&aV  , g_a);
    cudaGetSymbolAddress((void**)&Hb  , g_H);
    cudaGetSymbolAddress((void**)&binv, g_Binv);
    cudaGetSymbolAddress((void**)&p1  , g_p1);
    cudaGetSymbolAddress((void**)&p2  , g_p2);
    cudaGetSymbolAddress((void**)&xp  , g_xp);
    cudaGetSymbolAddress((void**)&cp  , g_cp);
    cudaGetSymbolAddress((void**)&xh  , g_xh);
    cudaGetSymbolAddress((void**)&xl  , g_xl);
    cudaGetSymbolAddress((void**)&wh  , g_wh);
    cudaGetSymbolAddress((void**)&wl  , g_wl);
    cudaGetSymbolAddress((void**)&phih, g_phih);
    cudaGetSymbolAddress((void**)&phil, g_phil);
    cudaGetSymbolAddress((void**)&Mh  , g_Mh);
    cudaGetSymbolAddress((void**)&Ml  , g_Ml);
    cudaGetSymbolAddress((void**)&Hh  , g_Hh);
    cudaGetSymbolAddress((void**)&Hl  , g_Hl);
    cudaGetSymbolAddress((void**)&yh  , g_yh);
    cudaGetSymbolAddress((void**)&yl  , g_yl);
    cudaGetSymbolAddress((void**)&th  , g_th);
    cudaGetSymbolAddress((void**)&tl  , g_tl);
    cudaGetSymbolAddress((void**)&tmph, g_tmph);
    cudaGetSymbolAddress((void**)&tmpl, g_tmpl);
    cudaGetSymbolAddress((void**)&wphih, g_wphih);
    cudaGetSymbolAddress((void**)&wphil, g_wphil);
    cudaGetSymbolAddress((void**)&w2h , g_w2h);
    cudaGetSymbolAddress((void**)&w2l , g_w2l);

    cudaFuncSetAttribute(conv_mma, cudaFuncAttributeMaxDynamicSharedMemorySize, CONV_SMEM);
    cudaFuncSetAttribute(hgemm_nn, cudaFuncAttributeMaxDynamicSharedMemorySize, CONV_SMEM);
    cudaFuncSetAttribute(hgemm_tn, cudaFuncAttributeMaxDynamicSharedMemorySize, TN_SMEM);

    // splits of inputs
    cvt_split<<<(Bn*Vn*CIN + 255)/256, 256>>>(x, xh, xl, (long)Bn*Vn*CIN);
    cvt_split<<<(49*CIN*En + 255)/256, 256>>>(wm, wh, wl, (long)49*CIN*En);
    cvt_split<<<(CIN*Fn + 255)/256, 256>>>(wphi, wphih, wphil, (long)CIN*Fn);
    cvt_split<<<(CIN*En + 255)/256, 256>>>(w2, w2h, w2l, (long)CIN*En);

    // mean(x) -> a
    xmean_part<<<dim3(Bn,NCH),256>>>(x, xp);
    a_kernel<<<Bn,256>>>(xp, wa, ba, aV);

    // phi = x @ w_phi + b_phi -> split (M=32768, N=128, K=256)
    hgemm_nn<<<dim3(1,256,1),256,CONV_SMEM>>>(xh, xl, wphih, wphil,
        (float*)0, phih, phil, bphi, Fn, CIN, 0,0,(long)0,0, 0);

    // M = conv7x7(x) + b_m -> split
    conv_mma<<<dim3(2,32,Bn), 256, CONV_SMEM>>>(xh, xl, wh, wl, bm, Mh, Ml);

    // t = a * (phi^T @ M) -> split
    hgemm_tn<<<dim3(2,1,Bn*NCH),256,TN_SMEM>>>(phih, phil, Mh, Ml, p1,
        Fn, En, Fn, En, Vn/NCH, (long)Vn*Fn, (long)Vn*En);
    reduce_scale_split<<<(Bn*Fn*En)/256,256>>>(th, tl, p1, aV, Fn, En);

    // H = |phi @ t|  (fp32 out)
    hgemm_nn<<<dim3(2,32,Bn),256,CONV_SMEM>>>(phih, phil, th, tl,
        Hb, (bf16*)0, (bf16*)0, (const float*)0, En, Fn,
        (long)Vn*Fn, (long)Fn*En, (long)Vn*En, 0, 1);

    // Binv from column sums of H
    colsum_part<<<dim3(Bn,NCH),256>>>(Hb, cp);
    binv_kernel<<<Bn,256>>>(cp, binv);

    // D_H = D^{-1/2} H -> split
    rowscale_split<<<Bn*Vn,256>>>(Hb, Hh, Hl);

    // tmp = Binv * (D_H^T @ x) -> split
    hgemm_tn<<<dim3(2,2,Bn*NCH),256,TN_SMEM>>>(Hh, Hl, xh, xl, p2,
        En, CIN, En, CIN, Vn/NCH, (long)Vn*En, (long)Vn*CIN);
    reduce_scale_split<<<(Bn*En*CIN)/256,256>>>(tmph, tmpl, p2, binv, En, CIN);

    // y = x - D_H @ tmp -> split
    hgemm_nn<<<dim3(2,32,Bn),256,CONV_SMEM>>>(Hh, Hl, tmph, tmpl,
        (float*)0, yh, yl, x, CIN, En,
        (long)Vn*En, (long)En*CIN, (long)Vn*CIN, (long)Vn*CIN, 2);

    // out = y @ w2 + b2  (M=32768, N=256, K=256)
    hgemm_nn<<<dim3(2,256,1),256,CONV_SMEM>>>(yh, yl, w2h, w2l,
        out, (bf16*)0, (bf16*)0, b2, En, CIN, 0,0,(long)0,0, 0);
}

// round 8
// speedup vs baseline: 2.4849x; 1.0303x over previous
#include <cuda_runtime.h>
#include <cuda_bf16.h>
#include <cstdint>

typedef unsigned long long u64;
typedef __nv_bfloat16 bf16;

#define Bn   8
#define Vn   4096
#define CIN  256
#define Fn   128
#define En   256
#define NCH  16

// ---------------- scratch (device globals) -----------------------------------
__device__ float g_a   [Bn*Fn];
__device__ float g_H   [Bn*Vn*En];
__device__ float g_Binv[Bn*En];
__device__ float g_p1  [Bn*NCH*Fn*En];
__device__ float g_p2  [Bn*NCH*En*CIN];
__device__ float g_xp  [Bn*NCH*CIN];
__device__ float g_cp  [Bn*NCH*En];
// bf16 split operand pairs
__device__ bf16 g_xh [Bn*Vn*CIN];
__device__ bf16 g_xl [Bn*Vn*CIN];
__device__ bf16 g_wh [49*CIN*En];
__device__ bf16 g_wl [49*CIN*En];
__device__ bf16 g_phih[Bn*Vn*Fn];
__device__ bf16 g_phil[Bn*Vn*Fn];
__device__ bf16 g_Mh [Bn*Vn*En];
__device__ bf16 g_Ml [Bn*Vn*En];
__device__ bf16 g_Hh [Bn*Vn*En];
__device__ bf16 g_Hl [Bn*Vn*En];
__device__ bf16 g_yh [Bn*Vn*CIN];
__device__ bf16 g_yl [Bn*Vn*CIN];
__device__ bf16 g_th [Bn*Fn*En];
__device__ bf16 g_tl [Bn*Fn*En];
__device__ bf16 g_tmph[Bn*En*CIN];
__device__ bf16 g_tmpl[Bn*En*CIN];
__device__ bf16 g_wphih[CIN*Fn];
__device__ bf16 g_wphil[CIN*Fn];
__device__ bf16 g_w2h[CIN*En];
__device__ bf16 g_w2l[CIN*En];

// =================== helpers =================================================
__global__ void cvt_split(const float* __restrict__ src, bf16* __restrict__ hi,
                          bf16* __restrict__ lo, long n){
    long i = (long)blockIdx.x*256 + threadIdx.x;
    if (i >= n) return;
    float v = src[i];
    bf16 h = __float2bfloat16_rn(v);
    hi[i] = h;
    lo[i] = __float2bfloat16_rn(v - __bfloat162float(h));
}

__device__ __forceinline__ uint32_t smem_u32(const void* p) {
    uint32_t a;
    asm("{ .reg .u64 t; cvta.to.shared.u64 t, %1; cvt.u32.u64 %0, t; }" : "=r"(a) : "l"(p));
    return a;
}
__device__ __forceinline__ void cp16(uint32_t d, const void* s, int sz){
    asm volatile("cp.async.cg.shared.global [%0], [%1], 16, %2;"
                 :: "r"(d), "l"(s), "r"(sz) : "memory");
}
__device__ __forceinline__ void ldsm4(uint32_t* r, uint32_t a){
    asm volatile("ldmatrix.sync.aligned.m8n8.x4.shared.b16 {%0,%1,%2,%3}, [%4];"
                 : "=r"(r[0]),"=r"(r[1]),"=r"(r[2]),"=r"(r[3]) : "r"(a));
}
__device__ __forceinline__ void ldsm4t(uint32_t* r, uint32_t a){
    asm volatile("ldmatrix.sync.aligned.m8n8.x4.trans.shared.b16 {%0,%1,%2,%3}, [%4];"
                 : "=r"(r[0]),"=r"(r[1]),"=r"(r[2]),"=r"(r[3]) : "r"(a));
}
__device__ __forceinline__ void mma16816(float* c, const uint32_t* a, uint32_t b0, uint32_t b1){
    asm volatile("mma.sync.aligned.m16n8k16.row.col.f32.bf16.bf16.f32 "
                 "{%0,%1,%2,%3}, {%4,%5,%6,%7}, {%8,%9}, {%0,%1,%2,%3};"
                 : "+f"(c[0]),"+f"(c[1]),"+f"(c[2]),"+f"(c[3])
                 : "r"(a[0]),"r"(a[1]),"r"(a[2]),"r"(a[3]), "r"(b0),"r"(b1));
}
__device__ __forceinline__ void st_split2(bf16* H, bf16* L, float v0, float v1){
    bf16 h0 = __float2bfloat16_rn(v0);
    bf16 h1 = __float2bfloat16_rn(v1);
    bf16 l0 = __float2bfloat16_rn(v0 - __bfloat162float(h0));
    bf16 l1 = __float2bfloat16_rn(v1 - __bfloat162float(h1));
    __nv_bfloat162 hp; hp.x = h0; hp.y = h1;
    __nv_bfloat162 lp; lp.x = l0; lp.y = l1;
    *(__nv_bfloat162*)H = hp;
    *(__nv_bfloat162*)L = lp;
}

// shared tile constants (128xN GEMM path)
#define A_LD   40
#define B_LD   136
#define OFF_AH 0
#define OFF_AL 5120
#define OFF_BH 10240
#define OFF_BL 14592
#define STAGE_E 18944
#define GEMM_SMEM (2*STAGE_E*2)

// inner 3-pass MMA block (NN + TN GEMMs, warp tile 32x64)
#define COMPUTE_TILE(sa_ah, sa_al, sa_bh, sa_bl, LOAD_A)                        \
    _Pragma("unroll")                                                           \
    for (int kk = 0; kk < 2; kk++){                                             \
        uint32_t ah[2][4], al[2][4];                                            \
        LOAD_A;                                                                 \
        _Pragma("unroll")                                                       \
        for (int nf = 0; nf < 4; nf++){                                         \
            uint32_t bh[4], bl[4];                                              \
            uint32_t bd = (sa_bh) + (uint32_t)((kk*16 + (lane & 15))*B_LD       \
                                          + nbase + nf*16 + (lane >> 4)*8)*2;   \
            ldsm4t(bh, bd);                                                     \
            ldsm4t(bl, bd + ((sa_bl)-(sa_bh)));                                 \
            _Pragma("unroll")                                                   \
            for (int mt = 0; mt < 2; mt++){                                     \
                float* c0 = acc[mt][nf*2];                                      \
                float* c1 = acc[mt][nf*2+1];                                    \
                mma16816(c0, ah[mt], bh[0], bh[1]);                             \
                mma16816(c1, ah[mt], bh[2], bh[3]);                             \
                mma16816(c0, ah[mt], bl[0], bl[1]);                             \
                mma16816(c1, ah[mt], bl[2], bl[3]);                             \
                mma16816(c0, al[mt], bh[0], bh[1]);                             \
                mma16816(c1, al[mt], bh[2], bh[3]);                             \
            }                                                                   \
        }                                                                       \
    }

// =================== conv: CTA 128x256, warp 64x64, 3-stage ==================
#define CB_LD   264                 // 256 + 8 pad (elems)
#define C_AH    0
#define C_AL    5120                // 128*40
#define C_BH    10240
#define C_BL    18688               // +32*264
#define C_STAGE 27136               // elems per stage
#define C_NSTG  3
#define CONV_SMEM (C_NSTG*C_STAGE*2)   // 162816 bytes
#define NCHUNK  392                 // 49 taps * 8 chunks of 32 ch

__device__ __forceinline__ void conv_load_chunk(
    uint32_t smb, int stage,
    const bf16* __restrict__ xh, const bf16* __restrict__ xl,
    const bf16* __restrict__ wh, const bf16* __restrict__ wl,
    long bV, int p0, int ic, int tid)
{
    int tap = ic >> 3, c0 = (ic & 7) * 32;
    int ky = tap / 7, kx = tap - ky*7;
    uint32_t base = smb + stage*C_STAGE*2;

    // ---- A: 128 pos-rows x 32 ch, hi & lo ----
    int row  = tid >> 1;
    int koff = (tid & 1) * 16;
    int pos = p0 + row;
    int hs = (pos >> 6) + ky - 3, ws = (pos & 63) + kx - 3;
    int sz = (((unsigned)hs < 64u) && ((unsigned)ws < 64u)) ? 16 : 0;
    long sidx = sz ? (bV + ((hs << 6) + ws)) * CIN + c0 + koff : 0;
    uint32_t da = base + (uint32_t)(C_AH + row*A_LD + koff)*2;
    cp16(da,      xh + sidx,     sz);
    cp16(da + 16, xh + sidx + 8, sz);
    uint32_t dal = base + (uint32_t)(C_AL + row*A_LD + koff)*2;
    cp16(dal,      xl + sidx,     sz);
    cp16(dal + 16, xl + sidx + 8, sz);

    // ---- B: 32 ch-rows x 256 E, hi & lo ----
    #pragma unroll
    for (int q = 0; q < 4; q++){
        int qq = tid + 256*q;               // 0..1023
        int brow = qq >> 5;                 // 0..31
        int bcol = (qq & 31) * 8;           // 0..248
        long widx = ((long)(tap*CIN + c0 + brow))*En + bcol;
        cp16(base + (uint32_t)(C_BH + brow*CB_LD + bcol)*2, wh + widx, 16);
        cp16(base + (uint32_t)(C_BL + brow*CB_LD + bcol)*2, wl + widx, 16);
    }
    asm volatile("cp.async.commit_group;" ::: "memory");
}

__global__ void __launch_bounds__(256, 1)
conv_mma(const bf16* __restrict__ xh, const bf16* __restrict__ xl,
         const bf16* __restrict__ wh, const bf16* __restrict__ wl,
         const float* __restrict__ bm, bf16* __restrict__ Mh, bf16* __restrict__ Ml)
{
    extern __shared__ char smem[];
    uint32_t smb = smem_u32(smem);
    int tid = threadIdx.x;
    int wid = tid >> 5, lane = tid & 31;
    int p0 = blockIdx.x * 128;
    int b  = blockIdx.y;
    long bV = (long)b * Vn;

    int mbase = (wid & 1) * 64;
    int nbase = (wid >> 1) * 64;

    float acc[4][8][4];
    #pragma unroll
    for (int i=0;i<4;i++)
    #pragma unroll
        for (int j=0;j<8;j++)
        #pragma unroll
            for (int k=0;k<4;k++) acc[i][j][k]=0.f;

    conv_load_chunk(smb, 0, xh, xl, wh, wl, bV, p0, 0, tid);
    conv_load_chunk(smb, 1, xh, xl, wh, wl, bV, p0, 1, tid);
    conv_load_chunk(smb, 2, xh, xl, wh, wl, bV, p0, 2, tid);

    int stage = 0;
    for (int ic = 0; ic < NCHUNK; ic++){
        if (ic < NCHUNK-3) asm volatile("cp.async.wait_group 2;" ::: "memory");
        else               asm volatile("cp.async.wait_group 0;" ::: "memory");
        __syncthreads();

        uint32_t sa = smb + (uint32_t)stage*C_STAGE*2;
        #pragma unroll
        for (int kk = 0; kk < 2; kk++){
            uint32_t ah[4][4], al[4][4];
            #pragma unroll
            for (int mt = 0; mt < 4; mt++){
                uint32_t ad = sa + (uint32_t)((mbase + mt*16 + (lane & 15))*A_LD
                                              + kk*16 + (lane >> 4)*8)*2;
                ldsm4(ah[mt], ad);
                ldsm4(al[mt], ad + (C_AL - C_AH)*2);
            }
            #pragma unroll
            for (int nf = 0; nf < 4; nf++){
                uint32_t bh[4], bl[4];
                uint32_t bd = sa + (uint32_t)(C_BH + (kk*16 + (lane & 15))*CB_LD
                                              + nbase + nf*16 + (lane >> 4)*8)*2;
                ldsm4t(bh, bd);
                ldsm4t(bl, bd + (C_BL - C_BH)*2);
                #pragma unroll
                for (int mt = 0; mt < 4; mt++){
                    float* c0 = acc[mt][nf*2];
                    float* c1 = acc[mt][nf*2+1];
                    mma16816(c0, ah[mt], bh[0], bh[1]);   // hi*hi
                    mma16816(c1, ah[mt], bh[2], bh[3]);
                    mma16816(c0, ah[mt], bl[0], bl[1]);   // hi*lo
                    mma16816(c1, ah[mt], bl[2], bl[3]);
                    mma16816(c0, al[mt], bh[0], bh[1]);   // lo*hi
                    mma16816(c1, al[mt], bh[2], bh[3]);
                }
            }
        }
        __syncthreads();
        if (ic + 3 < NCHUNK)
            conv_load_chunk(smb, stage, xh, xl, wh, wl, bV, p0, ic + 3, tid);
        stage = (stage == C_NSTG-1) ? 0 : stage + 1;
    }

    // epilogue: split-store 128x256 with bias
    #pragma unroll
    for (int mt = 0; mt < 4; mt++){
        long r0 = bV + p0 + mbase + mt*16 + (lane >> 2);
        #pragma unroll
        for (int n8 = 0; n8 < 8; n8++){
            int col = nbase + n8*8 + (lane & 3)*2;
            float b0 = bm[col], b1 = bm[col+1];
            float* c = acc[mt][n8];
            st_split2(Mh + r0*En + col,     Ml + r0*En + col,     c[0]+b0, c[1]+b1);
            st_split2(Mh + (r0+8)*En + col, Ml + (r0+8)*En + col, c[2]+b0, c[3]+b1);
        }
    }
}

// =================== generic NN HMMA GEMM (warp 32x64) =======================
__device__ __forceinline__ void nn_load_chunk(
    uint32_t smb, int stage,
    const bf16* __restrict__ Ah, const bf16* __restrict__ Al,
    const bf16* __restrict__ Bh, const bf16* __restrict__ Bl,
    int m0, int n0, int k0, int K, int N, int tid)
{
    uint32_t base = smb + stage*STAGE_E*2;
    int row  = tid >> 1;
    int koff = (tid & 1) * 16;
    long sidx = (long)(m0+row)*K + k0 + koff;
    uint32_t da = base + (uint32_t)(OFF_AH + row*A_LD + koff)*2;
    cp16(da,      Ah + sidx,     16);
    cp16(da + 16, Ah + sidx + 8, 16);
    uint32_t dal = base + (uint32_t)(OFF_AL + row*A_LD + koff)*2;
    cp16(dal,      Al + sidx,     16);
    cp16(dal + 16, Al + sidx + 8, 16);
    #pragma unroll
    for (int q = 0; q < 2; q++){
        int qq = tid*2 + q;
        int brow = qq >> 4;
        int bcol = (qq & 15) * 8;
        long widx = (long)(k0+brow)*N + n0 + bcol;
        uint32_t db = base + (uint32_t)(OFF_BH + brow*B_LD + bcol)*2;
        cp16(db, Bh + widx, 16);
        uint32_t dbl = base + (uint32_t)(OFF_BL + brow*B_LD + bcol)*2;
        cp16(dbl, Bl + widx, 16);
    }
    asm volatile("cp.async.commit_group;" ::: "memory");
}

__global__ void __launch_bounds__(256, 2)
hgemm_nn(const bf16* __restrict__ Ah, const bf16* __restrict__ Al,
         const bf16* __restrict__ Bh, const bf16* __restrict__ Bl,
         float* __restrict__ Cf, bf16* __restrict__ Ch, bf16* __restrict__ Cl,
         const float* __restrict__ aux,
         int N, int K, long sA, long sB, long sC, long sAux, int epi)
{
    extern __shared__ char smem[];
    uint32_t smb = smem_u32(smem);
    int tid = threadIdx.x;
    int wid = tid >> 5, lane = tid & 31;
    int n0 = blockIdx.x * 128;
    int m0 = blockIdx.y * 128;
    int b  = blockIdx.z;
    Ah += (long)b*sA; Al += (long)b*sA;
    Bh += (long)b*sB; Bl += (long)b*sB;
    const float* auxp = aux ? aux + (long)b*sAux : (const float*)0;

    int mbase = (wid & 3) * 32;
    int nbase = (wid >> 2) * 64;

    float acc[2][8][4];
    #pragma unroll
    for (int i=0;i<2;i++)
    #pragma unroll
        for (int j=0;j<8;j++)
        #pragma unroll
            for (int k=0;k<4;k++) acc[i][j][k]=0.f;

    int nchunk = K >> 5;
    nn_load_chunk(smb, 0, Ah, Al, Bh, Bl, m0, n0, 0,  K, N, tid);
    nn_load_chunk(smb, 1, Ah, Al, Bh, Bl, m0, n0, 32, K, N, tid);

    for (int ic = 0; ic < nchunk; ic++){
        if (ic < nchunk-2) asm volatile("cp.async.wait_group 1;" ::: "memory");
        else               asm volatile("cp.async.wait_group 0;" ::: "memory");
        __syncthreads();
        uint32_t sa = smb + (uint32_t)(ic & 1)*STAGE_E*2;
        COMPUTE_TILE(sa + OFF_AH*2, sa + OFF_AL*2, sa + OFF_BH*2, sa + OFF_BL*2,
            {
                _Pragma("unroll")
                for (int mt = 0; mt < 2; mt++){
                    uint32_t ad = sa + (uint32_t)((mbase + mt*16 + (lane & 15))*A_LD
                                                  + kk*16 + (lane >> 4)*8)*2;
                    ldsm4(ah[mt], ad);
                    ldsm4(al[mt], ad + OFF_AL*2);
                }
            });
        __syncthreads();
        if (ic + 2 < nchunk)
            nn_load_chunk(smb, ic & 1, Ah, Al, Bh, Bl, m0, n0, (ic+2)*32, K, N, tid);
    }

    #pragma unroll
    for (int mt = 0; mt < 2; mt++){
        long r0 = m0 + mbase + mt*16 + (lane >> 2);
        #pragma unroll
        for (int n8 = 0; n8 < 8; n8++){
            int col = n0 + nbase + n8*8 + (lane & 3)*2;
            float* c = acc[mt][n8];
            float v00=c[0], v01=c[1], v10=c[2], v11=c[3];
            if (epi == 0){
                float b0 = auxp[col], b1 = auxp[col+1];
                v00+=b0; v01+=b1; v10+=b0; v11+=b1;
            } else if (epi == 1){
                v00=fabsf(v00); v01=fabsf(v01); v10=fabsf(v10); v11=fabsf(v11);
            } else {
                v00 = auxp[r0*N + col]     - v00;
                v01 = auxp[r0*N + col + 1] - v01;
                v10 = auxp[(r0+8)*N + col]     - v10;
                v11 = auxp[(r0+8)*N + col + 1] - v11;
            }
            if (Cf){
                float* base = Cf + (long)b*sC;
                *(float2*)(base + r0*N + col)     = make_float2(v00, v01);
                *(float2*)(base + (r0+8)*N + col) = make_float2(v10, v11);
            }
            if (Ch){
                bf16* bh = Ch + (long)b*sC;
                bf16* bl = Cl + (long)b*sC;
                st_split2(bh + r0*N + col,     bl + r0*N + col,     v00, v01);
                st_split2(bh + (r0+8)*N + col, bl + (r0+8)*N + col, v10, v11);
            }
        }
    }
}

// =================== TN HMMA split-K partials ================================
#define TN_AH 0
#define TN_AL 4352
#define TN_BH 8704
#define TN_BL 13056
#define TN_STAGE 17408
#define TN_SMEM (2*TN_STAGE*2)

__device__ __forceinline__ void tn_load_chunk(
    uint32_t smb, int stage,
    const bf16* __restrict__ Ah, const bf16* __restrict__ Al,
    const bf16* __restrict__ Bh, const bf16* __restrict__ Bl,
    long offA, long offB, int m0, int n0, int k0, int lda, int ldb, int tid)
{
    uint32_t base = smb + stage*TN_STAGE*2;
    #pragma unroll
    for (int q = 0; q < 2; q++){
        int qq = tid*2 + q;
        int brow = qq >> 4;
        int bcol = (qq & 15) * 8;
        long aidx = offA + (long)(k0+brow)*lda + m0 + bcol;
        uint32_t da = base + (uint32_t)(TN_AH + brow*B_LD + bcol)*2;
        cp16(da, Ah + aidx, 16);
        cp16(base + (uint32_t)(TN_AL + brow*B_LD + bcol)*2, Al + aidx, 16);
        long bidx = offB + (long)(k0+brow)*ldb + n0 + bcol;
        cp16(base + (uint32_t)(TN_BH + brow*B_LD + bcol)*2, Bh + bidx, 16);
        cp16(base + (uint32_t)(TN_BL + brow*B_LD + bcol)*2, Bl + bidx, 16);
    }
    asm volatile("cp.async.commit_group;" ::: "memory");
}

__global__ void __launch_bounds__(256, 2)
hgemm_tn(const bf16* __restrict__ Ah, const bf16* __restrict__ Al,
         const bf16* __restrict__ Bh, const bf16* __restrict__ Bl,
         float* __restrict__ P, int Mo, int No, int lda, int ldb, int Kc,
         long sA, long sB)
{
    extern __shared__ char smem[];
    uint32_t smb = smem_u32(smem);
    int tid = threadIdx.x;
    int wid = tid >> 5, lane = tid & 31;
    int b = blockIdx.z / NCH, s = blockIdx.z % NCH;
    long offA = (long)b*sA + (long)s*Kc*lda;
    long offB = (long)b*sB + (long)s*Kc*ldb;
    P += (long)(b*NCH + s)*Mo*No;
    int n0 = blockIdx.x * 128;
    int m0 = blockIdx.y * 128;

    int mbase = (wid & 3) * 32;
    int nbase = (wid >> 2) * 64;

    float acc[2][8][4];
    #pragma unroll
    for (int i=0;i<2;i++)
    #pragma unroll
        for (int j=0;j<8;j++)
        #pragma unroll
            for (int k=0;k<4;k++) acc[i][j][k]=0.f;

    int nchunk = Kc >> 5;
    tn_load_chunk(smb, 0, Ah, Al, Bh, Bl, offA, offB, m0, n0, 0,  lda, ldb, tid);
    tn_load_chunk(smb, 1, Ah, Al, Bh, Bl, offA, offB, m0, n0, 32, lda, ldb, tid);

    int krow = (lane & 7) + (lane >> 4)*8;
    int msub = ((lane >> 3) & 1)*8;

    for (int ic = 0; ic < nchunk; ic++){
        if (ic < nchunk-2) asm volatile("cp.async.wait_group 1;" ::: "memory");
        else               asm volatile("cp.async.wait_group 0;" ::: "memory");
        __syncthreads();
        uint32_t sa = smb + (uint32_t)(ic & 1)*TN_STAGE*2;
        COMPUTE_TILE(sa + TN_AH*2, sa + TN_AL*2, sa + TN_BH*2, sa + TN_BL*2,
            {
                _Pragma("unroll")
                for (int mt = 0; mt < 2; mt++){
                    uint32_t ad = sa + (uint32_t)(TN_AH + (kk*16 + krow)*B_LD
                                                  + mbase + mt*16 + msub)*2;
                    ldsm4t(ah[mt], ad);
                    ldsm4t(al[mt], ad + (TN_AL - TN_AH)*2);
                }
            });
        __syncthreads();
        if (ic + 2 < nchunk)
            tn_load_chunk(smb, ic & 1, Ah, Al, Bh, Bl, offA, offB, m0, n0, (ic+2)*32, lda, ldb, tid);
    }

    #pragma unroll
    for (int mt = 0; mt < 2; mt++){
        long r0 = m0 + mbase + mt*16 + (lane >> 2);
        #pragma unroll
        for (int n8 = 0; n8 < 8; n8++){
            int col = n0 + nbase + n8*8 + (lane & 3)*2;
            float* c = acc[mt][n8];
            *(float2*)(P + r0*No + col)     = make_float2(c[0], c[1]);
            *(float2*)(P + (r0+8)*No + col) = make_float2(c[2], c[3]);
        }
    }
}

// ---------------- small kernels ---------------------------------------------
__global__ void xmean_part(const float* __restrict__ x, float* __restrict__ xp){
    int b=blockIdx.x, s=blockIdx.y, tid=threadIdx.x;
    const float* p = x + ((long)b*Vn + s*(Vn/NCH))*CIN + tid;
    float acc=0.f;
    for (int i=0;i<Vn/NCH;i++) acc += p[(long)i*CIN];
    xp[(b*NCH+s)*CIN+tid]=acc;
}

__global__ void a_kernel(const float* __restrict__ xp, const float* __restrict__ w_a,
                         const float* __restrict__ b_a, float* __restrict__ a){
    __shared__ float xm[CIN];
    __shared__ float part[256];
    int b=blockIdx.x, tid=threadIdx.x;
    float acc=0.f;
    #pragma unroll
    for (int ch=0;ch<NCH;ch++) acc += xp[(b*NCH+ch)*CIN+tid];
    xm[tid] = acc * (1.0f/(float)Vn);
    __syncthreads();
    int f = tid & 127, half = tid >> 7;
    float s = 0.f;
    #pragma unroll 4
    for (int c = half*128; c < half*128 + 128; c++) s += xm[c]*w_a[c*Fn+f];
    part[tid] = s;
    __syncthreads();
    if (tid < Fn) a[b*Fn+tid] = part[tid] + part[tid+128] + b_a[tid];
}

__global__ void colsum_part(const float* __restrict__ Hm, float* __restrict__ cp){
    int b=blockIdx.x, s=blockIdx.y, tid=threadIdx.x;
    const float* p = Hm + ((long)b*Vn + s*(Vn/NCH))*En + tid;
    float acc=0.f;
    for (int i=0;i<Vn/NCH;i++) acc += p[(long)i*En];
    cp[(b*NCH+s)*En+tid]=acc;
}

__global__ void binv_kernel(const float* __restrict__ cp, float* __restrict__ binv){
    int b=blockIdx.x, tid=threadIdx.x;
    float s=0.f;
    #pragma unroll
    for (int ch=0;ch<NCH;ch++) s += cp[(b*NCH+ch)*En+tid];
    binv[b*En+tid] = 1.0f/s;
}

__global__ void rowscale_split(const float* __restrict__ H,
                               bf16* __restrict__ Hh, bf16* __restrict__ Hl){
    __shared__ float red[256];
    long row = blockIdx.x;
    int tid = threadIdx.x;
    const float* hr = H + row*En;
    float v = hr[tid];
    red[tid]=v; __syncthreads();
    for (int s=128;s>0;s>>=1){ if(tid<s) red[tid]+=red[tid+s]; __syncthreads(); }
    float o = v * rsqrtf(red[0]);
    bf16 h = __float2bfloat16_rn(o);
    Hh[row*En + tid] = h;
    Hl[row*En + tid] = __float2bfloat16_rn(o - __bfloat162float(h));
}

__global__ void reduce_scale_split(bf16* __restrict__ outh, bf16* __restrict__ outl,
                                   const float* __restrict__ part,
                                   const float* __restrict__ scale, int R, int C){
    long idx = (long)blockIdx.x*256 + threadIdx.x;
    int c = (int)(idx % C); long rc = idx / C; int r = (int)(rc % R); int b = (int)(rc / R);
    float s=0.f;
#pragma unroll
    for (int ch=0;ch<NCH;ch++) s += part[((long)(b*NCH+ch)*R + r)*C + c];
    float v = s * scale[b*R + r];
    bf16 h = __float2bfloat16_rn(v);
    outh[idx] = h;
    outl[idx] = __float2bfloat16_rn(v - __bfloat162float(h));
}

// ---------------- host launch ------------------------------------------------
extern "C" void kernel_launch(void* const* d_in, const int* in_sizes, int n_in,
                              void* d_out, int out_size){
    (void)in_sizes; (void)n_in; (void)out_size;
    const float* x    =(const float*)d_in[0];
    const float* wphi =(const float*)d_in[1];
    const float* bphi =(const float*)d_in[2];
    const float* wa   =(const float*)d_in[3];
    const float* ba   =(const float*)d_in[4];
    const float* wm   =(const float*)d_in[5];
    const float* bm   =(const float*)d_in[6];
    const float* w2   =(const float*)d_in[7];
    const float* b2   =(const float*)d_in[8];
    float* out=(float*)d_out;

    float *aV,*Hb,*binv,*p1,*p2,*xp,*cp;
    bf16 *xh,*xl,*wh,*wl,*phih,*phil,*Mh,*Ml,*Hh,*Hl,*yh,*yl,*th,*tl,*tmph,*tmpl;
    bf16 *wphih,*wphil,*w2h,*w2l;
    cudaGetSymbolAddress((void**)&aV  , g_a);
    cudaGetSymbolAddress((void**)&Hb  , g_H);
    cudaGetSymbolAddress((void**)&binv, g_Binv);
    cudaGetSymbolAddress((void**)&p1  , g_p1);
    cudaGetSymbolAddress((void**)&p2  , g_p2);
    cudaGetSymbolAddress((void**)&xp  , g_xp);
    cudaGetSymbolAddress((void**)&cp  , g_cp);
    cudaGetSymbolAddress((void**)&xh  , g_xh);
    cudaGetSymbolAddress((void**)&xl  , g_xl);
    cudaGetSymbolAddress((void**)&wh  , g_wh);
    cudaGetSymbolAddress((void**)&wl  , g_wl);
    cudaGetSymbolAddress((void**)&phih, g_phih);
    cudaGetSymbolAddress((void**)&phil, g_phil);
    cudaGetSymbolAddress((void**)&Mh  , g_Mh);
    cudaGetSymbolAddress((void**)&Ml  , g_Ml);
    cudaGetSymbolAddress((void**)&Hh  , g_Hh);
    cudaGetSymbolAddress((void**)&Hl  , g_Hl);
    cudaGetSymbolAddress((void**)&yh  , g_yh);
    cudaGetSymbolAddress((void**)&yl  , g_yl);
    cudaGetSymbolAddress((void**)&th  , g_th);
    cudaGetSymbolAddress((void**)&tl  , g_tl);
    cudaGetSymbolAddress((void**)&tmph, g_tmph);
    cudaGetSymbolAddress((void**)&tmpl, g_tmpl);
    cudaGetSymbolAddress((void**)&wphih, g_wphih);
    cudaGetSymbolAddress((void**)&wphil, g_wphil);
    cudaGetSymbolAddress((void**)&w2h , g_w2h);
    cudaGetSymbolAddress((void**)&w2l , g_w2l);

    cudaFuncSetAttribute(conv_mma, cudaFuncAttributeMaxDynamicSharedMemorySize, CONV_SMEM);
    cudaFuncSetAttribute(hgemm_nn, cudaFuncAttributeMaxDynamicSharedMemorySize, GEMM_SMEM);
    cudaFuncSetAttribute(hgemm_tn, cudaFuncAttributeMaxDynamicSharedMemorySize, TN_SMEM);

    // splits of inputs
    cvt_split<<<(Bn*Vn*CIN + 255)/256, 256>>>(x, xh, xl, (long)Bn*Vn*CIN);
    cvt_split<<<(49*CIN*En + 255)/256, 256>>>(wm, wh, wl, (long)49*CIN*En);
    cvt_split<<<(CIN*Fn + 255)/256, 256>>>(wphi, wphih, wphil, (long)CIN*Fn);
    cvt_split<<<(CIN*En + 255)/256, 256>>>(w2, w2h, w2l, (long)CIN*En);

    // mean(x) -> a
    xmean_part<<<dim3(Bn,NCH),256>>>(x, xp);
    a_kernel<<<Bn,256>>>(xp, wa, ba, aV);

    // phi = x @ w_phi + b_phi -> split (M=32768, N=128, K=256)
    hgemm_nn<<<dim3(1,256,1),256,GEMM_SMEM>>>(xh, xl, wphih, wphil,
        (float*)0, phih, phil, bphi, Fn, CIN, 0,0,(long)0,0, 0);

    // M = conv7x7(x) + b_m -> split  (CTA 128x256, warp 64x64)
    conv_mma<<<dim3(32, Bn), 256, CONV_SMEM>>>(xh, xl, wh, wl, bm, Mh, Ml);

    // t = a * (phi^T @ M) -> split
    hgemm_tn<<<dim3(2,1,Bn*NCH),256,TN_SMEM>>>(phih, phil, Mh, Ml, p1,
        Fn, En, Fn, En, Vn/NCH, (long)Vn*Fn, (long)Vn*En);
    reduce_scale_split<<<(Bn*Fn*En)/256,256>>>(th, tl, p1, aV, Fn, En);

    // H = |phi @ t|  (fp32 out)
    hgemm_nn<<<dim3(2,32,Bn),256,GEMM_SMEM>>>(phih, phil, th, tl,
        Hb, (bf16*)0, (bf16*)0, (const float*)0, En, Fn,
        (long)Vn*Fn, (long)Fn*En, (long)Vn*En, 0, 1);

    // Binv from column sums of H
    colsum_part<<<dim3(Bn,NCH),256>>>(Hb, cp);
    binv_kernel<<<Bn,256>>>(cp, binv);

    // D_H = D^{-1/2} H -> split
    rowscale_split<<<Bn*Vn,256>>>(Hb, Hh, Hl);

    // tmp = Binv * (D_H^T @ x) -> split
    hgemm_tn<<<dim3(2,2,Bn*NCH),256,TN_SMEM>>>(Hh, Hl, xh, xl, p2,
        En, CIN, En, CIN, Vn/NCH, (long)Vn*En, (long)Vn*CIN);
    reduce_scale_split<<<(Bn*En*CIN)/256,256>>>(tmph, tmpl, p2, binv, En, CIN);

    // y = x - D_H @ tmp -> split
    hgemm_nn<<<dim3(2,32,Bn),256,GEMM_SMEM>>>(Hh, Hl, tmph, tmpl,
        (float*)0, yh, yl, x, CIN, En,
        (long)Vn*En, (long)En*CIN, (long)Vn*CIN, (long)Vn*CIN, 2);

    // out = y @ w2 + b2  (M=32768, N=256, K=256)
    hgemm_nn<<<dim3(2,256,1),256,GEMM_SMEM>>>(yh, yl, w2h, w2l,
        out, (bf16*)0, (bf16*)0, b2, En, CIN, 0,0,(long)0,0, 0);
}

// round 9
// speedup vs baseline: 3.3411x; 1.3446x over previous
#include <cuda_runtime.h>
#include <cuda_bf16.h>
#include <cuda_fp16.h>
#include <cstdint>

typedef unsigned long long u64;
typedef __nv_bfloat16 bf16;

#define Bn   8
#define Vn   4096
#define CIN  256
#define Fn   128
#define En   256
#define NCH  16

// ---------------- scratch (device globals) -----------------------------------
__device__ float g_a   [Bn*Fn];
__device__ float g_H   [Bn*Vn*En];
__device__ float g_Binv[Bn*En];
__device__ float g_p1  [Bn*NCH*Fn*En];
__device__ float g_p2  [Bn*NCH*En*CIN];
__device__ float g_xp  [Bn*NCH*CIN];
__device__ float g_cp  [Bn*NCH*En];
// bf16 split operand pairs (GEMM path)
__device__ bf16 g_xh [Bn*Vn*CIN];
__device__ bf16 g_xl [Bn*Vn*CIN];
__device__ bf16 g_phih[Bn*Vn*Fn];
__device__ bf16 g_phil[Bn*Vn*Fn];
__device__ bf16 g_Mh [Bn*Vn*En];
__device__ bf16 g_Ml [Bn*Vn*En];
__device__ bf16 g_Hh [Bn*Vn*En];
__device__ bf16 g_Hl [Bn*Vn*En];
__device__ bf16 g_yh [Bn*Vn*CIN];
__device__ bf16 g_yl [Bn*Vn*CIN];
__device__ bf16 g_th [Bn*Fn*En];
__device__ bf16 g_tl [Bn*Fn*En];
__device__ bf16 g_tmph[Bn*En*CIN];
__device__ bf16 g_tmpl[Bn*En*CIN];
__device__ bf16 g_wphih[CIN*Fn];
__device__ bf16 g_wphil[CIN*Fn];
__device__ bf16 g_w2h[CIN*En];
__device__ bf16 g_w2l[CIN*En];
// fp16 operands for the 2-pass conv
__device__ __half g_x16h[Bn*Vn*CIN];
__device__ __half g_x16l[Bn*Vn*CIN];
__device__ __half g_w16 [49*CIN*En];

// =================== helpers =================================================
__global__ void cvt_split(const float* __restrict__ src, bf16* __restrict__ hi,
                          bf16* __restrict__ lo, long n){
    long i = (long)blockIdx.x*256 + threadIdx.x;
    if (i >= n) return;
    float v = src[i];
    bf16 h = __float2bfloat16_rn(v);
    hi[i] = h;
    lo[i] = __float2bfloat16_rn(v - __bfloat162float(h));
}
__global__ void cvt_split_h(const float* __restrict__ src, __half* __restrict__ hi,
                            __half* __restrict__ lo, long n){
    long i = (long)blockIdx.x*256 + threadIdx.x;
    if (i >= n) return;
    float v = src[i];
    __half h = __float2half_rn(v);
    hi[i] = h;
    lo[i] = __float2half_rn(v - __half2float(h));
}
__global__ void cvt_h(const float* __restrict__ src, __half* __restrict__ dst, long n){
    long i = (long)blockIdx.x*256 + threadIdx.x;
    if (i >= n) return;
    dst[i] = __float2half_rn(src[i]);
}

__device__ __forceinline__ uint32_t smem_u32(const void* p) {
    uint32_t a;
    asm("{ .reg .u64 t; cvta.to.shared.u64 t, %1; cvt.u32.u64 %0, t; }" : "=r"(a) : "l"(p));
    return a;
}
__device__ __forceinline__ void cp16(uint32_t d, const void* s, int sz){
    asm volatile("cp.async.cg.shared.global [%0], [%1], 16, %2;"
                 :: "r"(d), "l"(s), "r"(sz) : "memory");
}
__device__ __forceinline__ void ldsm4(uint32_t* r, uint32_t a){
    asm volatile("ldmatrix.sync.aligned.m8n8.x4.shared.b16 {%0,%1,%2,%3}, [%4];"
                 : "=r"(r[0]),"=r"(r[1]),"=r"(r[2]),"=r"(r[3]) : "r"(a));
}
__device__ __forceinline__ void ldsm4t(uint32_t* r, uint32_t a){
    asm volatile("ldmatrix.sync.aligned.m8n8.x4.trans.shared.b16 {%0,%1,%2,%3}, [%4];"
                 : "=r"(r[0]),"=r"(r[1]),"=r"(r[2]),"=r"(r[3]) : "r"(a));
}
__device__ __forceinline__ void mma16816(float* c, const uint32_t* a, uint32_t b0, uint32_t b1){
    asm volatile("mma.sync.aligned.m16n8k16.row.col.f32.bf16.bf16.f32 "
                 "{%0,%1,%2,%3}, {%4,%5,%6,%7}, {%8,%9}, {%0,%1,%2,%3};"
                 : "+f"(c[0]),"+f"(c[1]),"+f"(c[2]),"+f"(c[3])
                 : "r"(a[0]),"r"(a[1]),"r"(a[2]),"r"(a[3]), "r"(b0),"r"(b1));
}
__device__ __forceinline__ void mma16816h(float* c, const uint32_t* a, uint32_t b0, uint32_t b1){
    asm volatile("mma.sync.aligned.m16n8k16.row.col.f32.f16.f16.f32 "
                 "{%0,%1,%2,%3}, {%4,%5,%6,%7}, {%8,%9}, {%0,%1,%2,%3};"
                 : "+f"(c[0]),"+f"(c[1]),"+f"(c[2]),"+f"(c[3])
                 : "r"(a[0]),"r"(a[1]),"r"(a[2]),"r"(a[3]), "r"(b0),"r"(b1));
}
__device__ __forceinline__ void st_split2(bf16* H, bf16* L, float v0, float v1){
    bf16 h0 = __float2bfloat16_rn(v0);
    bf16 h1 = __float2bfloat16_rn(v1);
    bf16 l0 = __float2bfloat16_rn(v0 - __bfloat162float(h0));
    bf16 l1 = __float2bfloat16_rn(v1 - __bfloat162float(h1));
    __nv_bfloat162 hp; hp.x = h0; hp.y = h1;
    __nv_bfloat162 lp; lp.x = l0; lp.y = l1;
    *(__nv_bfloat162*)H = hp;
    *(__nv_bfloat162*)L = lp;
}

// shared tile constants (128xN GEMM path)
#define A_LD   40
#define B_LD   136
#define OFF_AH 0
#define OFF_AL 5120
#define OFF_BH 10240
#define OFF_BL 14592
#define STAGE_E 18944
#define GEMM_SMEM (2*STAGE_E*2)

// inner 3-pass MMA block (NN + TN GEMMs, warp tile 32x64)
#define COMPUTE_TILE(sa_ah, sa_al, sa_bh, sa_bl, LOAD_A)                        \
    _Pragma("unroll")                                                           \
    for (int kk = 0; kk < 2; kk++){                                             \
        uint32_t ah[2][4], al[2][4];                                            \
        LOAD_A;                                                                 \
        _Pragma("unroll")                                                       \
        for (int nf = 0; nf < 4; nf++){                                         \
            uint32_t bh[4], bl[4];                                              \
            uint32_t bd = (sa_bh) + (uint32_t)((kk*16 + (lane & 15))*B_LD       \
                                          + nbase + nf*16 + (lane >> 4)*8)*2;   \
            ldsm4t(bh, bd);                                                     \
            ldsm4t(bl, bd + ((sa_bl)-(sa_bh)));                                 \
            _Pragma("unroll")                                                   \
            for (int mt = 0; mt < 2; mt++){                                     \
                float* c0 = acc[mt][nf*2];                                      \
                float* c1 = acc[mt][nf*2+1];                                    \
                mma16816(c0, ah[mt], bh[0], bh[1]);                             \
                mma16816(c1, ah[mt], bh[2], bh[3]);                             \
                mma16816(c0, ah[mt], bl[0], bl[1]);                             \
                mma16816(c1, ah[mt], bl[2], bl[3]);                             \
                mma16816(c0, al[mt], bh[0], bh[1]);                             \
                mma16816(c1, al[mt], bh[2], bh[3]);                             \
            }                                                                   \
        }                                                                       \
    }

// =================== conv: fp16 2-pass, CTA 128x256, warp 64x64, 4-stage =====
#define CB_LD   264                 // 256 + 8 pad (elems)
#define C_AH    0
#define C_AL    5120                // 128*40
#define C_BH    10240
#define C_STAGE 18688               // elems per stage (A hi+lo + B single)
#define C_NSTG  4
#define CONV_SMEM (C_NSTG*C_STAGE*2)   // 149504 bytes
#define NCHUNK  392                 // 49 taps * 8 chunks of 32 ch

__device__ __forceinline__ void conv_load_chunk(
    uint32_t smb, int stage,
    const __half* __restrict__ xh, const __half* __restrict__ xl,
    const __half* __restrict__ wf,
    long bV, int p0, int ic, int tid)
{
    int tap = ic >> 3, c0 = (ic & 7) * 32;
    int ky = tap / 7, kx = tap - ky*7;
    uint32_t base = smb + stage*C_STAGE*2;

    // ---- A: 128 pos-rows x 32 ch, hi & lo ----
    int row  = tid >> 1;
    int koff = (tid & 1) * 16;
    int pos = p0 + row;
    int hs = (pos >> 6) + ky - 3, ws = (pos & 63) + kx - 3;
    int sz = (((unsigned)hs < 64u) && ((unsigned)ws < 64u)) ? 16 : 0;
    long sidx = sz ? (bV + ((hs << 6) + ws)) * CIN + c0 + koff : 0;
    uint32_t da = base + (uint32_t)(C_AH + row*A_LD + koff)*2;
    cp16(da,      xh + sidx,     sz);
    cp16(da + 16, xh + sidx + 8, sz);
    uint32_t dal = base + (uint32_t)(C_AL + row*A_LD + koff)*2;
    cp16(dal,      xl + sidx,     sz);
    cp16(dal + 16, xl + sidx + 8, sz);

    // ---- B: 32 ch-rows x 256 E, single fp16 ----
    #pragma unroll
    for (int q = 0; q < 4; q++){
        int qq = tid + 256*q;               // 0..1023
        int brow = qq >> 5;                 // 0..31
        int bcol = (qq & 31) * 8;           // 0..248
        long widx = ((long)(tap*CIN + c0 + brow))*En + bcol;
        cp16(base + (uint32_t)(C_BH + brow*CB_LD + bcol)*2, wf + widx, 16);
    }
    asm volatile("cp.async.commit_group;" ::: "memory");
}

__global__ void __launch_bounds__(256, 1)
conv_mma(const __half* __restrict__ xh, const __half* __restrict__ xl,
         const __half* __restrict__ wf,
         const float* __restrict__ bm, bf16* __restrict__ Mh, bf16* __restrict__ Ml)
{
    extern __shared__ char smem[];
    uint32_t smb = smem_u32(smem);
    int tid = threadIdx.x;
    int wid = tid >> 5, lane = tid & 31;
    int p0 = blockIdx.x * 128;
    int b  = blockIdx.y;
    long bV = (long)b * Vn;

    int mbase = (wid & 1) * 64;
    int nbase = (wid >> 1) * 64;

    float acc[4][8][4];
    #pragma unroll
    for (int i=0;i<4;i++)
    #pragma unroll
        for (int j=0;j<8;j++)
        #pragma unroll
            for (int k=0;k<4;k++) acc[i][j][k]=0.f;

    conv_load_chunk(smb, 0, xh, xl, wf, bV, p0, 0, tid);
    conv_load_chunk(smb, 1, xh, xl, wf, bV, p0, 1, tid);
    conv_load_chunk(smb, 2, xh, xl, wf, bV, p0, 2, tid);

    int stage = 0;
    for (int ic = 0; ic < NCHUNK; ic++){
        if (ic < NCHUNK-3) asm volatile("cp.async.wait_group 2;" ::: "memory");
        else               asm volatile("cp.async.wait_group 0;" ::: "memory");
        __syncthreads();

        uint32_t sa = smb + (uint32_t)stage*C_STAGE*2;
        #pragma unroll
        for (int kk = 0; kk < 2; kk++){
            uint32_t ah[4][4], al[4][4];
            #pragma unroll
            for (int mt = 0; mt < 4; mt++){
                uint32_t ad = sa + (uint32_t)((mbase + mt*16 + (lane & 15))*A_LD
                                              + kk*16 + (lane >> 4)*8)*2;
                ldsm4(ah[mt], ad);
                ldsm4(al[mt], ad + (C_AL - C_AH)*2);
            }
            #pragma unroll
            for (int nf = 0; nf < 4; nf++){
                uint32_t bh[4];
                uint32_t bd = sa + (uint32_t)(C_BH + (kk*16 + (lane & 15))*CB_LD
                                              + nbase + nf*16 + (lane >> 4)*8)*2;
                ldsm4t(bh, bd);
                #pragma unroll
                for (int mt = 0; mt < 4; mt++){
                    float* c0 = acc[mt][nf*2];
                    float* c1 = acc[mt][nf*2+1];
                    mma16816h(c0, ah[mt], bh[0], bh[1]);   // xh * w
                    mma16816h(c1, ah[mt], bh[2], bh[3]);
                    mma16816h(c0, al[mt], bh[0], bh[1]);   // xl * w
                    mma16816h(c1, al[mt], bh[2], bh[3]);
                }
            }
        }
        __syncthreads();
        if (ic + 3 < NCHUNK)
            conv_load_chunk(smb, (ic + 3) & 3, xh, xl, wf, bV, p0, ic + 3, tid);
        stage = (stage + 1) & 3;
    }

    // epilogue: split-store 128x256 with bias
    #pragma unroll
    for (int mt = 0; mt < 4; mt++){
        long r0 = bV + p0 + mbase + mt*16 + (lane >> 2);
        #pragma unroll
        for (int n8 = 0; n8 < 8; n8++){
            int col = nbase + n8*8 + (lane & 3)*2;
            float b0 = bm[col], b1 = bm[col+1];
            float* c = acc[mt][n8];
            st_split2(Mh + r0*En + col,     Ml + r0*En + col,     c[0]+b0, c[1]+b1);
            st_split2(Mh + (r0+8)*En + col, Ml + (r0+8)*En + col, c[2]+b0, c[3]+b1);
        }
    }
}

// =================== generic NN HMMA GEMM (warp 32x64) =======================
__device__ __forceinline__ void nn_load_chunk(
    uint32_t smb, int stage,
    const bf16* __restrict__ Ah, const bf16* __restrict__ Al,
    const bf16* __restrict__ Bh, const bf16* __restrict__ Bl,
    int m0, int n0, int k0, int K, int N, int tid)
{
    uint32_t base = smb + stage*STAGE_E*2;
    int row  = tid >> 1;
    int koff = (tid & 1) * 16;
    long sidx = (long)(m0+row)*K + k0 + koff;
    uint32_t da = base + (uint32_t)(OFF_AH + row*A_LD + koff)*2;
    cp16(da,      Ah + sidx,     16);
    cp16(da + 16, Ah + sidx + 8, 16);
    uint32_t dal = base + (uint32_t)(OFF_AL + row*A_LD + koff)*2;
    cp16(dal,      Al + sidx,     16);
    cp16(dal + 16, Al + sidx + 8, 16);
    #pragma unroll
    for (int q = 0; q < 2; q++){
        int qq = tid*2 + q;
        int brow = qq >> 4;
        int bcol = (qq & 15) * 8;
        long widx = (long)(k0+brow)*N + n0 + bcol;
        uint32_t db = base + (uint32_t)(OFF_BH + brow*B_LD + bcol)*2;
        cp16(db, Bh + widx, 16);
        uint32_t dbl = base + (uint32_t)(OFF_BL + brow*B_LD + bcol)*2;
        cp16(dbl, Bl + widx, 16);
    }
    asm volatile("cp.async.commit_group;" ::: "memory");
}

__global__ void __launch_bounds__(256, 2)
hgemm_nn(const bf16* __restrict__ Ah, const bf16* __restrict__ Al,
         const bf16* __restrict__ Bh, const bf16* __restrict__ Bl,
         float* __restrict__ Cf, bf16* __restrict__ Ch, bf16* __restrict__ Cl,
         const float* __restrict__ aux,
         int N, int K, long sA, long sB, long sC, long sAux, int epi)
{
    extern __shared__ char smem[];
    uint32_t smb = smem_u32(smem);
    int tid = threadIdx.x;
    int wid = tid >> 5, lane = tid & 31;
    int n0 = blockIdx.x * 128;
    int m0 = blockIdx.y * 128;
    int b  = blockIdx.z;
    Ah += (long)b*sA; Al += (long)b*sA;
    Bh += (long)b*sB; Bl += (long)b*sB;
    const float* auxp = aux ? aux + (long)b*sAux : (const float*)0;

    int mbase = (wid & 3) * 32;
    int nbase = (wid >> 2) * 64;

    float acc[2][8][4];
    #pragma unroll
    for (int i=0;i<2;i++)
    #pragma unroll
        for (int j=0;j<8;j++)
        #pragma unroll
            for (int k=0;k<4;k++) acc[i][j][k]=0.f;

    int nchunk = K >> 5;
    nn_load_chunk(smb, 0, Ah, Al, Bh, Bl, m0, n0, 0,  K, N, tid);
    nn_load_chunk(smb, 1, Ah, Al, Bh, Bl, m0, n0, 32, K, N, tid);

    for (int ic = 0; ic < nchunk; ic++){
        if (ic < nchunk-2) asm volatile("cp.async.wait_group 1;" ::: "memory");
        else               asm volatile("cp.async.wait_group 0;" ::: "memory");
        __syncthreads();
        uint32_t sa = smb + (uint32_t)(ic & 1)*STAGE_E*2;
        COMPUTE_TILE(sa + OFF_AH*2, sa + OFF_AL*2, sa + OFF_BH*2, sa + OFF_BL*2,
            {
                _Pragma("unroll")
                for (int mt = 0; mt < 2; mt++){
                    uint32_t ad = sa + (uint32_t)((mbase + mt*16 + (lane & 15))*A_LD
                                                  + kk*16 + (lane >> 4)*8)*2;
                    ldsm4(ah[mt], ad);
                    ldsm4(al[mt], ad + OFF_AL*2);
                }
            });
        __syncthreads();
        if (ic + 2 < nchunk)
            nn_load_chunk(smb, ic & 1, Ah, Al, Bh, Bl, m0, n0, (ic+2)*32, K, N, tid);
    }

    #pragma unroll
    for (int mt = 0; mt < 2; mt++){
        long r0 = m0 + mbase + mt*16 + (lane >> 2);
        #pragma unroll
        for (int n8 = 0; n8 < 8; n8++){
            int col = n0 + nbase + n8*8 + (lane & 3)*2;
            float* c = acc[mt][n8];
            float v00=c[0], v01=c[1], v10=c[2], v11=c[3];
            if (epi == 0){
                float b0 = auxp[col], b1 = auxp[col+1];
                v00+=b0; v01+=b1; v10+=b0; v11+=b1;
            } else if (epi == 1){
                v00=fabsf(v00); v01=fabsf(v01); v10=fabsf(v10); v11=fabsf(v11);
            } else {
                v00 = auxp[r0*N + col]     - v00;
                v01 = auxp[r0*N + col + 1] - v01;
                v10 = auxp[(r0+8)*N + col]     - v10;
                v11 = auxp[(r0+8)*N + col + 1] - v11;
            }
            if (Cf){
                float* base = Cf + (long)b*sC;
                *(float2*)(base + r0*N + col)     = make_float2(v00, v01);
                *(float2*)(base + (r0+8)*N + col) = make_float2(v10, v11);
            }
            if (Ch){
                bf16* bh = Ch + (long)b*sC;
                bf16* bl = Cl + (long)b*sC;
                st_split2(bh + r0*N + col,     bl + r0*N + col,     v00, v01);
                st_split2(bh + (r0+8)*N + col, bl + (r0+8)*N + col, v10, v11);
            }
        }
    }
}

// =================== TN HMMA split-K partials ================================
#define TN_AH 0
#define TN_AL 4352
#define TN_BH 8704
#define TN_BL 13056
#define TN_STAGE 17408
#define TN_SMEM (2*TN_STAGE*2)

__device__ __forceinline__ void tn_load_chunk(
    uint32_t smb, int stage,
    const bf16* __restrict__ Ah, const bf16* __restrict__ Al,
    const bf16* __restrict__ Bh, const bf16* __restrict__ Bl,
    long offA, long offB, int m0, int n0, int k0, int lda, int ldb, int tid)
{
    uint32_t base = smb + stage*TN_STAGE*2;
    #pragma unroll
    for (int q = 0; q < 2; q++){
        int qq = tid*2 + q;
        int brow = qq >> 4;
        int bcol = (qq & 15) * 8;
        long aidx = offA + (long)(k0+brow)*lda + m0 + bcol;
        uint32_t da = base + (uint32_t)(TN_AH + brow*B_LD + bcol)*2;
        cp16(da, Ah + aidx, 16);
        cp16(base + (uint32_t)(TN_AL + brow*B_LD + bcol)*2, Al + aidx, 16);
        long bidx = offB + (long)(k0+brow)*ldb + n0 + bcol;
        cp16(base + (uint32_t)(TN_BH + brow*B_LD + bcol)*2, Bh + bidx, 16);
        cp16(base + (uint32_t)(TN_BL + brow*B_LD + bcol)*2, Bl + bidx, 16);
    }
    asm volatile("cp.async.commit_group;" ::: "memory");
}

__global__ void __launch_bounds__(256, 2)
hgemm_tn(const bf16* __restrict__ Ah, const bf16* __restrict__ Al,
         const bf16* __restrict__ Bh, const bf16* __restrict__ Bl,
         float* __restrict__ P, int Mo, int No, int lda, int ldb, int Kc,
         long sA, long sB)
{
    extern __shared__ char smem[];
    uint32_t smb = smem_u32(smem);
    int tid = threadIdx.x;
    int wid = tid >> 5, lane = tid & 31;
    int b = blockIdx.z / NCH, s = blockIdx.z % NCH;
    long offA = (long)b*sA + (long)s*Kc*lda;
    long offB = (long)b*sB + (long)s*Kc*ldb;
    P += (long)(b*NCH + s)*Mo*No;
    int n0 = blockIdx.x * 128;
    int m0 = blockIdx.y * 128;

    int mbase = (wid & 3) * 32;
    int nbase = (wid >> 2) * 64;

    float acc[2][8][4];
    #pragma unroll
    for (int i=0;i<2;i++)
    #pragma unroll
        for (int j=0;j<8;j++)
        #pragma unroll
            for (int k=0;k<4;k++) acc[i][j][k]=0.f;

    int nchunk = Kc >> 5;
    tn_load_chunk(smb, 0, Ah, Al, Bh, Bl, offA, offB, m0, n0, 0,  lda, ldb, tid);
    tn_load_chunk(smb, 1, Ah, Al, Bh, Bl, offA, offB, m0, n0, 32, lda, ldb, tid);

    int krow = (lane & 7) + (lane >> 4)*8;
    int msub = ((lane >> 3) & 1)*8;

    for (int ic = 0; ic < nchunk; ic++){
        if (ic < nchunk-2) asm volatile("cp.async.wait_group 1;" ::: "memory");
        else               asm volatile("cp.async.wait_group 0;" ::: "memory");
        __syncthreads();
        uint32_t sa = smb + (uint32_t)(ic & 1)*TN_STAGE*2;
        COMPUTE_TILE(sa + TN_AH*2, sa + TN_AL*2, sa + TN_BH*2, sa + TN_BL*2,
            {
                _Pragma("unroll")
                for (int mt = 0; mt < 2; mt++){
                    uint32_t ad = sa + (uint32_t)(TN_AH + (kk*16 + krow)*B_LD
                                                  + mbase + mt*16 + msub)*2;
                    ldsm4t(ah[mt], ad);
                    ldsm4t(al[mt], ad + (TN_AL - TN_AH)*2);
                }
            });
        __syncthreads();
        if (ic + 2 < nchunk)
            tn_load_chunk(smb, ic & 1, Ah, Al, Bh, Bl, offA, offB, m0, n0, (ic+2)*32, lda, ldb, tid);
    }

    #pragma unroll
    for (int mt = 0; mt < 2; mt++){
        long r0 = m0 + mbase + mt*16 + (lane >> 2);
        #pragma unroll
        for (int n8 = 0; n8 < 8; n8++){
            int col = n0 + nbase + n8*8 + (lane & 3)*2;
            float* c = acc[mt][n8];
            *(float2*)(P + r0*No + col)     = make_float2(c[0], c[1]);
            *(float2*)(P + (r0+8)*No + col) = make_float2(c[2], c[3]);
        }
    }
}

// ---------------- small kernels ---------------------------------------------
__global__ void xmean_part(const float* __restrict__ x, float* __restrict__ xp){
    int b=blockIdx.x, s=blockIdx.y, tid=threadIdx.x;
    const float* p = x + ((long)b*Vn + s*(Vn/NCH))*CIN + tid;
    float acc=0.f;
    for (int i=0;i<Vn/NCH;i++) acc += p[(long)i*CIN];
    xp[(b*NCH+s)*CIN+tid]=acc;
}

__global__ void a_kernel(const float* __restrict__ xp, const float* __restrict__ w_a,
                         const float* __restrict__ b_a, float* __restrict__ a){
    __shared__ float xm[CIN];
    __shared__ float part[256];
    int b=blockIdx.x, tid=threadIdx.x;
    float acc=0.f;
    #pragma unroll
    for (int ch=0;ch<NCH;ch++) acc += xp[(b*NCH+ch)*CIN+tid];
    xm[tid] = acc * (1.0f/(float)Vn);
    __syncthreads();
    int f = tid & 127, half = tid >> 7;
    float s = 0.f;
    #pragma unroll 4
    for (int c = half*128; c < half*128 + 128; c++) s += xm[c]*w_a[c*Fn+f];
    part[tid] = s;
    __syncthreads();
    if (tid < Fn) a[b*Fn+tid] = part[tid] + part[tid+128] + b_a[tid];
}

__global__ void colsum_part(const float* __restrict__ Hm, float* __restrict__ cp){
    int b=blockIdx.x, s=blockIdx.y, tid=threadIdx.x;
    const float* p = Hm + ((long)b*Vn + s*(Vn/NCH))*En + tid;
    float acc=0.f;
    for (int i=0;i<Vn/NCH;i++) acc += p[(long)i*En];
    cp[(b*NCH+s)*En+tid]=acc;
}

__global__ void binv_kernel(const float* __restrict__ cp, float* __restrict__ binv){
    int b=blockIdx.x, tid=threadIdx.x;
    float s=0.f;
    #pragma unroll
    for (int ch=0;ch<NCH;ch++) s += cp[(b*NCH+ch)*En+tid];
    binv[b*En+tid] = 1.0f/s;
}

__global__ void rowscale_split(const float* __restrict__ H,
                               bf16* __restrict__ Hh, bf16* __restrict__ Hl){
    __shared__ float red[256];
    long row = blockIdx.x;
    int tid = threadIdx.x;
    const float* hr = H + row*En;
    float v = hr[tid];
    red[tid]=v; __syncthreads();
    for (int s=128;s>0;s>>=1){ if(tid<s) red[tid]+=red[tid+s]; __syncthreads(); }
    float o = v * rsqrtf(red[0]);
    bf16 h = __float2bfloat16_rn(o);
    Hh[row*En + tid] = h;
    Hl[row*En + tid] = __float2bfloat16_rn(o - __bfloat162float(h));
}

__global__ void reduce_scale_split(bf16* __restrict__ outh, bf16* __restrict__ outl,
                                   const float* __restrict__ part,
                                   const float* __restrict__ scale, int R, int C){
    long idx = (long)blockIdx.x*256 + threadIdx.x;
    int c = (int)(idx % C); long rc = idx / C; int r = (int)(rc % R); int b = (int)(rc / R);
    float s=0.f;
#pragma unroll
    for (int ch=0;ch<NCH;ch++) s += part[((long)(b*NCH+ch)*R + r)*C + c];
    float v = s * scale[b*R + r];
    bf16 h = __float2bfloat16_rn(v);
    outh[idx] = h;
    outl[idx] = __float2bfloat16_rn(v - __bfloat162float(h));
}

// ---------------- host launch ------------------------------------------------
extern "C" void kernel_launch(void* const* d_in, const int* in_sizes, int n_in,
                              void* d_out, int out_size){
    (void)in_sizes; (void)n_in; (void)out_size;
    const float* x    =(const float*)d_in[0];
    const float* wphi =(const float*)d_in[1];
    const float* bphi =(const float*)d_in[2];
    const float* wa   =(const float*)d_in[3];
    const float* ba   =(const float*)d_in[4];
    const float* wm   =(const float*)d_in[5];
    const float* bm   =(const float*)d_in[6];
    const float* w2   =(const float*)d_in[7];
    const float* b2   =(const float*)d_in[8];
    float* out=(float*)d_out;

    float *aV,*Hb,*binv,*p1,*p2,*xp,*cp;
    bf16 *xh,*xl,*phih,*phil,*Mh,*Ml,*Hh,*Hl,*yh,*yl,*th,*tl,*tmph,*tmpl;
    bf16 *wphih,*wphil,*w2h,*w2l;
    __half *x16h,*x16l,*w16;
    cudaGetSymbolAddress((void**)&aV  , g_a);
    cudaGetSymbolAddress((void**)&Hb  , g_H);
    cudaGetSymbolAddress((void**)&binv, g_Binv);
    cudaGetSymbolAddress((void**)&p1  , g_p1);
    cudaGetSymbolAddress((void**)&p2  , g_p2);
    cudaGetSymbolAddress((void**)&xp  , g_xp);
    cudaGetSymbolAddress((void**)&cp  , g_cp);
    cudaGetSymbolAddress((void**)&xh  , g_xh);
    cudaGetSymbolAddress((void**)&xl  , g_xl);
    cudaGetSymbolAddress((void**)&phih, g_phih);
    cudaGetSymbolAddress((void**)&phil, g_phil);
    cudaGetSymbolAddress((void**)&Mh  , g_Mh);
    cudaGetSymbolAddress((void**)&Ml  , g_Ml);
    cudaGetSymbolAddress((void**)&Hh  , g_Hh);
    cudaGetSymbolAddress((void**)&Hl  , g_Hl);
    cudaGetSymbolAddress((void**)&yh  , g_yh);
    cudaGetSymbolAddress((void**)&yl  , g_yl);
    cudaGetSymbolAddress((void**)&th  , g_th);
    cudaGetSymbolAddress((void**)&tl  , g_tl);
    cudaGetSymbolAddress((void**)&tmph, g_tmph);
    cudaGetSymbolAddress((void**)&tmpl, g_tmpl);
    cudaGetSymbolAddress((void**)&wphih, g_wphih);
    cudaGetSymbolAddress((void**)&wphil, g_wphil);
    cudaGetSymbolAddress((void**)&w2h , g_w2h);
    cudaGetSymbolAddress((void**)&w2l , g_w2l);
    cudaGetSymbolAddress((void**)&x16h, g_x16h);
    cudaGetSymbolAddress((void**)&x16l, g_x16l);
    cudaGetSymbolAddress((void**)&w16 , g_w16);

    cudaFuncSetAttribute(conv_mma, cudaFuncAttributeMaxDynamicSharedMemorySize, CONV_SMEM);
    cudaFuncSetAttribute(hgemm_nn, cudaFuncAttributeMaxDynamicSharedMemorySize, GEMM_SMEM);
    cudaFuncSetAttribute(hgemm_tn, cudaFuncAttributeMaxDynamicSharedMemorySize, TN_SMEM);

    // splits of inputs
    cvt_split<<<(Bn*Vn*CIN + 255)/256, 256>>>(x, xh, xl, (long)Bn*Vn*CIN);
    cvt_split_h<<<(Bn*Vn*CIN + 255)/256, 256>>>(x, x16h, x16l, (long)Bn*Vn*CIN);
    cvt_h<<<(49*CIN*En + 255)/256, 256>>>(wm, w16, (long)49*CIN*En);
    cvt_split<<<(CIN*Fn + 255)/256, 256>>>(wphi, wphih, wphil, (long)CIN*Fn);
    cvt_split<<<(CIN*En + 255)/256, 256>>>(w2, w2h, w2l, (long)CIN*En);

    // mean(x) -> a
    xmean_part<<<dim3(Bn,NCH),256>>>(x, xp);
    a_kernel<<<Bn,256>>>(xp, wa, ba, aV);

    // phi = x @ w_phi + b_phi -> split (M=32768, N=128, K=256)
    hgemm_nn<<<dim3(1,256,1),256,GEMM_SMEM>>>(xh, xl, wphih, wphil,
        (float*)0, phih, phil, bphi, Fn, CIN, 0,0,(long)0,0, 0);

    // M = conv7x7(x) + b_m -> split  (fp16 2-pass, CTA 128x256, warp 64x64)
    conv_mma<<<dim3(32, Bn), 256, CONV_SMEM>>>(x16h, x16l, w16, bm, Mh, Ml);

    // t = a * (phi^T @ M) -> split
    hgemm_tn<<<dim3(2,1,Bn*NCH),256,TN_SMEM>>>(phih, phil, Mh, Ml, p1,
        Fn, En, Fn, En, Vn/NCH, (long)Vn*Fn, (long)Vn*En);
    reduce_scale_split<<<(Bn*Fn*En)/256,256>>>(th, tl, p1, aV, Fn, En);

    // H = |phi @ t|  (fp32 out)
    hgemm_nn<<<dim3(2,32,Bn),256,GEMM_SMEM>>>(phih, phil, th, tl,
        Hb, (bf16*)0, (bf16*)0, (const float*)0, En, Fn,
        (long)Vn*Fn, (long)Fn*En, (long)Vn*En, 0, 1);

    // Binv from column sums of H
    colsum_part<<<dim3(Bn,NCH),256>>>(Hb, cp);
    binv_kernel<<<Bn,256>>>(cp, binv);

    // D_H = D^{-1/2} H -> split
    rowscale_split<<<Bn*Vn,256>>>(Hb, Hh, Hl);

    // tmp = Binv * (D_H^T @ x) -> split
    hgemm_tn<<<dim3(2,2,Bn*NCH),256,TN_SMEM>>>(Hh, Hl, xh, xl, p2,
        En, CIN, En, CIN, Vn/NCH, (long)Vn*En, (long)Vn*CIN);
    reduce_scale_split<<<(Bn*En*CIN)/256,256>>>(tmph, tmpl, p2, binv, En, CIN);

    // y = x - D_H @ tmp -> split
    hgemm_nn<<<dim3(2,32,Bn),256,GEMM_SMEM>>>(Hh, Hl, tmph, tmpl,
        (float*)0, yh, yl, x, CIN, En,
        (long)Vn*En, (long)En*CIN, (long)Vn*CIN, (long)Vn*CIN, 2);

    // out = y @ w2 + b2  (M=32768, N=256, K=256)
    hgemm_nn<<<dim3(2,256,1),256,GEMM_SMEM>>>(yh, yl, w2h, w2l,
        out, (bf16*)0, (bf16*)0, b2, En, CIN, 0,0,(long)0,0, 0);
}

// round 11
// speedup vs baseline: 4.8540x; 1.4528x over previous
#include <cuda_runtime.h>
#include <cuda_bf16.h>
#include <cuda_fp16.h>
#include <cstdint>

typedef unsigned long long u64;
typedef __nv_bfloat16 bf16;

#define Bn   8
#define Vn   4096
#define CIN  256
#define Fn   128
#define En   256
#define NCH  16

// ---------------- scratch (device globals) -----------------------------------
__device__ float g_a   [Bn*Fn];
__device__ float g_H   [Bn*Vn*En];
__device__ float g_Binv[Bn*En];
__device__ float g_p1  [Bn*NCH*Fn*En];
__device__ float g_p2  [Bn*NCH*En*CIN];
__device__ float g_xp  [Bn*NCH*CIN];
__device__ float g_cp  [Bn*NCH*En];
// bf16 split operand pairs (GEMM path)
__device__ bf16 g_xh [Bn*Vn*CIN];
__device__ bf16 g_xl [Bn*Vn*CIN];
__device__ bf16 g_phih[Bn*Vn*Fn];
__device__ bf16 g_phil[Bn*Vn*Fn];
__device__ bf16 g_Mh [Bn*Vn*En];
__device__ bf16 g_Ml [Bn*Vn*En];
__device__ bf16 g_Hh [Bn*Vn*En];
__device__ bf16 g_Hl [Bn*Vn*En];
__device__ bf16 g_yh [Bn*Vn*CIN];
__device__ bf16 g_yl [Bn*Vn*CIN];
__device__ bf16 g_th [Bn*Fn*En];
__device__ bf16 g_tl [Bn*Fn*En];
__device__ bf16 g_tmph[Bn*En*CIN];
__device__ bf16 g_tmpl[Bn*En*CIN];
__device__ bf16 g_wphih[CIN*Fn];
__device__ bf16 g_wphil[CIN*Fn];
__device__ bf16 g_w2h[CIN*En];
__device__ bf16 g_w2l[CIN*En];
// fp16 operands for the 1-pass conv
__device__ __half g_x16 [Bn*Vn*CIN];
__device__ __half g_w16 [49*CIN*En];

// =================== helpers =================================================
__global__ void cvt_split(const float* __restrict__ src, bf16* __restrict__ hi,
                          bf16* __restrict__ lo, long n){
    long i = (long)blockIdx.x*256 + threadIdx.x;
    if (i >= n) return;
    float v = src[i];
    bf16 h = __float2bfloat16_rn(v);
    hi[i] = h;
    lo[i] = __float2bfloat16_rn(v - __bfloat162float(h));
}
// fused: bf16 split + fp16 single convert of x
__global__ void cvt_x(const float* __restrict__ src, bf16* __restrict__ hi,
                      bf16* __restrict__ lo, __half* __restrict__ h16, long n){
    long i = (long)blockIdx.x*256 + threadIdx.x;
    if (i >= n) return;
    float v = src[i];
    bf16 h = __float2bfloat16_rn(v);
    hi[i] = h;
    lo[i] = __float2bfloat16_rn(v - __bfloat162float(h));
    h16[i] = __float2half_rn(v);
}
__global__ void cvt_h(const float* __restrict__ src, __half* __restrict__ dst, long n){
    long i = (long)blockIdx.x*256 + threadIdx.x;
    if (i >= n) return;
    dst[i] = __float2half_rn(src[i]);
}

__device__ __forceinline__ uint32_t smem_u32(const void* p) {
    uint32_t a;
    asm("{ .reg .u64 t; cvta.to.shared.u64 t, %1; cvt.u32.u64 %0, t; }" : "=r"(a) : "l"(p));
    return a;
}
__device__ __forceinline__ void cp16(uint32_t d, const void* s, int sz){
    asm volatile("cp.async.cg.shared.global [%0], [%1], 16, %2;"
                 :: "r"(d), "l"(s), "r"(sz) : "memory");
}
__device__ __forceinline__ void ldsm4(uint32_t* r, uint32_t a){
    asm volatile("ldmatrix.sync.aligned.m8n8.x4.shared.b16 {%0,%1,%2,%3}, [%4];"
                 : "=r"(r[0]),"=r"(r[1]),"=r"(r[2]),"=r"(r[3]) : "r"(a));
}
__device__ __forceinline__ void ldsm4t(uint32_t* r, uint32_t a){
    asm volatile("ldmatrix.sync.aligned.m8n8.x4.trans.shared.b16 {%0,%1,%2,%3}, [%4];"
                 : "=r"(r[0]),"=r"(r[1]),"=r"(r[2]),"=r"(r[3]) : "r"(a));
}
__device__ __forceinline__ void mma16816(float* c, const uint32_t* a, uint32_t b0, uint32_t b1){
    asm volatile("mma.sync.aligned.m16n8k16.row.col.f32.bf16.bf16.f32 "
                 "{%0,%1,%2,%3}, {%4,%5,%6,%7}, {%8,%9}, {%0,%1,%2,%3};"
                 : "+f"(c[0]),"+f"(c[1]),"+f"(c[2]),"+f"(c[3])
                 : "r"(a[0]),"r"(a[1]),"r"(a[2]),"r"(a[3]), "r"(b0),"r"(b1));
}
__device__ __forceinline__ void mma16816h(float* c, const uint32_t* a, uint32_t b0, uint32_t b1){
    asm volatile("mma.sync.aligned.m16n8k16.row.col.f32.f16.f16.f32 "
                 "{%0,%1,%2,%3}, {%4,%5,%6,%7}, {%8,%9}, {%0,%1,%2,%3};"
                 : "+f"(c[0]),"+f"(c[1]),"+f"(c[2]),"+f"(c[3])
                 : "r"(a[0]),"r"(a[1]),"r"(a[2]),"r"(a[3]), "r"(b0),"r"(b1));
}
__device__ __forceinline__ void st_split2(bf16* H, bf16* L, float v0, float v1){
    bf16 h0 = __float2bfloat16_rn(v0);
    bf16 h1 = __float2bfloat16_rn(v1);
    bf16 l0 = __float2bfloat16_rn(v0 - __bfloat162float(h0));
    bf16 l1 = __float2bfloat16_rn(v1 - __bfloat162float(h1));
    __nv_bfloat162 hp; hp.x = h0; hp.y = h1;
    __nv_bfloat162 lp; lp.x = l0; lp.y = l1;
    *(__nv_bfloat162*)H = hp;
    *(__nv_bfloat162*)L = lp;
}

// shared tile constants (128xN GEMM path)
#define A_LD   40
#define B_LD   136
#define OFF_AH 0
#define OFF_AL 5120
#define OFF_BH 10240
#define OFF_BL 14592
#define STAGE_E 18944
#define GEMM_SMEM (2*STAGE_E*2)

// inner 3-pass MMA block (NN + TN GEMMs, warp tile 32x64)
#define COMPUTE_TILE(sa_ah, sa_al, sa_bh, sa_bl, LOAD_A)                        \
    _Pragma("unroll")                                                           \
    for (int kk = 0; kk < 2; kk++){                                             \
        uint32_t ah[2][4], al[2][4];                                            \
        LOAD_A;                                                                 \
        _Pragma("unroll")                                                       \
        for (int nf = 0; nf < 4; nf++){                                         \
            uint32_t bh[4], bl[4];                                              \
            uint32_t bd = (sa_bh) + (uint32_t)((kk*16 + (lane & 15))*B_LD       \
                                          + nbase + nf*16 + (lane >> 4)*8)*2;   \
            ldsm4t(bh, bd);                                                     \
            ldsm4t(bl, bd + ((sa_bl)-(sa_bh)));                                 \
            _Pragma("unroll")                                                   \
            for (int mt = 0; mt < 2; mt++){                                     \
                float* c0 = acc[mt][nf*2];                                      \
                float* c1 = acc[mt][nf*2+1];                                    \
                mma16816(c0, ah[mt], bh[0], bh[1]);                             \
                mma16816(c1, ah[mt], bh[2], bh[3]);                             \
                mma16816(c0, ah[mt], bl[0], bl[1]);                             \
                mma16816(c1, ah[mt], bl[2], bl[3]);                             \
                mma16816(c0, al[mt], bh[0], bh[1]);                             \
                mma16816(c1, al[mt], bh[2], bh[3]);                             \
            }                                                                   \
        }                                                                       \
    }

// =================== conv: fp16 1-pass, CTA 128x256, warp 64x64, 4-stage =====
#define CB_LD   264                 // 256 + 8 pad (elems)
#define C_AH    0
#define C_BH    5120                // after A (128*40)
#define C_STAGE 13568               // elems per stage (A single + B single)
#define C_NSTG  4
#define CONV_SMEM (C_NSTG*C_STAGE*2)   // 108544 bytes
#define NCHUNK  392                 // 49 taps * 8 chunks of 32 ch

__device__ __forceinline__ void conv_load_chunk(
    uint32_t smb, int stage,
    const __half* __restrict__ x16, const __half* __restrict__ wf,
    long bV, int p0, int ic, int tid)
{
    int tap = ic >> 3, c0 = (ic & 7) * 32;
    int ky = tap / 7, kx = tap - ky*7;
    uint32_t base = smb + stage*C_STAGE*2;

    // ---- A: 128 pos-rows x 32 ch ----
    int row  = tid >> 1;
    int koff = (tid & 1) * 16;
    int pos = p0 + row;
    int hs = (pos >> 6) + ky - 3, ws = (pos & 63) + kx - 3;
    int sz = (((unsigned)hs < 64u) && ((unsigned)ws < 64u)) ? 16 : 0;
    long sidx = sz ? (bV + ((hs << 6) + ws)) * CIN + c0 + koff : 0;
    uint32_t da = base + (uint32_t)(C_AH + row*A_LD + koff)*2;
    cp16(da,      x16 + sidx,     sz);
    cp16(da + 16, x16 + sidx + 8, sz);

    // ---- B: 32 ch-rows x 256 E ----
    #pragma unroll
    for (int q = 0; q < 4; q++){
        int qq = tid + 256*q;               // 0..1023
        int brow = qq >> 5;                 // 0..31
        int bcol = (qq & 31) * 8;           // 0..248
        long widx = ((long)(tap*CIN + c0 + brow))*En + bcol;
        cp16(base + (uint32_t)(C_BH + brow*CB_LD + bcol)*2, wf + widx, 16);
    }
    asm volatile("cp.async.commit_group;" ::: "memory");
}

__global__ void __launch_bounds__(256, 1)
conv_mma(const __half* __restrict__ x16, const __half* __restrict__ wf,
         const float* __restrict__ bm, bf16* __restrict__ Mh, bf16* __restrict__ Ml)
{
    extern __shared__ char smem[];
    uint32_t smb = smem_u32(smem);
    int tid = threadIdx.x;
    int wid = tid >> 5, lane = tid & 31;
    int p0 = blockIdx.x * 128;
    int b  = blockIdx.y;
    long bV = (long)b * Vn;

    int mbase = (wid & 1) * 64;
    int nbase = (wid >> 1) * 64;

    float acc[4][8][4];
    #pragma unroll
    for (int i=0;i<4;i++)
    #pragma unroll
        for (int j=0;j<8;j++)
        #pragma unroll
            for (int k=0;k<4;k++) acc[i][j][k]=0.f;

    conv_load_chunk(smb, 0, x16, wf, bV, p0, 0, tid);
    conv_load_chunk(smb, 1, x16, wf, bV, p0, 1, tid);
    conv_load_chunk(smb, 2, x16, wf, bV, p0, 2, tid);

    int stage = 0;
    for (int ic = 0; ic < NCHUNK; ic++){
        if (ic < NCHUNK-3) asm volatile("cp.async.wait_group 2;" ::: "memory");
        else               asm volatile("cp.async.wait_group 0;" ::: "memory");
        __syncthreads();

        uint32_t sa = smb + (uint32_t)stage*C_STAGE*2;
        #pragma unroll
        for (int kk = 0; kk < 2; kk++){
            uint32_t ah[4][4];
            #pragma unroll
            for (int mt = 0; mt < 4; mt++){
                uint32_t ad = sa + (uint32_t)((mbase + mt*16 + (lane & 15))*A_LD
                                              + kk*16 + (lane >> 4)*8)*2;
                ldsm4(ah[mt], ad);
            }
            #pragma unroll
            for (int nf = 0; nf < 4; nf++){
                uint32_t bh[4];
                uint32_t bd = sa + (uint32_t)(C_BH + (kk*16 + (lane & 15))*CB_LD
                                              + nbase + nf*16 + (lane >> 4)*8)*2;
                ldsm4t(bh, bd);
                #pragma unroll
                for (int mt = 0; mt < 4; mt++){
                    mma16816h(acc[mt][nf*2],   ah[mt], bh[0], bh[1]);
                    mma16816h(acc[mt][nf*2+1], ah[mt], bh[2], bh[3]);
                }
            }
        }
        __syncthreads();
        if (ic + 3 < NCHUNK)
            conv_load_chunk(smb, (ic + 3) & 3, x16, wf, bV, p0, ic + 3, tid);
        stage = (stage + 1) & 3;
    }

    // epilogue: split-store 128x256 with bias
    #pragma unroll
    for (int mt = 0; mt < 4; mt++){
        long r0 = bV + p0 + mbase + mt*16 + (lane >> 2);
        #pragma unroll
        for (int n8 = 0; n8 < 8; n8++){
            int col = nbase + n8*8 + (lane & 3)*2;
            float b0 = bm[col], b1 = bm[col+1];
            float* c = acc[mt][n8];
            st_split2(Mh + r0*En + col,     Ml + r0*En + col,     c[0]+b0, c[1]+b1);
            st_split2(Mh + (r0+8)*En + col, Ml + (r0+8)*En + col, c[2]+b0, c[3]+b1);
        }
    }
}

// =================== generic NN HMMA GEMM (warp 32x64) =======================
__device__ __forceinline__ void nn_load_chunk(
    uint32_t smb, int stage,
    const bf16* __restrict__ Ah, const bf16* __restrict__ Al,
    const bf16* __restrict__ Bh, const bf16* __restrict__ Bl,
    int m0, int n0, int k0, int K, int N, int tid)
{
    uint32_t base = smb + stage*STAGE_E*2;
    int row  = tid >> 1;
    int koff = (tid & 1) * 16;
    long sidx = (long)(m0+row)*K + k0 + koff;
    uint32_t da = base + (uint32_t)(OFF_AH + row*A_LD + koff)*2;
    cp16(da,      Ah + sidx,     16);
    cp16(da + 16, Ah + sidx + 8, 16);
    uint32_t dal = base + (uint32_t)(OFF_AL + row*A_LD + koff)*2;
    cp16(dal,      Al + sidx,     16);
    cp16(dal + 16, Al + sidx + 8, 16);
    #pragma unroll
    for (int q = 0; q < 2; q++){
        int qq = tid*2 + q;
        int brow = qq >> 4;
        int bcol = (qq & 15) * 8;
        long widx = (long)(k0+brow)*N + n0 + bcol;
        uint32_t db = base + (uint32_t)(OFF_BH + brow*B_LD + bcol)*2;
        cp16(db, Bh + widx, 16);
        uint32_t dbl = base + (uint32_t)(OFF_BL + brow*B_LD + bcol)*2;
        cp16(dbl, Bl + widx, 16);
    }
    asm volatile("cp.async.commit_group;" ::: "memory");
}

__global__ void __launch_bounds__(256, 2)
hgemm_nn(const bf16* __restrict__ Ah, const bf16* __restrict__ Al,
         const bf16* __restrict__ Bh, const bf16* __restrict__ Bl,
         float* __restrict__ Cf, bf16* __restrict__ Ch, bf16* __restrict__ Cl,
         const float* __restrict__ aux,
         int N, int K, long sA, long sB, long sC, long sAux, int epi)
{
    extern __shared__ char smem[];
    uint32_t smb = smem_u32(smem);
    int tid = threadIdx.x;
    int wid = tid >> 5, lane = tid & 31;
    int n0 = blockIdx.x * 128;
    int m0 = blockIdx.y * 128;
    int b  = blockIdx.z;
    Ah += (long)b*sA; Al += (long)b*sA;
    Bh += (long)b*sB; Bl += (long)b*sB;
    const float* auxp = aux ? aux + (long)b*sAux : (const float*)0;

    int mbase = (wid & 3) * 32;
    int nbase = (wid >> 2) * 64;

    float acc[2][8][4];
    #pragma unroll
    for (int i=0;i<2;i++)
    #pragma unroll
        for (int j=0;j<8;j++)
        #pragma unroll
            for (int k=0;k<4;k++) acc[i][j][k]=0.f;

    int nchunk = K >> 5;
    nn_load_chunk(smb, 0, Ah, Al, Bh, Bl, m0, n0, 0,  K, N, tid);
    nn_load_chunk(smb, 1, Ah, Al, Bh, Bl, m0, n0, 32, K, N, tid);

    for (int ic = 0; ic < nchunk; ic++){
        if (ic < nchunk-2) asm volatile("cp.async.wait_group 1;" ::: "memory");
        else               asm volatile("cp.async.wait_group 0;" ::: "memory");
        __syncthreads();
        uint32_t sa = smb + (uint32_t)(ic & 1)*STAGE_E*2;
        COMPUTE_TILE(sa + OFF_AH*2, sa + OFF_AL*2, sa + OFF_BH*2, sa + OFF_BL*2,
            {
                _Pragma("unroll")
                for (int mt = 0; mt < 2; mt++){
                    uint32_t ad = sa + (uint32_t)((mbase + mt*16 + (lane & 15))*A_LD
                                                  + kk*16 + (lane >> 4)*8)*2;
                    ldsm4(ah[mt], ad);
                    ldsm4(al[mt], ad + OFF_AL*2);
                }
            });
        __syncthreads();
        if (ic + 2 < nchunk)
            nn_load_chunk(smb, ic & 1, Ah, Al, Bh, Bl, m0, n0, (ic+2)*32, K, N, tid);
    }

    #pragma unroll
    for (int mt = 0; mt < 2; mt++){
        long r0 = m0 + mbase + mt*16 + (lane >> 2);
        #pragma unroll
        for (int n8 = 0; n8 < 8; n8++){
            int col = n0 + nbase + n8*8 + (lane & 3)*2;
            float* c = acc[mt][n8];
            float v00=c[0], v01=c[1], v10=c[2], v11=c[3];
            if (epi == 0){
                float b0 = auxp[col], b1 = auxp[col+1];
                v00+=b0; v01+=b1; v10+=b0; v11+=b1;
            } else if (epi == 1){
                v00=fabsf(v00); v01=fabsf(v01); v10=fabsf(v10); v11=fabsf(v11);
            } else {
                v00 = auxp[r0*N + col]     - v00;
                v01 = auxp[r0*N + col + 1] - v01;
                v10 = auxp[(r0+8)*N + col]     - v10;
                v11 = auxp[(r0+8)*N + col + 1] - v11;
            }
            if (Cf){
                float* base = Cf + (long)b*sC;
                *(float2*)(base + r0*N + col)     = make_float2(v00, v01);
                *(float2*)(base + (r0+8)*N + col) = make_float2(v10, v11);
            }
            if (Ch){
                bf16* bh = Ch + (long)b*sC;
                bf16* bl = Cl + (long)b*sC;
                st_split2(bh + r0*N + col,     bl + r0*N + col,     v00, v01);
                st_split2(bh + (r0+8)*N + col, bl + (r0+8)*N + col, v10, v11);
            }
        }
    }
}

// =================== TN HMMA split-K partials ================================
#define TN_AH 0
#define TN_AL 4352
#define TN_BH 8704
#define TN_BL 13056
#define TN_STAGE 17408
#define TN_SMEM (2*TN_STAGE*2)

__device__ __forceinline__ void tn_load_chunk(
    uint32_t smb, int stage,
    const bf16* __restrict__ Ah, const bf16* __restrict__ Al,
    const bf16* __restrict__ Bh, const bf16* __restrict__ Bl,
    long offA, long offB, int m0, int n0, int k0, int lda, int ldb, int tid)
{
    uint32_t base = smb + stage*TN_STAGE*2;
    #pragma unroll
    for (int q = 0; q < 2; q++){
        int qq = tid*2 + q;
        int brow = qq >> 4;
        int bcol = (qq & 15) * 8;
        long aidx = offA + (long)(k0+brow)*lda + m0 + bcol;
        uint32_t da = base + (uint32_t)(TN_AH + brow*B_LD + bcol)*2;
        cp16(da, Ah + aidx, 16);
        cp16(base + (uint32_t)(TN_AL + brow*B_LD + bcol)*2, Al + aidx, 16);
        long bidx = offB + (long)(k0+brow)*ldb + n0 + bcol;
        cp16(base + (uint32_t)(TN_BH + brow*B_LD + bcol)*2, Bh + bidx, 16);
        cp16(base + (uint32_t)(TN_BL + brow*B_LD + bcol)*2, Bl + bidx, 16);
    }
    asm volatile("cp.async.commit_group;" ::: "memory");
}

__global__ void __launch_bounds__(256, 2)
hgemm_tn(const bf16* __restrict__ Ah, const bf16* __restrict__ Al,
         const bf16* __restrict__ Bh, const bf16* __restrict__ Bl,
         float* __restrict__ P, int Mo, int No, int lda, int ldb, int Kc,
         long sA, long sB)
{
    extern __shared__ char smem[];
    uint32_t smb = smem_u32(smem);
    int tid = threadIdx.x;
    int wid = tid >> 5, lane = tid & 31;
    int b = blockIdx.z / NCH, s = blockIdx.z % NCH;
    long offA = (long)b*sA + (long)s*Kc*lda;
    long offB = (long)b*sB + (long)s*Kc*ldb;
    P += (long)(b*NCH + s)*Mo*No;
    int n0 = blockIdx.x * 128;
    int m0 = blockIdx.y * 128;

    int mbase = (wid & 3) * 32;
    int nbase = (wid >> 2) * 64;

    float acc[2][8][4];
    #pragma unroll
    for (int i=0;i<2;i++)
    #pragma unroll
        for (int j=0;j<8;j++)
        #pragma unroll
            for (int k=0;k<4;k++) acc[i][j][k]=0.f;

    int nchunk = Kc >> 5;
    tn_load_chunk(smb, 0, Ah, Al, Bh, Bl, offA, offB, m0, n0, 0,  lda, ldb, tid);
    tn_load_chunk(smb, 1, Ah, Al, Bh, Bl, offA, offB, m0, n0, 32, lda, ldb, tid);

    int krow = (lane & 7) + (lane >> 4)*8;
    int msub = ((lane >> 3) & 1)*8;

    for (int ic = 0; ic < nchunk; ic++){
        if (ic < nchunk-2) asm volatile("cp.async.wait_group 1;" ::: "memory");
        else               asm volatile("cp.async.wait_group 0;" ::: "memory");
        __syncthreads();
        uint32_t sa = smb + (uint32_t)(ic & 1)*TN_STAGE*2;
        COMPUTE_TILE(sa + TN_AH*2, sa + TN_AL*2, sa + TN_BH*2, sa + TN_BL*2,
            {
                _Pragma("unroll")
                for (int mt = 0; mt < 2; mt++){
                    uint32_t ad = sa + (uint32_t)(TN_AH + (kk*16 + krow)*B_LD
                                                  + mbase + mt*16 + msub)*2;
                    ldsm4t(ah[mt], ad);
                    ldsm4t(al[mt], ad + (TN_AL - TN_AH)*2);
                }
            });
        __syncthreads();
        if (ic + 2 < nchunk)
            tn_load_chunk(smb, ic & 1, Ah, Al, Bh, Bl, offA, offB, m0, n0, (ic+2)*32, lda, ldb, tid);
    }

    #pragma unroll
    for (int mt = 0; mt < 2; mt++){
        long r0 = m0 + mbase + mt*16 + (lane >> 2);
        #pragma unroll
        for (int n8 = 0; n8 < 8; n8++){
            int col = n0 + nbase + n8*8 + (lane & 3)*2;
            float* c = acc[mt][n8];
            *(float2*)(P + r0*No + col)     = make_float2(c[0], c[1]);
            *(float2*)(P + (r0+8)*No + col) = make_float2(c[2], c[3]);
        }
    }
}

// ---------------- small kernels ---------------------------------------------
__global__ void xmean_part(const float* __restrict__ x, float* __restrict__ xp){
    int b=blockIdx.x, s=blockIdx.y, tid=threadIdx.x;
    const float* p = x + ((long)b*Vn + s*(Vn/NCH))*CIN + tid;
    float acc=0.f;
    for (int i=0;i<Vn/NCH;i++) acc += p[(long)i*CIN];
    xp[(b*NCH+s)*CIN+tid]=acc;
}

__global__ void a_kernel(const float* __restrict__ xp, const float* __restrict__ w_a,
                         const float* __restrict__ b_a, float* __restrict__ a){
    __shared__ float xm[CIN];
    __shared__ float part[256];
    int b=blockIdx.x, tid=threadIdx.x;
    float acc=0.f;
    #pragma unroll
    for (int ch=0;ch<NCH;ch++) acc += xp[(b*NCH+ch)*CIN+tid];
    xm[tid] = acc * (1.0f/(float)Vn);
    __syncthreads();
    int f = tid & 127, half = tid >> 7;
    float s = 0.f;
    #pragma unroll 4
    for (int c = half*128; c < half*128 + 128; c++) s += xm[c]*w_a[c*Fn+f];
    part[tid] = s;
    __syncthreads();
    if (tid < Fn) a[b*Fn+tid] = part[tid] + part[tid+128] + b_a[tid];
}

__global__ void colsum_part(const float* __restrict__ Hm, float* __restrict__ cp){
    int b=blockIdx.x, s=blockIdx.y, tid=threadIdx.x;
    const float* p = Hm + ((long)b*Vn + s*(Vn/NCH))*En + tid;
    float acc=0.f;
    for (int i=0;i<Vn/NCH;i++) acc += p[(long)i*En];
    cp[(b*NCH+s)*En+tid]=acc;
}

__global__ void binv_kernel(const float* __restrict__ cp, float* __restrict__ binv){
    int b=blockIdx.x, tid=threadIdx.x;
    float s=0.f;
    #pragma unroll
    for (int ch=0;ch<NCH;ch++) s += cp[(b*NCH+ch)*En+tid];
    binv[b*En+tid] = 1.0f/s;
}

__global__ void rowscale_split(const float* __restrict__ H,
                               bf16* __restrict__ Hh, bf16* __restrict__ Hl){
    __shared__ float red[256];
    long row = blockIdx.x;
    int tid = threadIdx.x;
    const float* hr = H + row*En;
    float v = hr[tid];
    red[tid]=v; __syncthreads();
    for (int s=128;s>0;s>>=1){ if(tid<s) red[tid]+=red[tid+s]; __syncthreads(); }
    float o = v * rsqrtf(red[0]);
    bf16 h = __float2bfloat16_rn(o);
    Hh[row*En + tid] = h;
    Hl[row*En + tid] = __float2bfloat16_rn(o - __bfloat162float(h));
}

__global__ void reduce_scale_split(bf16* __restrict__ outh, bf16* __restrict__ outl,
                                   const float* __restrict__ part,
                                   const float* __restrict__ scale, int R, int C){
    long idx = (long)blockIdx.x*256 + threadIdx.x;
    int c = (int)(idx % C); long rc = idx / C; int r = (int)(rc % R); int b = (int)(rc / R);
    float s=0.f;
#pragma unroll
    for (int ch=0;ch<NCH;ch++) s += part[((long)(b*NCH+ch)*R + r)*C + c];
    float v = s * scale[b*R + r];
    bf16 h = __float2bfloat16_rn(v);
    outh[idx] = h;
    outl[idx] = __float2bfloat16_rn(v - __bfloat162float(h));
}

// ---------------- host launch ------------------------------------------------
extern "C" void kernel_launch(void* const* d_in, const int* in_sizes, int n_in,
                              void* d_out, int out_size){
    (void)in_sizes; (void)n_in; (void)out_size;
    const float* x    =(const float*)d_in[0];
    const float* wphi =(const float*)d_in[1];
    const float* bphi =(const float*)d_in[2];
    const float* wa   =(const float*)d_in[3];
    const float* ba   =(const float*)d_in[4];
    const float* wm   =(const float*)d_in[5];
    const float* bm   =(const float*)d_in[6];
    const float* w2   =(const float*)d_in[7];
    const float* b2   =(const float*)d_in[8];
    float* out=(float*)d_out;

    float *aV,*Hb,*binv,*p1,*p2,*xp,*cp;
    bf16 *xh,*xl,*phih,*phil,*Mh,*Ml,*Hh,*Hl,*yh,*yl,*th,*tl,*tmph,*tmpl;
    bf16 *wphih,*wphil,*w2h,*w2l;
    __half *x16,*w16;
    cudaGetSymbolAddress((void**)&aV  , g_a);
    cudaGetSymbolAddress((void**)&Hb  , g_H);
    cudaGetSymbolAddress((void**)&binv, g_Binv);
    cudaGetSymbolAddress((void**)&p1  , g_p1);
    cudaGetSymbolAddress((void**)&p2  , g_p2);
    cudaGetSymbolAddress((void**)&xp  , g_xp);
    cudaGetSymbolAddress((void**)&cp  , g_cp);
    cudaGetSymbolAddress((void**)&xh  , g_xh);
    cudaGetSymbolAddress((void**)&xl  , g_xl);
    cudaGetSymbolAddress((void**)&phih, g_phih);
    cudaGetSymbolAddress((void**)&phil, g_phil);
    cudaGetSymbolAddress((void**)&Mh  , g_Mh);
    cudaGetSymbolAddress((void**)&Ml  , g_Ml);
    cudaGetSymbolAddress((void**)&Hh  , g_Hh);
    cudaGetSymbolAddress((void**)&Hl  , g_Hl);
    cudaGetSymbolAddress((void**)&yh  , g_yh);
    cudaGetSymbolAddress((void**)&yl  , g_yl);
    cudaGetSymbolAddress((void**)&th  , g_th);
    cudaGetSymbolAddress((void**)&tl  , g_tl);
    cudaGetSymbolAddress((void**)&tmph, g_tmph);
    cudaGetSymbolAddress((void**)&tmpl, g_tmpl);
    cudaGetSymbolAddress((void**)&wphih, g_wphih);
    cudaGetSymbolAddress((void**)&wphil, g_wphil);
    cudaGetSymbolAddress((void**)&w2h , g_w2h);
    cudaGetSymbolAddress((void**)&w2l , g_w2l);
    cudaGetSymbolAddress((void**)&x16 , g_x16);
    cudaGetSymbolAddress((void**)&w16 , g_w16);

    cudaFuncSetAttribute(conv_mma, cudaFuncAttributeMaxDynamicSharedMemorySize, CONV_SMEM);
    cudaFuncSetAttribute(hgemm_nn, cudaFuncAttributeMaxDynamicSharedMemorySize, GEMM_SMEM);
    cudaFuncSetAttribute(hgemm_tn, cudaFuncAttributeMaxDynamicSharedMemorySize, TN_SMEM);

    // splits / converts of inputs
    cvt_x<<<(Bn*Vn*CIN + 255)/256, 256>>>(x, xh, xl, x16, (long)Bn*Vn*CIN);
    cvt_h<<<(49*CIN*En + 255)/256, 256>>>(wm, w16, (long)49*CIN*En);
    cvt_split<<<(CIN*Fn + 255)/256, 256>>>(wphi, wphih, wphil, (long)CIN*Fn);
    cvt_split<<<(CIN*En + 255)/256, 256>>>(w2, w2h, w2l, (long)CIN*En);

    // mean(x) -> a
    xmean_part<<<dim3(Bn,NCH),256>>>(x, xp);
    a_kernel<<<Bn,256>>>(xp, wa, ba, aV);

    // phi = x @ w_phi + b_phi -> split (M=32768, N=128, K=256)
    hgemm_nn<<<dim3(1,256,1),256,GEMM_SMEM>>>(xh, xl, wphih, wphil,
        (float*)0, phih, phil, bphi, Fn, CIN, 0,0,(long)0,0, 0);

    // M = conv7x7(x) + b_m -> split  (fp16 1-pass, CTA 128x256, warp 64x64)
    conv_mma<<<dim3(32, Bn), 256, CONV_SMEM>>>(x16, w16, bm, Mh, Ml);

    // t = a * (phi^T @ M) -> split
    hgemm_tn<<<dim3(2,1,Bn*NCH),256,TN_SMEM>>>(phih, phil, Mh, Ml, p1,
        Fn, En, Fn, En, Vn/NCH, (long)Vn*Fn, (long)Vn*En);
    reduce_scale_split<<<(Bn*Fn*En)/256,256>>>(th, tl, p1, aV, Fn, En);

    // H = |phi @ t|  (fp32 out)
    hgemm_nn<<<dim3(2,32,Bn),256,GEMM_SMEM>>>(phih, phil, th, tl,
        Hb, (bf16*)0, (bf16*)0, (const float*)0, En, Fn,
        (long)Vn*Fn, (long)Fn*En, (long)Vn*En, 0, 1);

    // Binv from column sums of H
    colsum_part<<<dim3(Bn,NCH),256>>>(Hb, cp);
    binv_kernel<<<Bn,256>>>(cp, binv);

    // D_H = D^{-1/2} H -> split
    rowscale_split<<<Bn*Vn,256>>>(Hb, Hh, Hl);

    // tmp = Binv * (D_H^T @ x) -> split
    hgemm_tn<<<dim3(2,2,Bn*NCH),256,TN_SMEM>>>(Hh, Hl, xh, xl, p2,
        En, CIN, En, CIN, Vn/NCH, (long)Vn*En, (long)Vn*CIN);
    reduce_scale_split<<<(Bn*En*CIN)/256,256>>>(tmph, tmpl, p2, binv, En, CIN);

    // y = x - D_H @ tmp -> split
    hgemm_nn<<<dim3(2,32,Bn),256,GEMM_SMEM>>>(Hh, Hl, tmph, tmpl,
        (float*)0, yh, yl, x, CIN, En,
        (long)Vn*En, (long)En*CIN, (long)Vn*CIN, (long)Vn*CIN, 2);

    // out = y @ w2 + b2  (M=32768, N=256, K=256)
    hgemm_nn<<<dim3(2,256,1),256,GEMM_SMEM>>>(yh, yl, w2h, w2l,
        out, (bf16*)0, (bf16*)0, b2, En, CIN, 0,0,(long)0,0, 0);
}

// round 12
// speedup vs baseline: 5.2685x; 1.0854x over previous
#include <cuda_runtime.h>
#include <cuda_bf16.h>
#include <cuda_fp16.h>
#include <cstdint>

typedef __half h16;

#define Bn   8
#define Vn   4096
#define CIN  256
#define Fn   128
#define En   256
#define NCH  16

// ---------------- scratch (device globals) -----------------------------------
__device__ float g_a   [Bn*Fn];
__device__ float g_H   [Bn*Vn*En];
__device__ float g_Binv[Bn*En];
__device__ float g_p1  [Bn*NCH*Fn*En];
__device__ float g_p2  [Bn*NCH*En*CIN];
__device__ float g_xp  [Bn*NCH*CIN];
__device__ float g_cp  [Bn*NCH*En];
// fp16 operands
__device__ h16 g_x16 [Bn*Vn*CIN];
__device__ h16 g_w16 [49*CIN*En];
__device__ h16 g_wphi16[CIN*Fn];
__device__ h16 g_w216[CIN*En];
__device__ h16 g_phi16[Bn*Vn*Fn];
__device__ h16 g_M16 [Bn*Vn*En];
__device__ h16 g_H16 [Bn*Vn*En];
__device__ h16 g_t16 [Bn*Fn*En];
__device__ h16 g_tmp16[Bn*En*CIN];
__device__ h16 g_yh  [Bn*Vn*CIN];
__device__ h16 g_yl  [Bn*Vn*CIN];

// =================== helpers =================================================
__global__ void cvt_h(const float* __restrict__ src, h16* __restrict__ dst, long n){
    long i = (long)blockIdx.x*256 + threadIdx.x;
    if (i >= n) return;
    dst[i] = __float2half_rn(src[i]);
}

__device__ __forceinline__ uint32_t smem_u32(const void* p) {
    uint32_t a;
    asm("{ .reg .u64 t; cvta.to.shared.u64 t, %1; cvt.u32.u64 %0, t; }" : "=r"(a) : "l"(p));
    return a;
}
__device__ __forceinline__ void cp16(uint32_t d, const void* s, int sz){
    asm volatile("cp.async.cg.shared.global [%0], [%1], 16, %2;"
                 :: "r"(d), "l"(s), "r"(sz) : "memory");
}
__device__ __forceinline__ void ldsm4(uint32_t* r, uint32_t a){
    asm volatile("ldmatrix.sync.aligned.m8n8.x4.shared.b16 {%0,%1,%2,%3}, [%4];"
                 : "=r"(r[0]),"=r"(r[1]),"=r"(r[2]),"=r"(r[3]) : "r"(a));
}
__device__ __forceinline__ void ldsm4t(uint32_t* r, uint32_t a){
    asm volatile("ldmatrix.sync.aligned.m8n8.x4.trans.shared.b16 {%0,%1,%2,%3}, [%4];"
                 : "=r"(r[0]),"=r"(r[1]),"=r"(r[2]),"=r"(r[3]) : "r"(a));
}
__device__ __forceinline__ void mma16816h(float* c, const uint32_t* a, uint32_t b0, uint32_t b1){
    asm volatile("mma.sync.aligned.m16n8k16.row.col.f32.f16.f16.f32 "
                 "{%0,%1,%2,%3}, {%4,%5,%6,%7}, {%8,%9}, {%0,%1,%2,%3};"
                 : "+f"(c[0]),"+f"(c[1]),"+f"(c[2]),"+f"(c[3])
                 : "r"(a[0]),"r"(a[1]),"r"(a[2]),"r"(a[3]), "r"(b0),"r"(b1));
}
__device__ __forceinline__ void st2h(h16* D, float v0, float v1){
    __half2 p; p.x = __float2half_rn(v0); p.y = __float2half_rn(v1);
    *(__half2*)D = p;
}
__device__ __forceinline__ void st_split2h(h16* H, h16* L, float v0, float v1){
    h16 h0 = __float2half_rn(v0);
    h16 h1 = __float2half_rn(v1);
    __half2 hp; hp.x = h0; hp.y = h1;
    __half2 lp; lp.x = __float2half_rn(v0 - __half2float(h0));
    lp.y = __float2half_rn(v1 - __half2float(h1));
    *(__half2*)H = hp;
    *(__half2*)L = lp;
}

// =================== conv: fp16 1-pass (UNCHANGED core) ======================
#define A_LD    40
#define B_LD    136
#define CB_LD   264
#define C_AH    0
#define C_BH    5120
#define C_STAGE 13568
#define C_NSTG  4
#define CONV_SMEM (C_NSTG*C_STAGE*2)
#define NCHUNK  392

__device__ __forceinline__ void conv_load_chunk(
    uint32_t smb, int stage,
    const h16* __restrict__ x16, const h16* __restrict__ wf,
    long bV, int p0, int ic, int tid)
{
    int tap = ic >> 3, c0 = (ic & 7) * 32;
    int ky = tap / 7, kx = tap - ky*7;
    uint32_t base = smb + stage*C_STAGE*2;

    int row  = tid >> 1;
    int koff = (tid & 1) * 16;
    int pos = p0 + row;
    int hs = (pos >> 6) + ky - 3, ws = (pos & 63) + kx - 3;
    int sz = (((unsigned)hs < 64u) && ((unsigned)ws < 64u)) ? 16 : 0;
    long sidx = sz ? (bV + ((hs << 6) + ws)) * CIN + c0 + koff : 0;
    uint32_t da = base + (uint32_t)(C_AH + row*A_LD + koff)*2;
    cp16(da,      x16 + sidx,     sz);
    cp16(da + 16, x16 + sidx + 8, sz);

    #pragma unroll
    for (int q = 0; q < 4; q++){
        int qq = tid + 256*q;
        int brow = qq >> 5;
        int bcol = (qq & 31) * 8;
        long widx = ((long)(tap*CIN + c0 + brow))*En + bcol;
        cp16(base + (uint32_t)(C_BH + brow*CB_LD + bcol)*2, wf + widx, 16);
    }
    asm volatile("cp.async.commit_group;" ::: "memory");
}

__global__ void __launch_bounds__(256, 1)
conv_mma(const h16* __restrict__ x16, const h16* __restrict__ wf,
         const float* __restrict__ bm, h16* __restrict__ M16)
{
    extern __shared__ char smem[];
    uint32_t smb = smem_u32(smem);
    int tid = threadIdx.x;
    int wid = tid >> 5, lane = tid & 31;
    int p0 = blockIdx.x * 128;
    int b  = blockIdx.y;
    long bV = (long)b * Vn;

    int mbase = (wid & 1) * 64;
    int nbase = (wid >> 1) * 64;

    float acc[4][8][4];
    #pragma unroll
    for (int i=0;i<4;i++)
    #pragma unroll
        for (int j=0;j<8;j++)
        #pragma unroll
            for (int k=0;k<4;k++) acc[i][j][k]=0.f;

    conv_load_chunk(smb, 0, x16, wf, bV, p0, 0, tid);
    conv_load_chunk(smb, 1, x16, wf, bV, p0, 1, tid);
    conv_load_chunk(smb, 2, x16, wf, bV, p0, 2, tid);

    int stage = 0;
    for (int ic = 0; ic < NCHUNK; ic++){
        if (ic < NCHUNK-3) asm volatile("cp.async.wait_group 2;" ::: "memory");
        else               asm volatile("cp.async.wait_group 0;" ::: "memory");
        __syncthreads();

        uint32_t sa = smb + (uint32_t)stage*C_STAGE*2;
        #pragma unroll
        for (int kk = 0; kk < 2; kk++){
            uint32_t ah[4][4];
            #pragma unroll
            for (int mt = 0; mt < 4; mt++){
                uint32_t ad = sa + (uint32_t)((mbase + mt*16 + (lane & 15))*A_LD
                                              + kk*16 + (lane >> 4)*8)*2;
                ldsm4(ah[mt], ad);
            }
            #pragma unroll
            for (int nf = 0; nf < 4; nf++){
                uint32_t bh[4];
                uint32_t bd = sa + (uint32_t)(C_BH + (kk*16 + (lane & 15))*CB_LD
                                              + nbase + nf*16 + (lane >> 4)*8)*2;
                ldsm4t(bh, bd);
                #pragma unroll
                for (int mt = 0; mt < 4; mt++){
                    mma16816h(acc[mt][nf*2],   ah[mt], bh[0], bh[1]);
                    mma16816h(acc[mt][nf*2+1], ah[mt], bh[2], bh[3]);
                }
            }
        }
        __syncthreads();
        if (ic + 3 < NCHUNK)
            conv_load_chunk(smb, (ic + 3) & 3, x16, wf, bV, p0, ic + 3, tid);
        stage = (stage + 1) & 3;
    }

    // epilogue: single fp16 store with bias
    #pragma unroll
    for (int mt = 0; mt < 4; mt++){
        long r0 = bV + p0 + mbase + mt*16 + (lane >> 2);
        #pragma unroll
        for (int n8 = 0; n8 < 8; n8++){
            int col = nbase + n8*8 + (lane & 3)*2;
            float b0 = bm[col], b1 = bm[col+1];
            float* c = acc[mt][n8];
            st2h(M16 + r0*En + col,     c[0]+b0, c[1]+b1);
            st2h(M16 + (r0+8)*En + col, c[2]+b0, c[3]+b1);
        }
    }
}

// =================== NN fp16 GEMM (1- or 2-pass A) ===========================
#define OFF_A  0
#define OFF_AL 5120
#define OFF_B  10240
#define STAGE_E 14592
#define GEMM_SMEM (2*STAGE_E*2)

template<int PASSES>
__device__ __forceinline__ void nn_load_chunk(
    uint32_t smb, int stage,
    const h16* __restrict__ Ah, const h16* __restrict__ Al,
    const h16* __restrict__ Bs,
    int m0, int n0, int k0, int K, int N, int tid)
{
    uint32_t base = smb + stage*STAGE_E*2;
    int row  = tid >> 1;
    int koff = (tid & 1) * 16;
    long sidx = (long)(m0+row)*K + k0 + koff;
    uint32_t da = base + (uint32_t)(OFF_A + row*A_LD + koff)*2;
    cp16(da,      Ah + sidx,     16);
    cp16(da + 16, Ah + sidx + 8, 16);
    if (PASSES == 2){
        uint32_t dal = base + (uint32_t)(OFF_AL + row*A_LD + koff)*2;
        cp16(dal,      Al + sidx,     16);
        cp16(dal + 16, Al + sidx + 8, 16);
    }
    #pragma unroll
    for (int q = 0; q < 2; q++){
        int qq = tid*2 + q;
        int brow = qq >> 4;
        int bcol = (qq & 15) * 8;
        long widx = (long)(k0+brow)*N + n0 + bcol;
        cp16(base + (uint32_t)(OFF_B + brow*B_LD + bcol)*2, Bs + widx, 16);
    }
    asm volatile("cp.async.commit_group;" ::: "memory");
}

template<int PASSES>
__global__ void __launch_bounds__(256, 2)
hgemm_nn(const h16* __restrict__ Ah, const h16* __restrict__ Al,
         const h16* __restrict__ Bs,
         float* __restrict__ Cf, h16* __restrict__ Ch, h16* __restrict__ Cl,
         const float* __restrict__ aux,
         int N, int K, long sA, long sB, long sC, long sAux, int epi)
{
    extern __shared__ char smem[];
    uint32_t smb = smem_u32(smem);
    int tid = threadIdx.x;
    int wid = tid >> 5, lane = tid & 31;
    int n0 = blockIdx.x * 128;
    int m0 = blockIdx.y * 128;
    int b  = blockIdx.z;
    Ah += (long)b*sA; if (PASSES == 2) Al += (long)b*sA;
    Bs += (long)b*sB;
    const float* auxp = aux ? aux + (long)b*sAux : (const float*)0;

    int mbase = (wid & 3) * 32;
    int nbase = (wid >> 2) * 64;

    float acc[2][8][4];
    #pragma unroll
    for (int i=0;i<2;i++)
    #pragma unroll
        for (int j=0;j<8;j++)
        #pragma unroll
            for (int k=0;k<4;k++) acc[i][j][k]=0.f;

    int nchunk = K >> 5;
    nn_load_chunk<PASSES>(smb, 0, Ah, Al, Bs, m0, n0, 0,  K, N, tid);
    nn_load_chunk<PASSES>(smb, 1, Ah, Al, Bs, m0, n0, 32, K, N, tid);

    for (int ic = 0; ic < nchunk; ic++){
        if (ic < nchunk-2) asm volatile("cp.async.wait_group 1;" ::: "memory");
        else               asm volatile("cp.async.wait_group 0;" ::: "memory");
        __syncthreads();
        uint32_t sa = smb + (uint32_t)(ic & 1)*STAGE_E*2;
        #pragma unroll
        for (int kk = 0; kk < 2; kk++){
            uint32_t ah[2][4], al[2][4];
            #pragma unroll
            for (int mt = 0; mt < 2; mt++){
                uint32_t ad = sa + (uint32_t)((mbase + mt*16 + (lane & 15))*A_LD
                                              + kk*16 + (lane >> 4)*8)*2;
                ldsm4(ah[mt], ad);
                if (PASSES == 2) ldsm4(al[mt], ad + OFF_AL*2);
            }
            #pragma unroll
            for (int nf = 0; nf < 4; nf++){
                uint32_t bh[4];
                uint32_t bd = sa + (uint32_t)(OFF_B + (kk*16 + (lane & 15))*B_LD
                                              + nbase + nf*16 + (lane >> 4)*8)*2;
                ldsm4t(bh, bd);
                #pragma unroll
                for (int mt = 0; mt < 2; mt++){
                    mma16816h(acc[mt][nf*2],   ah[mt], bh[0], bh[1]);
                    mma16816h(acc[mt][nf*2+1], ah[mt], bh[2], bh[3]);
                    if (PASSES == 2){
                        mma16816h(acc[mt][nf*2],   al[mt], bh[0], bh[1]);
                        mma16816h(acc[mt][nf*2+1], al[mt], bh[2], bh[3]);
                    }
                }
            }
        }
        __syncthreads();
        if (ic + 2 < nchunk)
            nn_load_chunk<PASSES>(smb, ic & 1, Ah, Al, Bs, m0, n0, (ic+2)*32, K, N, tid);
    }

    #pragma unroll
    for (int mt = 0; mt < 2; mt++){
        long r0 = m0 + mbase + mt*16 + (lane >> 2);
        #pragma unroll
        for (int n8 = 0; n8 < 8; n8++){
            int col = n0 + nbase + n8*8 + (lane & 3)*2;
            float* c = acc[mt][n8];
            float v00=c[0], v01=c[1], v10=c[2], v11=c[3];
            if (epi == 0){
                float b0 = auxp[col], b1 = auxp[col+1];
                v00+=b0; v01+=b1; v10+=b0; v11+=b1;
            } else if (epi == 1){
                v00=fabsf(v00); v01=fabsf(v01); v10=fabsf(v10); v11=fabsf(v11);
            } else {
                v00 = auxp[r0*N + col]     - v00;
                v01 = auxp[r0*N + col + 1] - v01;
                v10 = auxp[(r0+8)*N + col]     - v10;
                v11 = auxp[(r0+8)*N + col + 1] - v11;
            }
            if (Cf){
                float* base = Cf + (long)b*sC;
                *(float2*)(base + r0*N + col)     = make_float2(v00, v01);
                *(float2*)(base + (r0+8)*N + col) = make_float2(v10, v11);
            }
            if (Ch && Cl){
                h16* bh = Ch + (long)b*sC;
                h16* bl = Cl + (long)b*sC;
                st_split2h(bh + r0*N + col,     bl + r0*N + col,     v00, v01);
                st_split2h(bh + (r0+8)*N + col, bl + (r0+8)*N + col, v10, v11);
            } else if (Ch){
                h16* bh = Ch + (long)b*sC;
                st2h(bh + r0*N + col,     v00, v01);
                st2h(bh + (r0+8)*N + col, v10, v11);
            }
        }
    }
}

// =================== TN fp16 1-pass split-K partials =========================
#define TN_A    0
#define TN_B    4352
#define TN_STAGE 8704
#define TN_SMEM (2*TN_STAGE*2)

__device__ __forceinline__ void tn_load_chunk(
    uint32_t smb, int stage,
    const h16* __restrict__ Ah, const h16* __restrict__ Bs,
    long offA, long offB, int m0, int n0, int k0, int lda, int ldb, int tid)
{
    uint32_t base = smb + stage*TN_STAGE*2;
    #pragma unroll
    for (int q = 0; q < 2; q++){
        int qq = tid*2 + q;
        int brow = qq >> 4;
        int bcol = (qq & 15) * 8;
        long aidx = offA + (long)(k0+brow)*lda + m0 + bcol;
        cp16(base + (uint32_t)(TN_A + brow*B_LD + bcol)*2, Ah + aidx, 16);
        long bidx = offB + (long)(k0+brow)*ldb + n0 + bcol;
        cp16(base + (uint32_t)(TN_B + brow*B_LD + bcol)*2, Bs + bidx, 16);
    }
    asm volatile("cp.async.commit_group;" ::: "memory");
}

__global__ void __launch_bounds__(256, 2)
hgemm_tn(const h16* __restrict__ Ah, const h16* __restrict__ Bs,
         float* __restrict__ P, int Mo, int No, int lda, int ldb, int Kc,
         long sA, long sB)
{
    extern __shared__ char smem[];
    uint32_t smb = smem_u32(smem);
    int tid = threadIdx.x;
    int wid = tid >> 5, lane = tid & 31;
    int b = blockIdx.z / NCH, s = blockIdx.z % NCH;
    long offA = (long)b*sA + (long)s*Kc*lda;
    long offB = (long)b*sB + (long)s*Kc*ldb;
    P += (long)(b*NCH + s)*Mo*No;
    int n0 = blockIdx.x * 128;
    int m0 = blockIdx.y * 128;

    int mbase = (wid & 3) * 32;
    int nbase = (wid >> 2) * 64;

    float acc[2][8][4];
    #pragma unroll
    for (int i=0;i<2;i++)
    #pragma unroll
        for (int j=0;j<8;j++)
        #pragma unroll
            for (int k=0;k<4;k++) acc[i][j][k]=0.f;

    int nchunk = Kc >> 5;
    tn_load_chunk(smb, 0, Ah, Bs, offA, offB, m0, n0, 0,  lda, ldb, tid);
    tn_load_chunk(smb, 1, Ah, Bs, offA, offB, m0, n0, 32, lda, ldb, tid);

    int krow = (lane & 7) + (lane >> 4)*8;
    int msub = ((lane >> 3) & 1)*8;

    for (int ic = 0; ic < nchunk; ic++){
        if (ic < nchunk-2) asm volatile("cp.async.wait_group 1;" ::: "memory");
        else               asm volatile("cp.async.wait_group 0;" ::: "memory");
        __syncthreads();
        uint32_t sa = smb + (uint32_t)(ic & 1)*TN_STAGE*2;
        #pragma unroll
        for (int kk = 0; kk < 2; kk++){
            uint32_t ah[2][4];
            #pragma unroll
            for (int mt = 0; mt < 2; mt++){
                uint32_t ad = sa + (uint32_t)(TN_A + (kk*16 + krow)*B_LD
                                              + mbase + mt*16 + msub)*2;
                ldsm4t(ah[mt], ad);
            }
            #pragma unroll
            for (int nf = 0; nf < 4; nf++){
                uint32_t bh[4];
                uint32_t bd = sa + (uint32_t)(TN_B + (kk*16 + (lane & 15))*B_LD
                                              + nbase + nf*16 + (lane >> 4)*8)*2;
                ldsm4t(bh, bd);
                #pragma unroll
                for (int mt = 0; mt < 2; mt++){
                    mma16816h(acc[mt][nf*2],   ah[mt], bh[0], bh[1]);
                    mma16816h(acc[mt][nf*2+1], ah[mt], bh[2], bh[3]);
                }
            }
        }
        __syncthreads();
        if (ic + 2 < nchunk)
            tn_load_chunk(smb, ic & 1, Ah, Bs, offA, offB, m0, n0, (ic+2)*32, lda, ldb, tid);
    }

    #pragma unroll
    for (int mt = 0; mt < 2; mt++){
        long r0 = m0 + mbase + mt*16 + (lane >> 2);
        #pragma unroll
        for (int n8 = 0; n8 < 8; n8++){
            int col = n0 + nbase + n8*8 + (lane & 3)*2;
            float* c = acc[mt][n8];
            *(float2*)(P + r0*No + col)     = make_float2(c[0], c[1]);
            *(float2*)(P + (r0+8)*No + col) = make_float2(c[2], c[3]);
        }
    }
}

// ---------------- small kernels ---------------------------------------------
__global__ void xmean_part(const float* __restrict__ x, float* __restrict__ xp){
    int b=blockIdx.x, s=blockIdx.y, tid=threadIdx.x;
    const float* p = x + ((long)b*Vn + s*(Vn/NCH))*CIN + tid;
    float acc=0.f;
    for (int i=0;i<Vn/NCH;i++) acc += p[(long)i*CIN];
    xp[(b*NCH+s)*CIN+tid]=acc;
}

__global__ void a_kernel(const float* __restrict__ xp, const float* __restrict__ w_a,
                         const float* __restrict__ b_a, float* __restrict__ a){
    __shared__ float xm[CIN];
    __shared__ float part[256];
    int b=blockIdx.x, tid=threadIdx.x;
    float acc=0.f;
    #pragma unroll
    for (int ch=0;ch<NCH;ch++) acc += xp[(b*NCH+ch)*CIN+tid];
    xm[tid] = acc * (1.0f/(float)Vn);
    __syncthreads();
    int f = tid & 127, half = tid >> 7;
    float s = 0.f;
    #pragma unroll 4
    for (int c = half*128; c < half*128 + 128; c++) s += xm[c]*w_a[c*Fn+f];
    part[tid] = s;
    __syncthreads();
    if (tid < Fn) a[b*Fn+tid] = part[tid] + part[tid+128] + b_a[tid];
}

__global__ void colsum_part(const float* __restrict__ Hm, float* __restrict__ cp){
    int b=blockIdx.x, s=blockIdx.y, tid=threadIdx.x;
    const float* p = Hm + ((long)b*Vn + s*(Vn/NCH))*En + tid;
    float acc=0.f;
    for (int i=0;i<Vn/NCH;i++) acc += p[(long)i*En];
    cp[(b*NCH+s)*En+tid]=acc;
}

__global__ void binv_kernel(const float* __restrict__ cp, float* __restrict__ binv){
    int b=blockIdx.x, tid=threadIdx.x;
    float s=0.f;
    #pragma unroll
    for (int ch=0;ch<NCH;ch++) s += cp[(b*NCH+ch)*En+tid];
    binv[b*En+tid] = 1.0f/s;
}

// row-normalize H (fp32 in) -> single fp16 out
__global__ void rowscale_h(const float* __restrict__ H, h16* __restrict__ H16){
    __shared__ float red[256];
    long row = blockIdx.x;
    int tid = threadIdx.x;
    const float* hr = H + row*En;
    float v = hr[tid];
    red[tid]=v; __syncthreads();
    for (int s=128;s>0;s>>=1){ if(tid<s) red[tid]+=red[tid+s]; __syncthreads(); }
    H16[row*En + tid] = __float2half_rn(v * rsqrtf(red[0]));
}

// fused: out(fp16) = scale[b,r] * sum_s part[b,s,r,c]
__global__ void reduce_scale_h(h16* __restrict__ outv, const float* __restrict__ part,
                               const float* __restrict__ scale, int R, int C){
    long idx = (long)blockIdx.x*256 + threadIdx.x;
    int c = (int)(idx % C); long rc = idx / C; int r = (int)(rc % R); int b = (int)(rc / R);
    float s=0.f;
#pragma unroll
    for (int ch=0;ch<NCH;ch++) s += part[((long)(b*NCH+ch)*R + r)*C + c];
    outv[idx] = __float2half_rn(s * scale[b*R + r]);
}

// ---------------- host launch ------------------------------------------------
extern "C" void kernel_launch(void* const* d_in, const int* in_sizes, int n_in,
                              void* d_out, int out_size){
    (void)in_sizes; (void)n_in; (void)out_size;
    const float* x    =(const float*)d_in[0];
    const float* wphi =(const float*)d_in[1];
    const float* bphi =(const float*)d_in[2];
    const float* wa   =(const float*)d_in[3];
    const float* ba   =(const float*)d_in[4];
    const float* wm   =(const float*)d_in[5];
    const float* bm   =(const float*)d_in[6];
    const float* w2   =(const float*)d_in[7];
    const float* b2   =(const float*)d_in[8];
    float* out=(float*)d_out;

    float *aV,*Hb,*binv,*p1,*p2,*xp,*cp;
    h16 *x16,*w16,*wphi16,*w216,*phi16,*M16,*H16,*t16,*tmp16,*yh,*yl;
    cudaGetSymbolAddress((void**)&aV  , g_a);
    cudaGetSymbolAddress((void**)&Hb  , g_H);
    cudaGetSymbolAddress((void**)&binv, g_Binv);
    cudaGetSymbolAddress((void**)&p1  , g_p1);
    cudaGetSymbolAddress((void**)&p2  , g_p2);
    cudaGetSymbolAddress((void**)&xp  , g_xp);
    cudaGetSymbolAddress((void**)&cp  , g_cp);
    cudaGetSymbolAddress((void**)&x16 , g_x16);
    cudaGetSymbolAddress((void**)&w16 , g_w16);
    cudaGetSymbolAddress((void**)&wphi16, g_wphi16);
    cudaGetSymbolAddress((void**)&w216, g_w216);
    cudaGetSymbolAddress((void**)&phi16, g_phi16);
    cudaGetSymbolAddress((void**)&M16 , g_M16);
    cudaGetSymbolAddress((void**)&H16 , g_H16);
    cudaGetSymbolAddress((void**)&t16 , g_t16);
    cudaGetSymbolAddress((void**)&tmp16, g_tmp16);
    cudaGetSymbolAddress((void**)&yh  , g_yh);
    cudaGetSymbolAddress((void**)&yl  , g_yl);

    cudaFuncSetAttribute(conv_mma, cudaFuncAttributeMaxDynamicSharedMemorySize, CONV_SMEM);
    cudaFuncSetAttribute(hgemm_nn<1>, cudaFuncAttributeMaxDynamicSharedMemorySize, GEMM_SMEM);
    cudaFuncSetAttribute(hgemm_nn<2>, cudaFuncAttributeMaxDynamicSharedMemorySize, GEMM_SMEM);
    cudaFuncSetAttribute(hgemm_tn, cudaFuncAttributeMaxDynamicSharedMemorySize, TN_SMEM);

    // fp16 converts of inputs
    cvt_h<<<(Bn*Vn*CIN + 255)/256, 256>>>(x, x16, (long)Bn*Vn*CIN);
    cvt_h<<<(49*CIN*En + 255)/256, 256>>>(wm, w16, (long)49*CIN*En);
    cvt_h<<<(CIN*Fn + 255)/256, 256>>>(wphi, wphi16, (long)CIN*Fn);
    cvt_h<<<(CIN*En + 255)/256, 256>>>(w2, w216, (long)CIN*En);

    // mean(x) -> a
    xmean_part<<<dim3(Bn,NCH),256>>>(x, xp);
    a_kernel<<<Bn,256>>>(xp, wa, ba, aV);

    // phi = x @ w_phi + b_phi -> fp16 (M=32768, N=128, K=256)
    hgemm_nn<1><<<dim3(1,256,1),256,GEMM_SMEM>>>(x16, (h16*)0, wphi16,
        (float*)0, phi16, (h16*)0, bphi, Fn, CIN, 0,0,(long)0,0, 0);

    // M = conv7x7(x) + b_m -> fp16
    conv_mma<<<dim3(32, Bn), 256, CONV_SMEM>>>(x16, w16, bm, M16);

    // t = a * (phi^T @ M) -> fp16
    hgemm_tn<<<dim3(2,1,Bn*NCH),256,TN_SMEM>>>(phi16, M16, p1,
        Fn, En, Fn, En, Vn/NCH, (long)Vn*Fn, (long)Vn*En);
    reduce_scale_h<<<(Bn*Fn*En)/256,256>>>(t16, p1, aV, Fn, En);

    // H = |phi @ t| (fp32 out)
    hgemm_nn<1><<<dim3(2,32,Bn),256,GEMM_SMEM>>>(phi16, (h16*)0, t16,
        Hb, (h16*)0, (h16*)0, (const float*)0, En, Fn,
        (long)Vn*Fn, (long)Fn*En, (long)Vn*En, 0, 1);

    // Binv from column sums of H
    colsum_part<<<dim3(Bn,NCH),256>>>(Hb, cp);
    binv_kernel<<<Bn,256>>>(cp, binv);

    // D_H = D^{-1/2} H -> fp16
    rowscale_h<<<Bn*Vn,256>>>(Hb, H16);

    // tmp = Binv * (D_H^T @ x) -> fp16
    hgemm_tn<<<dim3(2,2,Bn*NCH),256,TN_SMEM>>>(H16, x16, p2,
        En, CIN, En, CIN, Vn/NCH, (long)Vn*En, (long)Vn*CIN);
    reduce_scale_h<<<(Bn*En*CIN)/256,256>>>(tmp16, p2, binv, En, CIN);

    // y = x - D_H @ tmp -> split fp16 (hi/lo)
    hgemm_nn<1><<<dim3(2,32,Bn),256,GEMM_SMEM>>>(H16, (h16*)0, tmp16,
        (float*)0, yh, yl, x, CIN, En,
        (long)Vn*En, (long)En*CIN, (long)Vn*CIN, (long)Vn*CIN, 2);

    // out = y @ w2 + b2  (2-pass: y exact split, w2 single)
    hgemm_nn<2><<<dim3(2,256,1),256,GEMM_SMEM>>>(yh, yl, w216,
        out, (h16*)0, (h16*)0, b2, En, CIN, 0,0,(long)0,0, 0);
}

// round 13
// speedup vs baseline: 5.4797x; 1.0401x over previous
#include <cuda_runtime.h>
#include <cuda_bf16.h>
#include <cuda_fp16.h>
#include <cstdint>

typedef __half h16;

#define Bn   8
#define Vn   4096
#define CIN  256
#define Fn   128
#define En   256
#define NCH  16

// ---------------- scratch (device globals) -----------------------------------
__device__ float g_a   [Bn*Fn];
__device__ float g_Binv[Bn*En];
__device__ float g_p1  [Bn*NCH*Fn*En];
__device__ float g_p2  [Bn*NCH*En*CIN];
__device__ float g_xp  [Bn*NCH*CIN];
__device__ float g_cp  [Bn*NCH*En];
// fp16 operands
__device__ h16 g_x16 [Bn*Vn*CIN];
__device__ h16 g_w16 [49*CIN*En];
__device__ h16 g_wphi16[CIN*Fn];
__device__ h16 g_w216[CIN*En];
__device__ h16 g_phi16[Bn*Vn*Fn];
__device__ h16 g_M16 [Bn*Vn*En];
__device__ h16 g_H16 [Bn*Vn*En];
__device__ h16 g_t16 [Bn*Fn*En];
__device__ h16 g_tmp16[Bn*En*CIN];
__device__ h16 g_y16 [Bn*Vn*CIN];

// =================== helpers =================================================
#define N_X  (Bn*Vn*CIN)            // 8388608
#define N_WM (49*CIN*En)            // 3211264
#define N_WP (CIN*Fn)               // 32768
#define N_W2 (CIN*En)               // 65536
#define N_ALL (N_X + N_WM + N_WP + N_W2)

__global__ void cvt_all(const float* __restrict__ x, const float* __restrict__ wm,
                        const float* __restrict__ wphi, const float* __restrict__ w2,
                        h16* __restrict__ x16, h16* __restrict__ w16,
                        h16* __restrict__ wphi16, h16* __restrict__ w216){
    long i = (long)blockIdx.x*256 + threadIdx.x;
    if (i < N_X)                      x16[i]            = __float2half_rn(x[i]);
    else if (i < N_X+N_WM)            w16[i-N_X]        = __float2half_rn(wm[i-N_X]);
    else if (i < N_X+N_WM+N_WP)       wphi16[i-N_X-N_WM]= __float2half_rn(wphi[i-N_X-N_WM]);
    else if (i < N_ALL)               w216[i-N_X-N_WM-N_WP] = __float2half_rn(w2[i-N_X-N_WM-N_WP]);
}

__device__ __forceinline__ uint32_t smem_u32(const void* p) {
    uint32_t a;
    asm("{ .reg .u64 t; cvta.to.shared.u64 t, %1; cvt.u32.u64 %0, t; }" : "=r"(a) : "l"(p));
    return a;
}
__device__ __forceinline__ void cp16(uint32_t d, const void* s, int sz){
    asm volatile("cp.async.cg.shared.global [%0], [%1], 16, %2;"
                 :: "r"(d), "l"(s), "r"(sz) : "memory");
}
__device__ __forceinline__ void ldsm4(uint32_t* r, uint32_t a){
    asm volatile("ldmatrix.sync.aligned.m8n8.x4.shared.b16 {%0,%1,%2,%3}, [%4];"
                 : "=r"(r[0]),"=r"(r[1]),"=r"(r[2]),"=r"(r[3]) : "r"(a));
}
__device__ __forceinline__ void ldsm4t(uint32_t* r, uint32_t a){
    asm volatile("ldmatrix.sync.aligned.m8n8.x4.trans.shared.b16 {%0,%1,%2,%3}, [%4];"
                 : "=r"(r[0]),"=r"(r[1]),"=r"(r[2]),"=r"(r[3]) : "r"(a));
}
__device__ __forceinline__ void mma16816h(float* c, const uint32_t* a, uint32_t b0, uint32_t b1){
    asm volatile("mma.sync.aligned.m16n8k16.row.col.f32.f16.f16.f32 "
                 "{%0,%1,%2,%3}, {%4,%5,%6,%7}, {%8,%9}, {%0,%1,%2,%3};"
                 : "+f"(c[0]),"+f"(c[1]),"+f"(c[2]),"+f"(c[3])
                 : "r"(a[0]),"r"(a[1]),"r"(a[2]),"r"(a[3]), "r"(b0),"r"(b1));
}
__device__ __forceinline__ void st2h(h16* D, float v0, float v1){
    __half2 p; p.x = __float2half_rn(v0); p.y = __float2half_rn(v1);
    *(__half2*)D = p;
}

// =================== conv: fp16 1-pass, barrier-reduced ======================
#define A_LD    40
#define B_LD    136
#define CB_LD   264
#define C_AH    0
#define C_BH    5120
#define C_STAGE 13568
#define C_NSTG  4
#define CONV_SMEM (C_NSTG*C_STAGE*2)
#define NCHUNK  392

__device__ __forceinline__ void conv_load_chunk(
    uint32_t smb, int stage,
    const h16* __restrict__ x16, const h16* __restrict__ wf,
    long bV, int p0, int ic, int tid)
{
    int tap = ic >> 3, c0 = (ic & 7) * 32;
    int ky = tap / 7, kx = tap - ky*7;
    uint32_t base = smb + stage*C_STAGE*2;

    int row  = tid >> 1;
    int koff = (tid & 1) * 16;
    int pos = p0 + row;
    int hs = (pos >> 6) + ky - 3, ws = (pos & 63) + kx - 3;
    int sz = (((unsigned)hs < 64u) && ((unsigned)ws < 64u)) ? 16 : 0;
    long sidx = sz ? (bV + ((hs << 6) + ws)) * CIN + c0 + koff : 0;
    uint32_t da = base + (uint32_t)(C_AH + row*A_LD + koff)*2;
    cp16(da,      x16 + sidx,     sz);
    cp16(da + 16, x16 + sidx + 8, sz);

    #pragma unroll
    for (int q = 0; q < 4; q++){
        int qq = tid + 256*q;
        int brow = qq >> 5;
        int bcol = (qq & 31) * 8;
        long widx = ((long)(tap*CIN + c0 + brow))*En + bcol;
        cp16(base + (uint32_t)(C_BH + brow*CB_LD + bcol)*2, wf + widx, 16);
    }
    asm volatile("cp.async.commit_group;" ::: "memory");
}

__global__ void __launch_bounds__(256, 1)
conv_mma(const h16* __restrict__ x16, const h16* __restrict__ wf,
         const float* __restrict__ bm, h16* __restrict__ M16)
{
    extern __shared__ char smem[];
    uint32_t smb = smem_u32(smem);
    int tid = threadIdx.x;
    int wid = tid >> 5, lane = tid & 31;
    int p0 = blockIdx.x * 128;
    int b  = blockIdx.y;
    long bV = (long)b * Vn;

    int mbase = (wid & 1) * 64;
    int nbase = (wid >> 1) * 64;

    float acc[4][8][4];
    #pragma unroll
    for (int i=0;i<4;i++)
    #pragma unroll
        for (int j=0;j<8;j++)
        #pragma unroll
            for (int k=0;k<4;k++) acc[i][j][k]=0.f;

    conv_load_chunk(smb, 0, x16, wf, bV, p0, 0, tid);
    conv_load_chunk(smb, 1, x16, wf, bV, p0, 1, tid);
    conv_load_chunk(smb, 2, x16, wf, bV, p0, 2, tid);

    int stage = 0;
    for (int ic = 0; ic < NCHUNK; ic++){
        if (ic < NCHUNK-3) asm volatile("cp.async.wait_group 2;" ::: "memory");
        else               asm volatile("cp.async.wait_group 0;" ::: "memory");
        __syncthreads();
        // issue next load immediately (stage (ic+3)&3 was last read in iter ic-1,
        // and the barrier above proves all warps completed iter ic-1)
        if (ic + 3 < NCHUNK)
            conv_load_chunk(smb, (ic + 3) & 3, x16, wf, bV, p0, ic + 3, tid);

        uint32_t sa = smb + (uint32_t)stage*C_STAGE*2;
        #pragma unroll
        for (int kk = 0; kk < 2; kk++){
            uint32_t ah[4][4];
            #pragma unroll
            for (int mt = 0; mt < 4; mt++){
                uint32_t ad = sa + (uint32_t)((mbase + mt*16 + (lane & 15))*A_LD
                                              + kk*16 + (lane >> 4)*8)*2;
                ldsm4(ah[mt], ad);
            }
            #pragma unroll
            for (int nf = 0; nf < 4; nf++){
                uint32_t bh[4];
                uint32_t bd = sa + (uint32_t)(C_BH + (kk*16 + (lane & 15))*CB_LD
                                              + nbase + nf*16 + (lane >> 4)*8)*2;
                ldsm4t(bh, bd);
                #pragma unroll
                for (int mt = 0; mt < 4; mt++){
                    mma16816h(acc[mt][nf*2],   ah[mt], bh[0], bh[1]);
                    mma16816h(acc[mt][nf*2+1], ah[mt], bh[2], bh[3]);
                }
            }
        }
        stage = (stage + 1) & 3;
    }

    #pragma unroll
    for (int mt = 0; mt < 4; mt++){
        long r0 = bV + p0 + mbase + mt*16 + (lane >> 2);
        #pragma unroll
        for (int n8 = 0; n8 < 8; n8++){
            int col = nbase + n8*8 + (lane & 3)*2;
            float b0 = bm[col], b1 = bm[col+1];
            float* c = acc[mt][n8];
            st2h(M16 + r0*En + col,     c[0]+b0, c[1]+b1);
            st2h(M16 + (r0+8)*En + col, c[2]+b0, c[3]+b1);
        }
    }
}

// =================== NN fp16 GEMM (1-pass) ===================================
#define OFF_A  0
#define OFF_B  5120
#define STAGE_E 9472
#define GEMM_SMEM (2*STAGE_E*2)

__device__ __forceinline__ void nn_load_chunk(
    uint32_t smb, int stage,
    const h16* __restrict__ Ah, const h16* __restrict__ Bs,
    int m0, int n0, int k0, int K, int N, int tid)
{
    uint32_t base = smb + stage*STAGE_E*2;
    int row  = tid >> 1;
    int koff = (tid & 1) * 16;
    long sidx = (long)(m0+row)*K + k0 + koff;
    uint32_t da = base + (uint32_t)(OFF_A + row*A_LD + koff)*2;
    cp16(da,      Ah + sidx,     16);
    cp16(da + 16, Ah + sidx + 8, 16);
    #pragma unroll
    for (int q = 0; q < 2; q++){
        int qq = tid*2 + q;
        int brow = qq >> 4;
        int bcol = (qq & 15) * 8;
        long widx = (long)(k0+brow)*N + n0 + bcol;
        cp16(base + (uint32_t)(OFF_B + brow*B_LD + bcol)*2, Bs + widx, 16);
    }
    asm volatile("cp.async.commit_group;" ::: "memory");
}

__global__ void __launch_bounds__(256, 2)
hgemm_nn(const h16* __restrict__ Ah, const h16* __restrict__ Bs,
         float* __restrict__ Cf, h16* __restrict__ Ch,
         const float* __restrict__ aux,
         int N, int K, long sA, long sB, long sC, long sAux, int epi)
{
    extern __shared__ char smem[];
    uint32_t smb = smem_u32(smem);
    int tid = threadIdx.x;
    int wid = tid >> 5, lane = tid & 31;
    int n0 = blockIdx.x * 128;
    int m0 = blockIdx.y * 128;
    int b  = blockIdx.z;
    Ah += (long)b*sA;
    Bs += (long)b*sB;
    const float* auxp = aux ? aux + (long)b*sAux : (const float*)0;

    int mbase = (wid & 3) * 32;
    int nbase = (wid >> 2) * 64;

    float acc[2][8][4];
    #pragma unroll
    for (int i=0;i<2;i++)
    #pragma unroll
        for (int j=0;j<8;j++)
        #pragma unroll
            for (int k=0;k<4;k++) acc[i][j][k]=0.f;

    int nchunk = K >> 5;
    nn_load_chunk(smb, 0, Ah, Bs, m0, n0, 0,  K, N, tid);
    nn_load_chunk(smb, 1, Ah, Bs, m0, n0, 32, K, N, tid);

    for (int ic = 0; ic < nchunk; ic++){
        if (ic < nchunk-2) asm volatile("cp.async.wait_group 1;" ::: "memory");
        else               asm volatile("cp.async.wait_group 0;" ::: "memory");
        __syncthreads();
        uint32_t sa = smb + (uint32_t)(ic & 1)*STAGE_E*2;
        #pragma unroll
        for (int kk = 0; kk < 2; kk++){
            uint32_t ah[2][4];
            #pragma unroll
            for (int mt = 0; mt < 2; mt++){
                uint32_t ad = sa + (uint32_t)((mbase + mt*16 + (lane & 15))*A_LD
                                              + kk*16 + (lane >> 4)*8)*2;
                ldsm4(ah[mt], ad);
            }
            #pragma unroll
            for (int nf = 0; nf < 4; nf++){
                uint32_t bh[4];
                uint32_t bd = sa + (uint32_t)(OFF_B + (kk*16 + (lane & 15))*B_LD
                                              + nbase + nf*16 + (lane >> 4)*8)*2;
                ldsm4t(bh, bd);
                #pragma unroll
                for (int mt = 0; mt < 2; mt++){
                    mma16816h(acc[mt][nf*2],   ah[mt], bh[0], bh[1]);
                    mma16816h(acc[mt][nf*2+1], ah[mt], bh[2], bh[3]);
                }
            }
        }
        __syncthreads();
        if (ic + 2 < nchunk)
            nn_load_chunk(smb, ic & 1, Ah, Bs, m0, n0, (ic+2)*32, K, N, tid);
    }

    #pragma unroll
    for (int mt = 0; mt < 2; mt++){
        long r0 = m0 + mbase + mt*16 + (lane >> 2);
        #pragma unroll
        for (int n8 = 0; n8 < 8; n8++){
            int col = n0 + nbase + n8*8 + (lane & 3)*2;
            float* c = acc[mt][n8];
            float v00=c[0], v01=c[1], v10=c[2], v11=c[3];
            if (epi == 0){
                float b0 = auxp[col], b1 = auxp[col+1];
                v00+=b0; v01+=b1; v10+=b0; v11+=b1;
            } else if (epi == 1){
                v00=fabsf(v00); v01=fabsf(v01); v10=fabsf(v10); v11=fabsf(v11);
            } else {
                v00 = auxp[r0*N + col]     - v00;
                v01 = auxp[r0*N + col + 1] - v01;
                v10 = auxp[(r0+8)*N + col]     - v10;
                v11 = auxp[(r0+8)*N + col + 1] - v11;
            }
            if (Cf){
                float* base = Cf + (long)b*sC;
                *(float2*)(base + r0*N + col)     = make_float2(v00, v01);
                *(float2*)(base + (r0+8)*N + col) = make_float2(v10, v11);
            }
            if (Ch){
                h16* bh = Ch + (long)b*sC;
                st2h(bh + r0*N + col,     v00, v01);
                st2h(bh + (r0+8)*N + col, v10, v11);
            }
        }
    }
}

// =================== TN fp16 1-pass split-K partials =========================
#define TN_A    0
#define TN_B    4352
#define TN_STAGE 8704
#define TN_SMEM (2*TN_STAGE*2)

__device__ __forceinline__ void tn_load_chunk(
    uint32_t smb, int stage,
    const h16* __restrict__ Ah, const h16* __restrict__ Bs,
    long offA, long offB, int m0, int n0, int k0, int lda, int ldb, int tid)
{
    uint32_t base = smb + stage*TN_STAGE*2;
    #pragma unroll
    for (int q = 0; q < 2; q++){
        int qq = tid*2 + q;
        int brow = qq >> 4;
        int bcol = (qq & 15) * 8;
        long aidx = offA + (long)(k0+brow)*lda + m0 + bcol;
        cp16(base + (uint32_t)(TN_A + brow*B_LD + bcol)*2, Ah + aidx, 16);
        long bidx = offB + (long)(k0+brow)*ldb + n0 + bcol;
        cp16(base + (uint32_t)(TN_B + brow*B_LD + bcol)*2, Bs + bidx, 16);
    }
    asm volatile("cp.async.commit_group;" ::: "memory");
}

__global__ void __launch_bounds__(256, 2)
hgemm_tn(const h16* __restrict__ Ah, const h16* __restrict__ Bs,
         float* __restrict__ P, int Mo, int No, int lda, int ldb, int Kc,
         long sA, long sB)
{
    extern __shared__ char smem[];
    uint32_t smb = smem_u32(smem);
    int tid = threadIdx.x;
    int wid = tid >> 5, lane = tid & 31;
    int b = blockIdx.z / NCH, s = blockIdx.z % NCH;
    long offA = (long)b*sA + (long)s*Kc*lda;
    long offB = (long)b*sB + (long)s*Kc*ldb;
    P += (long)(b*NCH + s)*Mo*No;
    int n0 = blockIdx.x * 128;
    int m0 = blockIdx.y * 128;

    int mbase = (wid & 3) * 32;
    int nbase = (wid >> 2) * 64;

    float acc[2][8][4];
    #pragma unroll
    for (int i=0;i<2;i++)
    #pragma unroll
        for (int j=0;j<8;j++)
        #pragma unroll
            for (int k=0;k<4;k++) acc[i][j][k]=0.f;

    int nchunk = Kc >> 5;
    tn_load_chunk(smb, 0, Ah, Bs, offA, offB, m0, n0, 0,  lda, ldb, tid);
    tn_load_chunk(smb, 1, Ah, Bs, offA, offB, m0, n0, 32, lda, ldb, tid);

    int krow = (lane & 7) + (lane >> 4)*8;
    int msub = ((lane >> 3) & 1)*8;

    for (int ic = 0; ic < nchunk; ic++){
        if (ic < nchunk-2) asm volatile("cp.async.wait_group 1;" ::: "memory");
        else               asm volatile("cp.async.wait_group 0;" ::: "memory");
        __syncthreads();
        uint32_t sa = smb + (uint32_t)(ic & 1)*TN_STAGE*2;
        #pragma unroll
        for (int kk = 0; kk < 2; kk++){
            uint32_t ah[2][4];
            #pragma unroll
            for (int mt = 0; mt < 2; mt++){
                uint32_t ad = sa + (uint32_t)(TN_A + (kk*16 + krow)*B_LD
                                              + mbase + mt*16 + msub)*2;
                ldsm4t(ah[mt], ad);
            }
            #pragma unroll
            for (int nf = 0; nf < 4; nf++){
                uint32_t bh[4];
                uint32_t bd = sa + (uint32_t)(TN_B + (kk*16 + (lane & 15))*B_LD
                                              + nbase + nf*16 + (lane >> 4)*8)*2;
                ldsm4t(bh, bd);
                #pragma unroll
                for (int mt = 0; mt < 2; mt++){
                    mma16816h(acc[mt][nf*2],   ah[mt], bh[0], bh[1]);
                    mma16816h(acc[mt][nf*2+1], ah[mt], bh[2], bh[3]);
                }
            }
        }
        __syncthreads();
        if (ic + 2 < nchunk)
            tn_load_chunk(smb, ic & 1, Ah, Bs, offA, offB, m0, n0, (ic+2)*32, lda, ldb, tid);
    }

    #pragma unroll
    for (int mt = 0; mt < 2; mt++){
        long r0 = m0 + mbase + mt*16 + (lane >> 2);
        #pragma unroll
        for (int n8 = 0; n8 < 8; n8++){
            int col = n0 + nbase + n8*8 + (lane & 3)*2;
            float* c = acc[mt][n8];
            *(float2*)(P + r0*No + col)     = make_float2(c[0], c[1]);
            *(float2*)(P + (r0+8)*No + col) = make_float2(c[2], c[3]);
        }
    }
}

// ---------------- small kernels ---------------------------------------------
__global__ void xmean_part(const float* __restrict__ x, float* __restrict__ xp){
    int b=blockIdx.x, s=blockIdx.y, tid=threadIdx.x;
    const float* p = x + ((long)b*Vn + s*(Vn/NCH))*CIN + tid;
    float acc=0.f;
    for (int i=0;i<Vn/NCH;i++) acc += p[(long)i*CIN];
    xp[(b*NCH+s)*CIN+tid]=acc;
}

__global__ void a_kernel(const float* __restrict__ xp, const float* __restrict__ w_a,
                         const float* __restrict__ b_a, float* __restrict__ a){
    __shared__ float xm[CIN];
    __shared__ float part[256];
    int b=blockIdx.x, tid=threadIdx.x;
    float acc=0.f;
    #pragma unroll
    for (int ch=0;ch<NCH;ch++) acc += xp[(b*NCH+ch)*CIN+tid];
    xm[tid] = acc * (1.0f/(float)Vn);
    __syncthreads();
    int f = tid & 127, half = tid >> 7;
    float s = 0.f;
    #pragma unroll 4
    for (int c = half*128; c < half*128 + 128; c++) s += xm[c]*w_a[c*Fn+f];
    part[tid] = s;
    __syncthreads();
    if (tid < Fn) a[b*Fn+tid] = part[tid] + part[tid+128] + b_a[tid];
}

__global__ void colsum_part(const h16* __restrict__ Hm, float* __restrict__ cp){
    int b=blockIdx.x, s=blockIdx.y, tid=threadIdx.x;
    const h16* p = Hm + ((long)b*Vn + s*(Vn/NCH))*En + tid;
    float acc=0.f;
    for (int i=0;i<Vn/NCH;i++) acc += __half2float(p[(long)i*En]);
    cp[(b*NCH+s)*En+tid]=acc;
}

__global__ void binv_kernel(const float* __restrict__ cp, float* __restrict__ binv){
    int b=blockIdx.x, tid=threadIdx.x;
    float s=0.f;
    #pragma unroll
    for (int ch=0;ch<NCH;ch++) s += cp[(b*NCH+ch)*En+tid];
    binv[b*En+tid] = 1.0f/s;
}

// in-place row-normalize H (fp16)
__global__ void rowscale_h(h16* __restrict__ H16){
    __shared__ float red[256];
    long row = blockIdx.x;
    int tid = threadIdx.x;
    float v = __half2float(H16[row*En + tid]);
    red[tid]=v; __syncthreads();
    for (int s=128;s>0;s>>=1){ if(tid<s) red[tid]+=red[tid+s]; __syncthreads(); }
    H16[row*En + tid] = __float2half_rn(v * rsqrtf(red[0]));
}

// fused: out(fp16) = scale[b,r] * sum_s part[b,s,r,c]
__global__ void reduce_scale_h(h16* __restrict__ outv, const float* __restrict__ part,
                               const float* __restrict__ scale, int R, int C){
    long idx = (long)blockIdx.x*256 + threadIdx.x;
    int c = (int)(idx % C); long rc = idx / C; int r = (int)(rc % R); int b = (int)(rc / R);
    float s=0.f;
#pragma unroll
    for (int ch=0;ch<NCH;ch++) s += part[((long)(b*NCH+ch)*R + r)*C + c];
    outv[idx] = __float2half_rn(s * scale[b*R + r]);
}

// ---------------- host launch ------------------------------------------------
extern "C" void kernel_launch(void* const* d_in, const int* in_sizes, int n_in,
                              void* d_out, int out_size){
    (void)in_sizes; (void)n_in; (void)out_size;
    const float* x    =(const float*)d_in[0];
    const float* wphi =(const float*)d_in[1];
    const float* bphi =(const float*)d_in[2];
    const float* wa   =(const float*)d_in[3];
    const float* ba   =(const float*)d_in[4];
    const float* wm   =(const float*)d_in[5];
    const float* bm   =(const float*)d_in[6];
    const float* w2   =(const float*)d_in[7];
    const float* b2   =(const float*)d_in[8];
    float* out=(float*)d_out;

    float *aV,*binv,*p1,*p2,*xp,*cp;
    h16 *x16,*w16,*wphi16,*w216,*phi16,*M16,*H16,*t16,*tmp16,*y16;
    cudaGetSymbolAddress((void**)&aV  , g_a);
    cudaGetSymbolAddress((void**)&binv, g_Binv);
    cudaGetSymbolAddress((void**)&p1  , g_p1);
    cudaGetSymbolAddress((void**)&p2  , g_p2);
    cudaGetSymbolAddress((void**)&xp  , g_xp);
    cudaGetSymbolAddress((void**)&cp  , g_cp);
    cudaGetSymbolAddress((void**)&x16 , g_x16);
    cudaGetSymbolAddress((void**)&w16 , g_w16);
    cudaGetSymbolAddress((void**)&wphi16, g_wphi16);
    cudaGetSymbolAddress((void**)&w216, g_w216);
    cudaGetSymbolAddress((void**)&phi16, g_phi16);
    cudaGetSymbolAddress((void**)&M16 , g_M16);
    cudaGetSymbolAddress((void**)&H16 , g_H16);
    cudaGetSymbolAddress((void**)&t16 , g_t16);
    cudaGetSymbolAddress((void**)&tmp16, g_tmp16);
    cudaGetSymbolAddress((void**)&y16 , g_y16);

    cudaFuncSetAttribute(conv_mma, cudaFuncAttributeMaxDynamicSharedMemorySize, CONV_SMEM);
    cudaFuncSetAttribute(hgemm_nn, cudaFuncAttributeMaxDynamicSharedMemorySize, GEMM_SMEM);
    cudaFuncSetAttribute(hgemm_tn, cudaFuncAttributeMaxDynamicSharedMemorySize, TN_SMEM);

    // fp16 converts of all inputs (single launch)
    cvt_all<<<(N_ALL + 255)/256, 256>>>(x, wm, wphi, w2, x16, w16, wphi16, w216);

    // mean(x) -> a
    xmean_part<<<dim3(Bn,NCH),256>>>(x, xp);
    a_kernel<<<Bn,256>>>(xp, wa, ba, aV);

    // phi = x @ w_phi + b_phi -> fp16 (M=32768, N=128, K=256)
    hgemm_nn<<<dim3(1,256,1),256,GEMM_SMEM>>>(x16, wphi16,
        (float*)0, phi16, bphi, Fn, CIN, 0,0,(long)0,0, 0);

    // M = conv7x7(x) + b_m -> fp16
    conv_mma<<<dim3(32, Bn), 256, CONV_SMEM>>>(x16, w16, bm, M16);

    // t = a * (phi^T @ M) -> fp16
    hgemm_tn<<<dim3(2,1,Bn*NCH),256,TN_SMEM>>>(phi16, M16, p1,
        Fn, En, Fn, En, Vn/NCH, (long)Vn*Fn, (long)Vn*En);
    reduce_scale_h<<<(Bn*Fn*En)/256,256>>>(t16, p1, aV, Fn, En);

    // H = |phi @ t| -> fp16
    hgemm_nn<<<dim3(2,32,Bn),256,GEMM_SMEM>>>(phi16, t16,
        (float*)0, H16, (const float*)0, En, Fn,
        (long)Vn*Fn, (long)Fn*En, (long)Vn*En, 0, 1);

    // Binv from column sums of H
    colsum_part<<<dim3(Bn,NCH),256>>>(H16, cp);
    binv_kernel<<<Bn,256>>>(cp, binv);

    // D_H = D^{-1/2} H  (in-place fp16)
    rowscale_h<<<Bn*Vn,256>>>(H16);

    // tmp = Binv * (D_H^T @ x) -> fp16
    hgemm_tn<<<dim3(2,2,Bn*NCH),256,TN_SMEM>>>(H16, x16, p2,
        En, CIN, En, CIN, Vn/NCH, (long)Vn*En, (long)Vn*CIN);
    reduce_scale_h<<<(Bn*En*CIN)/256,256>>>(tmp16, p2, binv, En, CIN);

    // y = x - D_H @ tmp -> fp16
    hgemm_nn<<<dim3(2,32,Bn),256,GEMM_SMEM>>>(H16, tmp16,
        (float*)0, y16, x, CIN, En,
        (long)Vn*En, (long)En*CIN, (long)Vn*CIN, (long)Vn*CIN, 2);

    // out = y @ w2 + b2  (1-pass)
    hgemm_nn<<<dim3(2,256,1),256,GEMM_SMEM>>>(y16, w216,
        out, (h16*)0, b2, En, CIN, 0,0,(long)0,0, 0);
}